// round 5
// baseline (speedup 1.0000x reference)
#include <cuda_runtime.h>

#define BATCH 4
#define CDIM 256
#define NTOK 4096   // 64*64
#define TCD 768     // 3*C
#define FULLMASK 0xffffffffu

// Scratch (allocation-free rule: __device__ globals)
__device__ float g_Q[BATCH * NTOK * CDIM];
__device__ float g_K[BATCH * NTOK * CDIM];
__device__ float g_V[BATCH * NTOK * CDIM];
__device__ float g_AO[BATCH * NTOK * CDIM];

__device__ __forceinline__ unsigned to_tf32_bits(float x) {
    unsigned r;
    asm("cvt.rna.tf32.f32 %0, %1;" : "=r"(r) : "f"(x));
    return r;
}
__device__ __forceinline__ float to_tf32(float x) {
    return __uint_as_float(to_tf32_bits(x));
}
__device__ __forceinline__ float4 to_tf32_4(float4 v) {
    return make_float4(to_tf32(v.x), to_tf32(v.y), to_tf32(v.z), to_tf32(v.w));
}
__device__ __forceinline__ float ex2(float x) {
    float r;
    asm("ex2.approx.f32 %0, %1;" : "=f"(r) : "f"(x));
    return r;
}
__device__ __forceinline__ void mma_tf32(float d[4], const unsigned a[4], const unsigned b[2]) {
    asm volatile(
        "mma.sync.aligned.m16n8k8.row.col.f32.tf32.tf32.f32 "
        "{%0,%1,%2,%3}, {%4,%5,%6,%7}, {%8,%9}, {%0,%1,%2,%3};\n"
        : "+f"(d[0]), "+f"(d[1]), "+f"(d[2]), "+f"(d[3])
        : "r"(a[0]), "r"(a[1]), "r"(a[2]), "r"(a[3]), "r"(b[0]), "r"(b[1]));
}

// ---------------------------------------------------------------------------
// Kernel 1: QKV GEMM via tf32 mma.  C[n][d] = sum_c x[b,c,n] * Wqkv[d,c].
// Inputs rna-rounded to tf32 at staging (unbiased).
// ---------------------------------------------------------------------------
#define XS 132
#define WS 36
#define QKV_SMEM ((2 * (32 * XS + 64 * WS)) * 4)

__global__ __launch_bounds__(256) void qkv_kernel(const float* __restrict__ x,
                                                  const float* __restrict__ Wqkv) {
    extern __shared__ float sq[];
    float* Xs[2] = {sq, sq + 32 * XS + 64 * WS};
    float* Wsm[2] = {sq + 32 * XS, sq + 2 * 32 * XS + 64 * WS};

    const int b  = blockIdx.z;
    const int n0 = blockIdx.x * 128;
    const int d0 = blockIdx.y * 64;
    const int tid = threadIdx.x;
    const int lane = tid & 31, w = tid >> 5;
    const int g = lane >> 2, t = lane & 3;
    const int wm = w >> 2, wn = w & 3;        // 2 x 4 warp grid

    const float* xb = x + (long)b * CDIM * NTOK;

    float acc[4][2][4] = {};

    {
#pragma unroll
        for (int tl = 0; tl < 4; tl++) {   // X: 32c x 128n = 1024 f4
            const int f4 = tid + tl * 256;
            const int row = f4 >> 5, cq = f4 & 31;
            *(float4*)&Xs[0][row * XS + cq * 4] =
                to_tf32_4(*(const float4*)&xb[(long)row * NTOK + n0 + cq * 4]);
        }
#pragma unroll
        for (int tl = 0; tl < 2; tl++) {   // W: 64d x 32c = 512 f4
            const int f4 = tid + tl * 256;
            const int row = f4 >> 3, cq = f4 & 7;
            *(float4*)&Wsm[0][row * WS + cq * 4] =
                to_tf32_4(*(const float4*)&Wqkv[(long)(d0 + row) * CDIM + cq * 4]);
        }
    }
    __syncthreads();

    for (int ck = 0; ck < 8; ck++) {
        const int cur = ck & 1;
        if (ck < 7) {
            const int c0 = (ck + 1) * 32;
            const int nxt = cur ^ 1;
#pragma unroll
            for (int tl = 0; tl < 4; tl++) {
                const int f4 = tid + tl * 256;
                const int row = f4 >> 5, cq = f4 & 31;
                *(float4*)&Xs[nxt][row * XS + cq * 4] =
                    to_tf32_4(*(const float4*)&xb[(long)(c0 + row) * NTOK + n0 + cq * 4]);
            }
#pragma unroll
            for (int tl = 0; tl < 2; tl++) {
                const int f4 = tid + tl * 256;
                const int row = f4 >> 3, cq = f4 & 7;
                *(float4*)&Wsm[nxt][row * WS + cq * 4] =
                    to_tf32_4(*(const float4*)&Wqkv[(long)(d0 + row) * CDIM + c0 + cq * 4]);
            }
        }
#pragma unroll
        for (int ks = 0; ks < 4; ks++) {
            const int k = ks * 8;
            unsigned a[4][4], bb[2][2];
#pragma unroll
            for (int mt = 0; mt < 4; mt++) {
                const int nb = wm * 64 + mt * 16 + g;
                a[mt][0] = __float_as_uint(Xs[cur][(k + t) * XS + nb]);
                a[mt][1] = __float_as_uint(Xs[cur][(k + t) * XS + nb + 8]);
                a[mt][2] = __float_as_uint(Xs[cur][(k + t + 4) * XS + nb]);
                a[mt][3] = __float_as_uint(Xs[cur][(k + t + 4) * XS + nb + 8]);
            }
#pragma unroll
            for (int nt = 0; nt < 2; nt++) {
                const float* wr = &Wsm[cur][(wn * 16 + nt * 8 + g) * WS + k + t];
                bb[nt][0] = __float_as_uint(wr[0]);
                bb[nt][1] = __float_as_uint(wr[4]);
            }
#pragma unroll
            for (int mt = 0; mt < 4; mt++)
#pragma unroll
                for (int nt = 0; nt < 2; nt++)
                    mma_tf32(acc[mt][nt], a[mt], bb[nt]);
        }
        __syncthreads();
    }

    const int seg = d0 >> 8;
    float* base = (seg == 0) ? g_Q : (seg == 1) ? g_K : g_V;
    const int dlocal0 = (d0 & 255);
#pragma unroll
    for (int mt = 0; mt < 4; mt++) {
        const int n = n0 + wm * 64 + mt * 16 + g;
#pragma unroll
        for (int nt = 0; nt < 2; nt++) {
            const int col = dlocal0 + wn * 16 + nt * 8 + 2 * t;
            *(float2*)&base[((long)b * NTOK + n) * CDIM + col] =
                make_float2(to_tf32(acc[mt][nt][0]), to_tf32(acc[mt][nt][1]));
            *(float2*)&base[((long)b * NTOK + n + 8) * CDIM + col] =
                make_float2(to_tf32(acc[mt][nt][2]), to_tf32(acc[mt][nt][3]));
        }
    }
}

// ---------------------------------------------------------------------------
// Kernel 2: tf32 mma flash attention. Q resident, register-P.
// 64-key tiles (sacc 32 regs) + __launch_bounds__(256,1) -> no spills.
// grid (32, 4), 256 threads, 8 warps; warp owns 16 query rows.
// ---------------------------------------------------------------------------
#define QSTR 260
#define KSTR 68
#define VSTR 260
#define KVBUF 8320   // max(64*68, 32*260) floats
#define ATTN_SMEM ((128 * QSTR + 2 * KVBUF + 64) * 4)

__global__ __launch_bounds__(256, 1) void attn_kernel(const int* __restrict__ fg_mask) {
    extern __shared__ float sm[];
    float* Qs  = sm;                   // [128][260]
    float* KV0 = Qs + 128 * QSTR;
    float* KV1 = KV0 + KVBUF;
    float* fgf = KV1 + KVBUF;          // [64]

    const int b  = blockIdx.y;
    const int q0 = blockIdx.x * 128;
    const int tid = threadIdx.x;
    const int lane = tid & 31, w = tid >> 5;
    const int g = lane >> 2, t = lane & 3;
    const int qrow = w * 16 + g;

    const float* Qg = g_Q + ((long)b * NTOK + q0) * CDIM;
    const float* Kg = g_K + (long)b * NTOK * CDIM;
    const float* Vg = g_V + (long)b * NTOK * CDIM;

    // resident Q tile [128 n][256 c]
#pragma unroll
    for (int tl = 0; tl < 32; tl++) {
        const int f4 = tid + tl * 256;
        const int row = f4 >> 6, cq = f4 & 63;
        *(float4*)&Qs[row * QSTR + cq * 4] =
            *(const float4*)&Qg[(long)row * CDIM + cq * 4];
    }

    float oacc[32][4];
#pragma unroll
    for (int i = 0; i < 32; i++)
#pragma unroll
        for (int j = 0; j < 4; j++) oacc[i][j] = 0.0f;
    float l0 = 0.0f, l1 = 0.0f;

    const float SC = 0.0625f * 1.4426950408889634f;   // 1/sqrt(C) * log2(e)

    for (int m0 = 0; m0 < NTOK; m0 += 64) {
        if (tid < 64) fgf[tid] = fg_mask[b * NTOK + m0 + tid] ? 1.0f : 0.0f;
        // K chunk 0 (64 keys x c 0..63) -> KV0
#pragma unroll
        for (int tl = 0; tl < 4; tl++) {
            const int f4 = tid + tl * 256;
            const int row = f4 >> 4, cq = f4 & 15;
            *(float4*)&KV0[row * KSTR + cq * 4] =
                *(const float4*)&Kg[(long)(m0 + row) * CDIM + cq * 4];
        }
        __syncthreads();   // also covers Q visibility on first tile

        float sacc[8][4];
#pragma unroll
        for (int i = 0; i < 8; i++)
#pragma unroll
            for (int j = 0; j < 4; j++) sacc[i][j] = 0.0f;

        // ---- S phase: 4 c-chunks of 64, double-buffered ----
        for (int cc = 0; cc < 4; cc++) {
            float* cur = (cc & 1) ? KV1 : KV0;
            if (cc < 3) {
                float* nxt = (cc & 1) ? KV0 : KV1;
                const int c0 = (cc + 1) * 64;
#pragma unroll
                for (int tl = 0; tl < 4; tl++) {
                    const int f4 = tid + tl * 256;
                    const int row = f4 >> 4, cq = f4 & 15;
                    *(float4*)&nxt[row * KSTR + cq * 4] =
                        *(const float4*)&Kg[(long)(m0 + row) * CDIM + c0 + cq * 4];
                }
            }
            const int c0q = cc * 64;
#pragma unroll
            for (int ks = 0; ks < 8; ks++) {
                const int k = ks * 8;
                unsigned a[4];
                const float* qr = &Qs[qrow * QSTR + c0q + k + t];
                a[0] = __float_as_uint(qr[0]);
                a[1] = __float_as_uint(qr[8 * QSTR]);
                a[2] = __float_as_uint(qr[4]);
                a[3] = __float_as_uint(qr[8 * QSTR + 4]);
#pragma unroll
                for (int nt = 0; nt < 8; nt++) {
                    unsigned bb[2];
                    const float* kr = &cur[(nt * 8 + g) * KSTR + k + t];
                    bb[0] = __float_as_uint(kr[0]);
                    bb[1] = __float_as_uint(kr[4]);
                    mma_tf32(sacc[nt], a, bb);
                }
            }
            __syncthreads();
        }

        // ---- softmax: mask * exp2(S*SC), tf32-round, in-register row sums ----
        float rs0 = 0.0f, rs1 = 0.0f;
#pragma unroll
        for (int nt = 0; nt < 8; nt++) {
            float2 f = *(const float2*)&fgf[nt * 8 + 2 * t];
            float p0 = to_tf32(ex2(sacc[nt][0] * SC) * f.x);
            float p1 = to_tf32(ex2(sacc[nt][1] * SC) * f.y);
            float p2 = to_tf32(ex2(sacc[nt][2] * SC) * f.x);
            float p3 = to_tf32(ex2(sacc[nt][3] * SC) * f.y);
            sacc[nt][0] = p0; sacc[nt][1] = p1; sacc[nt][2] = p2; sacc[nt][3] = p3;
            rs0 += p0 + p1;
            rs1 += p2 + p3;
        }
        rs0 += __shfl_xor_sync(FULLMASK, rs0, 1);
        rs0 += __shfl_xor_sync(FULLMASK, rs0, 2);
        rs1 += __shfl_xor_sync(FULLMASK, rs1, 1);
        rs1 += __shfl_xor_sync(FULLMASK, rs1, 2);
        l0 += rs0;
        l1 += rs1;

        // ---- PV phase: 2 key-chunks of 32 (full 256 c), double-buffered ----
#pragma unroll
        for (int tl = 0; tl < 8; tl++) {
            const int f4 = tid + tl * 256;
            const int row = f4 >> 6, cq = f4 & 63;
            *(float4*)&KV0[row * VSTR + cq * 4] =
                *(const float4*)&Vg[(long)(m0 + row) * CDIM + cq * 4];
        }
        __syncthreads();

        for (int kc = 0; kc < 2; kc++) {
            float* cur = (kc & 1) ? KV1 : KV0;
            if (kc < 1) {
#pragma unroll
                for (int tl = 0; tl < 8; tl++) {
                    const int f4 = tid + tl * 256;
                    const int row = f4 >> 6, cq = f4 & 63;
                    *(float4*)&KV1[row * VSTR + cq * 4] =
                        *(const float4*)&Vg[(long)(m0 + 32 + row) * CDIM + cq * 4];
                }
            }
#pragma unroll
            for (int ks = 0; ks < 4; ks++) {
                const int j = kc * 4 + ks;   // P col-group
                // register transpose: accumulator layout -> A-operand layout
                const unsigned srcA = (lane & ~3u) | (unsigned)(t >> 1);
                float q0A = __shfl_sync(FULLMASK, sacc[j][0], srcA);
                float q1A = __shfl_sync(FULLMASK, sacc[j][1], srcA);
                float q2A = __shfl_sync(FULLMASK, sacc[j][2], srcA);
                float q3A = __shfl_sync(FULLMASK, sacc[j][3], srcA);
                float q0B = __shfl_sync(FULLMASK, sacc[j][0], srcA + 2);
                float q1B = __shfl_sync(FULLMASK, sacc[j][1], srcA + 2);
                float q2B = __shfl_sync(FULLMASK, sacc[j][2], srcA + 2);
                float q3B = __shfl_sync(FULLMASK, sacc[j][3], srcA + 2);
                unsigned a[4];
                a[0] = __float_as_uint((t & 1) ? q1A : q0A);   // P[g][t]
                a[1] = __float_as_uint((t & 1) ? q3A : q2A);   // P[g+8][t]
                a[2] = __float_as_uint((t & 1) ? q1B : q0B);   // P[g][t+4]
                a[3] = __float_as_uint((t & 1) ? q3B : q2B);   // P[g+8][t+4]
#pragma unroll
                for (int nt = 0; nt < 32; nt++) {
                    unsigned bb[2];
                    bb[0] = __float_as_uint(cur[(ks * 8 + t) * VSTR + nt * 8 + g]);
                    bb[1] = __float_as_uint(cur[(ks * 8 + t + 4) * VSTR + nt * 8 + g]);
                    mma_tf32(oacc[nt], a, bb);
                }
            }
            __syncthreads();
        }
    }

    // ---- epilogue: normalize + store ----
    float* AOg = g_AO + ((long)b * NTOK + q0) * CDIM;
    const float inv0 = 1.0f / l0;
    const float inv1 = 1.0f / l1;
#pragma unroll
    for (int nt = 0; nt < 32; nt++) {
        const int col = nt * 8 + 2 * t;
        *(float2*)&AOg[(long)qrow * CDIM + col] =
            make_float2(oacc[nt][0] * inv0, oacc[nt][1] * inv0);
        *(float2*)&AOg[(long)(qrow + 8) * CDIM + col] =
            make_float2(oacc[nt][2] * inv1, oacc[nt][3] * inv1);
    }
}

// ---------------------------------------------------------------------------
// Kernel 3: projection via tf32 mma + bias + smem transpose store.
// Inputs rna-rounded at staging.
// ---------------------------------------------------------------------------
#define AS 36
#define CS 132
#define PROJ_SMEM ((2 * (128 * AS + 64 * AS)) * 4)

__global__ __launch_bounds__(256) void proj_kernel(const float* __restrict__ Wp,
                                                   const float* __restrict__ bp,
                                                   float* __restrict__ out) {
    extern __shared__ float sp[];
    float* As[2] = {sp, sp + 128 * AS + 64 * AS};
    float* Wsm[2] = {sp + 128 * AS, sp + 2 * 128 * AS + 64 * AS};
    float* Cs = sp;   // overlay after GEMM

    const int b   = blockIdx.z;
    const int n0  = blockIdx.x * 128;
    const int co0 = blockIdx.y * 64;
    const int tid = threadIdx.x;
    const int lane = tid & 31, w = tid >> 5;
    const int g = lane >> 2, t = lane & 3;
    const int wm = w >> 2, wn = w & 3;

    const float* A = g_AO + ((long)b * NTOK + n0) * CDIM;

    float acc[4][2][4] = {};

    {
#pragma unroll
        for (int tl = 0; tl < 4; tl++) {
            const int f4 = tid + tl * 256;
            const int row = f4 >> 3, cq = f4 & 7;
            *(float4*)&As[0][row * AS + cq * 4] =
                to_tf32_4(*(const float4*)&A[(long)row * CDIM + cq * 4]);
        }
#pragma unroll
        for (int tl = 0; tl < 2; tl++) {
            const int f4 = tid + tl * 256;
            const int row = f4 >> 3, cq = f4 & 7;
            *(float4*)&Wsm[0][row * AS + cq * 4] =
                to_tf32_4(*(const float4*)&Wp[(long)(co0 + row) * CDIM + cq * 4]);
        }
    }
    __syncthreads();

    for (int ck = 0; ck < 8; ck++) {
        const int cur = ck & 1;
        if (ck < 7) {
            const int c0 = (ck + 1) * 32;
            const int nxt = cur ^ 1;
#pragma unroll
            for (int tl = 0; tl < 4; tl++) {
                const int f4 = tid + tl * 256;
                const int row = f4 >> 3, cq = f4 & 7;
                *(float4*)&As[nxt][row * AS + cq * 4] =
                    to_tf32_4(*(const float4*)&A[(long)row * CDIM + c0 + cq * 4]);
            }
#pragma unroll
            for (int tl = 0; tl < 2; tl++) {
                const int f4 = tid + tl * 256;
                const int row = f4 >> 3, cq = f4 & 7;
                *(float4*)&Wsm[nxt][row * AS + cq * 4] =
                    to_tf32_4(*(const float4*)&Wp[(long)(co0 + row) * CDIM + c0 + cq * 4]);
            }
        }
#pragma unroll
        for (int ks = 0; ks < 4; ks++) {
            const int k = ks * 8;
            unsigned a[4][4], bb[2][2];
#pragma unroll
            for (int mt = 0; mt < 4; mt++) {
                const float* ar = &As[cur][(wm * 64 + mt * 16 + g) * AS + k + t];
                a[mt][0] = __float_as_uint(ar[0]);
                a[mt][1] = __float_as_uint(ar[8 * AS]);
                a[mt][2] = __float_as_uint(ar[4]);
                a[mt][3] = __float_as_uint(ar[8 * AS + 4]);
            }
#pragma unroll
            for (int nt = 0; nt < 2; nt++) {
                const float* wr = &Wsm[cur][(wn * 16 + nt * 8 + g) * AS + k + t];
                bb[nt][0] = __float_as_uint(wr[0]);
                bb[nt][1] = __float_as_uint(wr[4]);
            }
#pragma unroll
            for (int mt = 0; mt < 4; mt++)
#pragma unroll
                for (int nt = 0; nt < 2; nt++)
                    mma_tf32(acc[mt][nt], a[mt], bb[nt]);
        }
        __syncthreads();
    }

    // stage transposed into Cs[d][n]
#pragma unroll
    for (int mt = 0; mt < 4; mt++) {
        const int n = wm * 64 + mt * 16 + g;
#pragma unroll
        for (int nt = 0; nt < 2; nt++) {
            const int col = wn * 16 + nt * 8 + 2 * t;
            Cs[(col) * CS + n]         = acc[mt][nt][0];
            Cs[(col + 1) * CS + n]     = acc[mt][nt][1];
            Cs[(col) * CS + n + 8]     = acc[mt][nt][2];
            Cs[(col + 1) * CS + n + 8] = acc[mt][nt][3];
        }
    }
    __syncthreads();

    // coalesced store out[b][co0+d][n0..n0+128) with bias
#pragma unroll
    for (int tl = 0; tl < 8; tl++) {
        const int f4 = tid + tl * 256;
        const int row = f4 >> 5, cq = f4 & 31;
        const float bias = bp[co0 + row];
        float4 v = *(const float4*)&Cs[row * CS + cq * 4];
        v.x += bias; v.y += bias; v.z += bias; v.w += bias;
        *(float4*)&out[((long)b * CDIM + co0 + row) * NTOK + n0 + cq * 4] = v;
    }
}

// ---------------------------------------------------------------------------
extern "C" void kernel_launch(void* const* d_in, const int* in_sizes, int n_in,
                              void* d_out, int out_size) {
    const float* x    = (const float*)d_in[0];
    const int*   fg   = (const int*)d_in[1];
    const float* Wqkv = (const float*)d_in[2];
    const float* Wp   = (const float*)d_in[3];
    const float* bp   = (const float*)d_in[4];
    float* out = (float*)d_out;

    cudaFuncSetAttribute(qkv_kernel, cudaFuncAttributeMaxDynamicSharedMemorySize, QKV_SMEM);
    cudaFuncSetAttribute(attn_kernel, cudaFuncAttributeMaxDynamicSharedMemorySize, ATTN_SMEM);
    cudaFuncSetAttribute(proj_kernel, cudaFuncAttributeMaxDynamicSharedMemorySize, PROJ_SMEM);

    qkv_kernel<<<dim3(NTOK / 128, TCD / 64, BATCH), 256, QKV_SMEM>>>(x, Wqkv);
    attn_kernel<<<dim3(NTOK / 128, BATCH), 256, ATTN_SMEM>>>(fg);
    proj_kernel<<<dim3(NTOK / 128, CDIM / 64, BATCH), 256, PROJ_SMEM>>>(Wp, bp, out);
}

// round 6
// speedup vs baseline: 1.0766x; 1.0766x over previous
#include <cuda_runtime.h>

#define BATCH 4
#define CDIM 256
#define NTOK 4096   // 64*64
#define TCD 768     // 3*C
#define FULLMASK 0xffffffffu

// Scratch (allocation-free rule: __device__ globals)
__device__ float g_Q[BATCH * NTOK * CDIM];
__device__ float g_K[BATCH * NTOK * CDIM];
__device__ float g_V[BATCH * NTOK * CDIM];
__device__ float g_AO[BATCH * NTOK * CDIM];

__device__ __forceinline__ unsigned to_tf32_bits(float x) {
    unsigned r;
    asm("cvt.rna.tf32.f32 %0, %1;" : "=r"(r) : "f"(x));
    return r;
}
__device__ __forceinline__ float to_tf32(float x) {
    return __uint_as_float(to_tf32_bits(x));
}
__device__ __forceinline__ float4 to_tf32_4(float4 v) {
    return make_float4(to_tf32(v.x), to_tf32(v.y), to_tf32(v.z), to_tf32(v.w));
}
__device__ __forceinline__ float ex2(float x) {
    float r;
    asm("ex2.approx.f32 %0, %1;" : "=f"(r) : "f"(x));
    return r;
}
__device__ __forceinline__ void mma_tf32(float d[4], const unsigned a[4], const unsigned b[2]) {
    asm volatile(
        "mma.sync.aligned.m16n8k8.row.col.f32.tf32.tf32.f32 "
        "{%0,%1,%2,%3}, {%4,%5,%6,%7}, {%8,%9}, {%0,%1,%2,%3};\n"
        : "+f"(d[0]), "+f"(d[1]), "+f"(d[2]), "+f"(d[3])
        : "r"(a[0]), "r"(a[1]), "r"(a[2]), "r"(a[3]), "r"(b[0]), "r"(b[1]));
}

// ---------------------------------------------------------------------------
// Kernel 1: QKV GEMM via tf32 mma (unchanged from R5; passing).
// ---------------------------------------------------------------------------
#define XS 132
#define WS 36
#define QKV_SMEM ((2 * (32 * XS + 64 * WS)) * 4)

__global__ __launch_bounds__(256) void qkv_kernel(const float* __restrict__ x,
                                                  const float* __restrict__ Wqkv) {
    extern __shared__ float sq[];
    float* Xs[2] = {sq, sq + 32 * XS + 64 * WS};
    float* Wsm[2] = {sq + 32 * XS, sq + 2 * 32 * XS + 64 * WS};

    const int b  = blockIdx.z;
    const int n0 = blockIdx.x * 128;
    const int d0 = blockIdx.y * 64;
    const int tid = threadIdx.x;
    const int lane = tid & 31, w = tid >> 5;
    const int g = lane >> 2, t = lane & 3;
    const int wm = w >> 2, wn = w & 3;

    const float* xb = x + (long)b * CDIM * NTOK;

    float acc[4][2][4] = {};

    {
#pragma unroll
        for (int tl = 0; tl < 4; tl++) {
            const int f4 = tid + tl * 256;
            const int row = f4 >> 5, cq = f4 & 31;
            *(float4*)&Xs[0][row * XS + cq * 4] =
                to_tf32_4(*(const float4*)&xb[(long)row * NTOK + n0 + cq * 4]);
        }
#pragma unroll
        for (int tl = 0; tl < 2; tl++) {
            const int f4 = tid + tl * 256;
            const int row = f4 >> 3, cq = f4 & 7;
            *(float4*)&Wsm[0][row * WS + cq * 4] =
                to_tf32_4(*(const float4*)&Wqkv[(long)(d0 + row) * CDIM + cq * 4]);
        }
    }
    __syncthreads();

    for (int ck = 0; ck < 8; ck++) {
        const int cur = ck & 1;
        if (ck < 7) {
            const int c0 = (ck + 1) * 32;
            const int nxt = cur ^ 1;
#pragma unroll
            for (int tl = 0; tl < 4; tl++) {
                const int f4 = tid + tl * 256;
                const int row = f4 >> 5, cq = f4 & 31;
                *(float4*)&Xs[nxt][row * XS + cq * 4] =
                    to_tf32_4(*(const float4*)&xb[(long)(c0 + row) * NTOK + n0 + cq * 4]);
            }
#pragma unroll
            for (int tl = 0; tl < 2; tl++) {
                const int f4 = tid + tl * 256;
                const int row = f4 >> 3, cq = f4 & 7;
                *(float4*)&Wsm[nxt][row * WS + cq * 4] =
                    to_tf32_4(*(const float4*)&Wqkv[(long)(d0 + row) * CDIM + c0 + cq * 4]);
            }
        }
#pragma unroll
        for (int ks = 0; ks < 4; ks++) {
            const int k = ks * 8;
            unsigned a[4][4], bb[2][2];
#pragma unroll
            for (int mt = 0; mt < 4; mt++) {
                const int nb = wm * 64 + mt * 16 + g;
                a[mt][0] = __float_as_uint(Xs[cur][(k + t) * XS + nb]);
                a[mt][1] = __float_as_uint(Xs[cur][(k + t) * XS + nb + 8]);
                a[mt][2] = __float_as_uint(Xs[cur][(k + t + 4) * XS + nb]);
                a[mt][3] = __float_as_uint(Xs[cur][(k + t + 4) * XS + nb + 8]);
            }
#pragma unroll
            for (int nt = 0; nt < 2; nt++) {
                const float* wr = &Wsm[cur][(wn * 16 + nt * 8 + g) * WS + k + t];
                bb[nt][0] = __float_as_uint(wr[0]);
                bb[nt][1] = __float_as_uint(wr[4]);
            }
#pragma unroll
            for (int mt = 0; mt < 4; mt++)
#pragma unroll
                for (int nt = 0; nt < 2; nt++)
                    mma_tf32(acc[mt][nt], a[mt], bb[nt]);
        }
        __syncthreads();
    }

    const int seg = d0 >> 8;
    float* base = (seg == 0) ? g_Q : (seg == 1) ? g_K : g_V;
    const int dlocal0 = (d0 & 255);
#pragma unroll
    for (int mt = 0; mt < 4; mt++) {
        const int n = n0 + wm * 64 + mt * 16 + g;
#pragma unroll
        for (int nt = 0; nt < 2; nt++) {
            const int col = dlocal0 + wn * 16 + nt * 8 + 2 * t;
            *(float2*)&base[((long)b * NTOK + n) * CDIM + col] =
                make_float2(to_tf32(acc[mt][nt][0]), to_tf32(acc[mt][nt][1]));
            *(float2*)&base[((long)b * NTOK + n + 8) * CDIM + col] =
                make_float2(to_tf32(acc[mt][nt][2]), to_tf32(acc[mt][nt][3]));
        }
    }
}

// ---------------------------------------------------------------------------
// Kernel 2: tf32 mma flash attention, 64-query CTAs, packed-pair K/V layouts.
// 8 warps, 2m x 4n grid for both S (32x32) and PV (32x64). P via smem.
// ---------------------------------------------------------------------------
#define QSTR 260
#define KPSTR 72         // packed K row stride (64 cols + 8 pad); 72 % 32 == 8
#define VPSTR 520        // packed V row stride (256*2 + 8 pad);  520 % 32 == 8
#define PSTR 132
#define KVBUF (128 * KPSTR)   // 9216 floats >= 16*520 = 8320
#define ATTN_SMEM ((64 * QSTR + 2 * KVBUF + 64 * PSTR + 128 + 256) * 4)

__global__ __launch_bounds__(256, 1) void attn_kernel(const int* __restrict__ fg_mask) {
    extern __shared__ float sm[];
    float* Qs   = sm;                    // [64][260] plain
    float* KV0  = Qs + 64 * QSTR;
    float* KV1  = KV0 + KVBUF;
    float* Ps   = KV1 + KVBUF;           // [64][132] plain
    float* fgf  = Ps + 64 * PSTR;        // [128]
    float* lsum = fgf + 128;             // [4][64]

    const int b  = blockIdx.y;
    const int q0 = blockIdx.x * 64;
    const int tid = threadIdx.x;
    const int lane = tid & 31, w = tid >> 5;
    const int g = lane >> 2, t = lane & 3;
    const int wm = w >> 2, wn = w & 3;   // 2m x 4n for both phases

    const float* Qg = g_Q + ((long)b * NTOK + q0) * CDIM;
    const float* Kg = g_K + (long)b * NTOK * CDIM;
    const float* Vg = g_V + (long)b * NTOK * CDIM;

    // resident Q tile [64][256]
#pragma unroll
    for (int tl = 0; tl < 16; tl++) {
        const int f4 = tid + tl * 256;
        const int row = f4 >> 6, cq = f4 & 63;
        *(float4*)&Qs[row * QSTR + cq * 4] =
            *(const float4*)&Qg[(long)row * CDIM + cq * 4];
    }

    float oacc[2][8][4];
#pragma unroll
    for (int i = 0; i < 2; i++)
#pragma unroll
        for (int j = 0; j < 8; j++)
#pragma unroll
            for (int k = 0; k < 4; k++) oacc[i][j][k] = 0.0f;
    float rsum[4] = {0.0f, 0.0f, 0.0f, 0.0f};   // partial l, own (wn,t) slice

    const float SC = 0.0625f * 1.4426950408889634f;

    for (int m0 = 0; m0 < NTOK; m0 += 128) {
        if (tid < 128) fgf[tid] = fg_mask[b * NTOK + m0 + tid] ? 1.0f : 0.0f;

        // stage K c-chunk 0 into KV0 (packed pairs: cols (j, j+4) adjacent)
#pragma unroll
        for (int tl = 0; tl < 8; tl++) {
            const int f4 = tid + tl * 256;
            const int key = f4 >> 4, cq = f4 & 15;
            float4 v = *(const float4*)&Kg[(long)(m0 + key) * CDIM + cq * 4];
            float* dst = &KV0[key * KPSTR + (cq >> 1) * 8 + (cq & 1)];
            dst[0] = v.x; dst[2] = v.y; dst[4] = v.z; dst[6] = v.w;
        }
        __syncthreads();

        float sacc[2][4][4] = {};

        // ---- S phase: 4 c-chunks of 64, double-buffered ----
        for (int cc = 0; cc < 4; cc++) {
            float* cur = (cc & 1) ? KV1 : KV0;
            if (cc < 3) {
                float* nxt = (cc & 1) ? KV0 : KV1;
                const int c0 = (cc + 1) * 64;
#pragma unroll
                for (int tl = 0; tl < 8; tl++) {
                    const int f4 = tid + tl * 256;
                    const int key = f4 >> 4, cq = f4 & 15;
                    float4 v = *(const float4*)&Kg[(long)(m0 + key) * CDIM + c0 + cq * 4];
                    float* dst = &nxt[key * KPSTR + (cq >> 1) * 8 + (cq & 1)];
                    dst[0] = v.x; dst[2] = v.y; dst[4] = v.z; dst[6] = v.w;
                }
            }
            const int c0q = cc * 64;
#pragma unroll
            for (int ks = 0; ks < 8; ks++) {
                unsigned a[2][4];
#pragma unroll
                for (int mt = 0; mt < 2; mt++) {
                    const float* qr = &Qs[(wm * 32 + mt * 16 + g) * QSTR + c0q + ks * 8 + t];
                    a[mt][0] = __float_as_uint(qr[0]);
                    a[mt][1] = __float_as_uint(qr[8 * QSTR]);
                    a[mt][2] = __float_as_uint(qr[4]);
                    a[mt][3] = __float_as_uint(qr[8 * QSTR + 4]);
                }
#pragma unroll
                for (int nt = 0; nt < 4; nt++) {
                    float2 bv = *(const float2*)&cur[(wn * 32 + nt * 8 + g) * KPSTR + ks * 8 + t * 2];
                    unsigned bb[2] = {__float_as_uint(bv.x), __float_as_uint(bv.y)};
                    mma_tf32(sacc[0][nt], a[0], bb);
                    mma_tf32(sacc[1][nt], a[1], bb);
                }
            }
            __syncthreads();
        }

        // ---- softmax: mask * exp2(S*SC), tf32-round, store P, partial l ----
#pragma unroll
        for (int mt = 0; mt < 2; mt++) {
            const int r0 = wm * 32 + mt * 16 + g;
#pragma unroll
            for (int nt = 0; nt < 4; nt++) {
                const int col = wn * 32 + nt * 8 + 2 * t;
                const float f0 = fgf[col], f1 = fgf[col + 1];
                float p0 = to_tf32(ex2(sacc[mt][nt][0] * SC) * f0);
                float p1 = to_tf32(ex2(sacc[mt][nt][1] * SC) * f1);
                float p2 = to_tf32(ex2(sacc[mt][nt][2] * SC) * f0);
                float p3 = to_tf32(ex2(sacc[mt][nt][3] * SC) * f1);
                rsum[mt * 2 + 0] += p0 + p1;
                rsum[mt * 2 + 1] += p2 + p3;
                *(float2*)&Ps[r0 * PSTR + col] = make_float2(p0, p1);
                *(float2*)&Ps[(r0 + 8) * PSTR + col] = make_float2(p2, p3);
            }
        }

        // stage V key-chunk 0 into KV0 (packed pairs: rows (t, t+4) adjacent)
#pragma unroll
        for (int tl = 0; tl < 8; tl++) {
            const int f4 = tid + tl * 256;
            const int r = f4 >> 6, cq = f4 & 63;
            float4 v = *(const float4*)&Vg[(long)(m0 + r) * CDIM + cq * 4];
            float* dst = &KV0[((r >> 3) * 4 + (r & 3)) * VPSTR + cq * 8 + ((r >> 2) & 1)];
            dst[0] = v.x; dst[2] = v.y; dst[4] = v.z; dst[6] = v.w;
        }
        __syncthreads();

        // ---- PV phase: 4 key-chunks of 32, double-buffered ----
        for (int kc = 0; kc < 4; kc++) {
            float* cur = (kc & 1) ? KV1 : KV0;
            if (kc < 3) {
                float* nxt = (kc & 1) ? KV0 : KV1;
                const int kb = m0 + (kc + 1) * 32;
#pragma unroll
                for (int tl = 0; tl < 8; tl++) {
                    const int f4 = tid + tl * 256;
                    const int r = f4 >> 6, cq = f4 & 63;
                    float4 v = *(const float4*)&Vg[(long)(kb + r) * CDIM + cq * 4];
                    float* dst = &nxt[((r >> 3) * 4 + (r & 3)) * VPSTR + cq * 8 + ((r >> 2) & 1)];
                    dst[0] = v.x; dst[2] = v.y; dst[4] = v.z; dst[6] = v.w;
                }
            }
#pragma unroll
            for (int ks = 0; ks < 4; ks++) {
                unsigned a[2][4];
                const int kcol = kc * 32 + ks * 8 + t;
#pragma unroll
                for (int mt = 0; mt < 2; mt++) {
                    const float* pr = &Ps[(wm * 32 + mt * 16 + g) * PSTR + kcol];
                    a[mt][0] = __float_as_uint(pr[0]);
                    a[mt][1] = __float_as_uint(pr[8 * PSTR]);
                    a[mt][2] = __float_as_uint(pr[4]);
                    a[mt][3] = __float_as_uint(pr[8 * PSTR + 4]);
                }
#pragma unroll
                for (int nt = 0; nt < 8; nt++) {
                    float2 bv = *(const float2*)&cur[(ks * 4 + t) * VPSTR + (wn * 64 + nt * 8 + g) * 2];
                    unsigned bb[2] = {__float_as_uint(bv.x), __float_as_uint(bv.y)};
                    mma_tf32(oacc[0][nt], a[0], bb);
                    mma_tf32(oacc[1][nt], a[1], bb);
                }
            }
            __syncthreads();
        }
    }

    // ---- epilogue: reduce l (intra-quad shfl + cross-warp smem), store ----
#pragma unroll
    for (int i = 0; i < 4; i++) {
        rsum[i] += __shfl_xor_sync(FULLMASK, rsum[i], 1);
        rsum[i] += __shfl_xor_sync(FULLMASK, rsum[i], 2);
    }
    if (t == 0) {
#pragma unroll
        for (int i = 0; i < 4; i++)
            lsum[wn * 64 + wm * 32 + g + i * 8] = rsum[i];
    }
    __syncthreads();

    float* AOg = g_AO + ((long)b * NTOK + q0) * CDIM;
#pragma unroll
    for (int mt = 0; mt < 2; mt++) {
        const int r0 = wm * 32 + mt * 16 + g;
        const float la = lsum[r0] + lsum[64 + r0] + lsum[128 + r0] + lsum[192 + r0];
        const float lb = lsum[r0 + 8] + lsum[64 + r0 + 8] + lsum[128 + r0 + 8] + lsum[192 + r0 + 8];
        const float inv0 = 1.0f / la;
        const float inv1 = 1.0f / lb;
#pragma unroll
        for (int nt = 0; nt < 8; nt++) {
            const int col = wn * 64 + nt * 8 + 2 * t;
            *(float2*)&AOg[(long)r0 * CDIM + col] =
                make_float2(oacc[mt][nt][0] * inv0, oacc[mt][nt][1] * inv0);
            *(float2*)&AOg[(long)(r0 + 8) * CDIM + col] =
                make_float2(oacc[mt][nt][2] * inv1, oacc[mt][nt][3] * inv1);
        }
    }
}

// ---------------------------------------------------------------------------
// Kernel 3: projection via tf32 mma (unchanged from R5; passing).
// ---------------------------------------------------------------------------
#define AS 36
#define CS 132
#define PROJ_SMEM ((2 * (128 * AS + 64 * AS)) * 4)

__global__ __launch_bounds__(256) void proj_kernel(const float* __restrict__ Wp,
                                                   const float* __restrict__ bp,
                                                   float* __restrict__ out) {
    extern __shared__ float sp[];
    float* As[2] = {sp, sp + 128 * AS + 64 * AS};
    float* Wsm[2] = {sp + 128 * AS, sp + 2 * 128 * AS + 64 * AS};
    float* Cs = sp;

    const int b   = blockIdx.z;
    const int n0  = blockIdx.x * 128;
    const int co0 = blockIdx.y * 64;
    const int tid = threadIdx.x;
    const int lane = tid & 31, w = tid >> 5;
    const int g = lane >> 2, t = lane & 3;
    const int wm = w >> 2, wn = w & 3;

    const float* A = g_AO + ((long)b * NTOK + n0) * CDIM;

    float acc[4][2][4] = {};

    {
#pragma unroll
        for (int tl = 0; tl < 4; tl++) {
            const int f4 = tid + tl * 256;
            const int row = f4 >> 3, cq = f4 & 7;
            *(float4*)&As[0][row * AS + cq * 4] =
                to_tf32_4(*(const float4*)&A[(long)row * CDIM + cq * 4]);
        }
#pragma unroll
        for (int tl = 0; tl < 2; tl++) {
            const int f4 = tid + tl * 256;
            const int row = f4 >> 3, cq = f4 & 7;
            *(float4*)&Wsm[0][row * AS + cq * 4] =
                to_tf32_4(*(const float4*)&Wp[(long)(co0 + row) * CDIM + cq * 4]);
        }
    }
    __syncthreads();

    for (int ck = 0; ck < 8; ck++) {
        const int cur = ck & 1;
        if (ck < 7) {
            const int c0 = (ck + 1) * 32;
            const int nxt = cur ^ 1;
#pragma unroll
            for (int tl = 0; tl < 4; tl++) {
                const int f4 = tid + tl * 256;
                const int row = f4 >> 3, cq = f4 & 7;
                *(float4*)&As[nxt][row * AS + cq * 4] =
                    to_tf32_4(*(const float4*)&A[(long)row * CDIM + c0 + cq * 4]);
            }
#pragma unroll
            for (int tl = 0; tl < 2; tl++) {
                const int f4 = tid + tl * 256;
                const int row = f4 >> 3, cq = f4 & 7;
                *(float4*)&Wsm[nxt][row * AS + cq * 4] =
                    to_tf32_4(*(const float4*)&Wp[(long)(co0 + row) * CDIM + c0 + cq * 4]);
            }
        }
#pragma unroll
        for (int ks = 0; ks < 4; ks++) {
            const int k = ks * 8;
            unsigned a[4][4], bb[2][2];
#pragma unroll
            for (int mt = 0; mt < 4; mt++) {
                const float* ar = &As[cur][(wm * 64 + mt * 16 + g) * AS + k + t];
                a[mt][0] = __float_as_uint(ar[0]);
                a[mt][1] = __float_as_uint(ar[8 * AS]);
                a[mt][2] = __float_as_uint(ar[4]);
                a[mt][3] = __float_as_uint(ar[8 * AS + 4]);
            }
#pragma unroll
            for (int nt = 0; nt < 2; nt++) {
                const float* wr = &Wsm[cur][(wn * 16 + nt * 8 + g) * AS + k + t];
                bb[nt][0] = __float_as_uint(wr[0]);
                bb[nt][1] = __float_as_uint(wr[4]);
            }
#pragma unroll
            for (int mt = 0; mt < 4; mt++)
#pragma unroll
                for (int nt = 0; nt < 2; nt++)
                    mma_tf32(acc[mt][nt], a[mt], bb[nt]);
        }
        __syncthreads();
    }

#pragma unroll
    for (int mt = 0; mt < 4; mt++) {
        const int n = wm * 64 + mt * 16 + g;
#pragma unroll
        for (int nt = 0; nt < 2; nt++) {
            const int col = wn * 16 + nt * 8 + 2 * t;
            Cs[(col) * CS + n]         = acc[mt][nt][0];
            Cs[(col + 1) * CS + n]     = acc[mt][nt][1];
            Cs[(col) * CS + n + 8]     = acc[mt][nt][2];
            Cs[(col + 1) * CS + n + 8] = acc[mt][nt][3];
        }
    }
    __syncthreads();

#pragma unroll
    for (int tl = 0; tl < 8; tl++) {
        const int f4 = tid + tl * 256;
        const int row = f4 >> 5, cq = f4 & 31;
        const float bias = bp[co0 + row];
        float4 v = *(const float4*)&Cs[row * CS + cq * 4];
        v.x += bias; v.y += bias; v.z += bias; v.w += bias;
        *(float4*)&out[((long)b * CDIM + co0 + row) * NTOK + n0 + cq * 4] = v;
    }
}

// ---------------------------------------------------------------------------
extern "C" void kernel_launch(void* const* d_in, const int* in_sizes, int n_in,
                              void* d_out, int out_size) {
    const float* x    = (const float*)d_in[0];
    const int*   fg   = (const int*)d_in[1];
    const float* Wqkv = (const float*)d_in[2];
    const float* Wp   = (const float*)d_in[3];
    const float* bp   = (const float*)d_in[4];
    float* out = (float*)d_out;

    cudaFuncSetAttribute(qkv_kernel, cudaFuncAttributeMaxDynamicSharedMemorySize, QKV_SMEM);
    cudaFuncSetAttribute(attn_kernel, cudaFuncAttributeMaxDynamicSharedMemorySize, ATTN_SMEM);
    cudaFuncSetAttribute(proj_kernel, cudaFuncAttributeMaxDynamicSharedMemorySize, PROJ_SMEM);

    qkv_kernel<<<dim3(NTOK / 128, TCD / 64, BATCH), 256, QKV_SMEM>>>(x, Wqkv);
    attn_kernel<<<dim3(NTOK / 64, BATCH), 256, ATTN_SMEM>>>(fg);
    proj_kernel<<<dim3(NTOK / 128, CDIM / 64, BATCH), 256, PROJ_SMEM>>>(Wp, bp, out);
}

// round 7
// speedup vs baseline: 1.3294x; 1.2348x over previous
#include <cuda_runtime.h>

#define BATCH 4
#define CDIM 256
#define NTOK 4096   // 64*64
#define TCD 768     // 3*C
#define FULLMASK 0xffffffffu

// Scratch (allocation-free rule: __device__ globals)
__device__ float g_Q[BATCH * NTOK * CDIM];
__device__ float g_K[BATCH * NTOK * CDIM];
__device__ float g_V[BATCH * NTOK * CDIM];
__device__ float g_AO[BATCH * NTOK * CDIM];

__device__ __forceinline__ unsigned to_tf32_bits(float x) {
    unsigned r;
    asm("cvt.rna.tf32.f32 %0, %1;" : "=r"(r) : "f"(x));
    return r;
}
__device__ __forceinline__ float to_tf32(float x) {
    return __uint_as_float(to_tf32_bits(x));
}
__device__ __forceinline__ float4 to_tf32_4(float4 v) {
    return make_float4(to_tf32(v.x), to_tf32(v.y), to_tf32(v.z), to_tf32(v.w));
}
__device__ __forceinline__ void mma_tf32(float d[4], const unsigned a[4], const unsigned b[2]) {
    asm volatile(
        "mma.sync.aligned.m16n8k8.row.col.f32.tf32.tf32.f32 "
        "{%0,%1,%2,%3}, {%4,%5,%6,%7}, {%8,%9}, {%0,%1,%2,%3};\n"
        : "+f"(d[0]), "+f"(d[1]), "+f"(d[2]), "+f"(d[3])
        : "r"(a[0]), "r"(a[1]), "r"(a[2]), "r"(a[3]), "r"(b[0]), "r"(b[1]));
}

// ---------------------------------------------------------------------------
// Kernel 1: QKV GEMM via tf32 mma (R5 version — measured 99us).
// ---------------------------------------------------------------------------
#define XS 132
#define WS 36
#define QKV_SMEM ((2 * (32 * XS + 64 * WS)) * 4)

__global__ __launch_bounds__(256) void qkv_kernel(const float* __restrict__ x,
                                                  const float* __restrict__ Wqkv) {
    extern __shared__ float sq[];
    float* Xs[2] = {sq, sq + 32 * XS + 64 * WS};
    float* Wsm[2] = {sq + 32 * XS, sq + 2 * 32 * XS + 64 * WS};

    const int b  = blockIdx.z;
    const int n0 = blockIdx.x * 128;
    const int d0 = blockIdx.y * 64;
    const int tid = threadIdx.x;
    const int lane = tid & 31, w = tid >> 5;
    const int g = lane >> 2, t = lane & 3;
    const int wm = w >> 2, wn = w & 3;

    const float* xb = x + (long)b * CDIM * NTOK;

    float acc[4][2][4] = {};

    {
#pragma unroll
        for (int tl = 0; tl < 4; tl++) {
            const int f4 = tid + tl * 256;
            const int row = f4 >> 5, cq = f4 & 31;
            *(float4*)&Xs[0][row * XS + cq * 4] =
                to_tf32_4(*(const float4*)&xb[(long)row * NTOK + n0 + cq * 4]);
        }
#pragma unroll
        for (int tl = 0; tl < 2; tl++) {
            const int f4 = tid + tl * 256;
            const int row = f4 >> 3, cq = f4 & 7;
            *(float4*)&Wsm[0][row * WS + cq * 4] =
                to_tf32_4(*(const float4*)&Wqkv[(long)(d0 + row) * CDIM + cq * 4]);
        }
    }
    __syncthreads();

    for (int ck = 0; ck < 8; ck++) {
        const int cur = ck & 1;
        if (ck < 7) {
            const int c0 = (ck + 1) * 32;
            const int nxt = cur ^ 1;
#pragma unroll
            for (int tl = 0; tl < 4; tl++) {
                const int f4 = tid + tl * 256;
                const int row = f4 >> 5, cq = f4 & 31;
                *(float4*)&Xs[nxt][row * XS + cq * 4] =
                    to_tf32_4(*(const float4*)&xb[(long)(c0 + row) * NTOK + n0 + cq * 4]);
            }
#pragma unroll
            for (int tl = 0; tl < 2; tl++) {
                const int f4 = tid + tl * 256;
                const int row = f4 >> 3, cq = f4 & 7;
                *(float4*)&Wsm[nxt][row * WS + cq * 4] =
                    to_tf32_4(*(const float4*)&Wqkv[(long)(d0 + row) * CDIM + c0 + cq * 4]);
            }
        }
#pragma unroll
        for (int ks = 0; ks < 4; ks++) {
            const int k = ks * 8;
            unsigned a[4][4], bb[2][2];
#pragma unroll
            for (int mt = 0; mt < 4; mt++) {
                const int nb = wm * 64 + mt * 16 + g;
                a[mt][0] = __float_as_uint(Xs[cur][(k + t) * XS + nb]);
                a[mt][1] = __float_as_uint(Xs[cur][(k + t) * XS + nb + 8]);
                a[mt][2] = __float_as_uint(Xs[cur][(k + t + 4) * XS + nb]);
                a[mt][3] = __float_as_uint(Xs[cur][(k + t + 4) * XS + nb + 8]);
            }
#pragma unroll
            for (int nt = 0; nt < 2; nt++) {
                const float* wr = &Wsm[cur][(wn * 16 + nt * 8 + g) * WS + k + t];
                bb[nt][0] = __float_as_uint(wr[0]);
                bb[nt][1] = __float_as_uint(wr[4]);
            }
#pragma unroll
            for (int mt = 0; mt < 4; mt++)
#pragma unroll
                for (int nt = 0; nt < 2; nt++)
                    mma_tf32(acc[mt][nt], a[mt], bb[nt]);
        }
        __syncthreads();
    }

    const int seg = d0 >> 8;
    float* base = (seg == 0) ? g_Q : (seg == 1) ? g_K : g_V;
    const int dlocal0 = (d0 & 255);
#pragma unroll
    for (int mt = 0; mt < 4; mt++) {
        const int n = n0 + wm * 64 + mt * 16 + g;
#pragma unroll
        for (int nt = 0; nt < 2; nt++) {
            const int col = dlocal0 + wn * 16 + nt * 8 + 2 * t;
            *(float2*)&base[((long)b * NTOK + n) * CDIM + col] =
                make_float2(to_tf32(acc[mt][nt][0]), to_tf32(acc[mt][nt][1]));
            *(float2*)&base[((long)b * NTOK + n + 8) * CDIM + col] =
                make_float2(to_tf32(acc[mt][nt][2]), to_tf32(acc[mt][nt][3]));
        }
    }
}

// ---------------------------------------------------------------------------
// Kernel 2: tf32 mma flash attention — Round 3 version VERBATIM (measured
// fastest attention: ~600us). 128-query CTAs, 8 warps, S 4x2 / PV 2x4 grids,
// P through smem, no max-tracking.
// ---------------------------------------------------------------------------
#define QS_STRIDE 68
#define PS_STRIDE 132
#define VS_STRIDE 260
#define ATTN_SMEM ((128 * QS_STRIDE * 2 + 128 * PS_STRIDE + 32 * VS_STRIDE + 128 + 256 + 128) * 4)

__global__ __launch_bounds__(256) void attn_kernel(const int* __restrict__ fg_mask) {
    extern __shared__ float sm[];
    float* Qs    = sm;                        // [128][68]
    float* Ks    = Qs + 128 * QS_STRIDE;      // [128][68]
    float* Ps    = Ks + 128 * QS_STRIDE;      // [128][132]
    float* Vs    = Ps + 128 * PS_STRIDE;      // [32][260]
    float* fgf   = Vs + 32 * VS_STRIDE;       // [128]
    float* lsumP = fgf + 128;                 // [2][128]
    float* runl  = lsumP + 256;               // [128]

    const int b   = blockIdx.y;
    const int q0  = blockIdx.x * 128;
    const int tid = threadIdx.x;
    const int lane = tid & 31, w = tid >> 5;
    const int g = lane >> 2, t = lane & 3;
    const int wmS = w >> 1, wnS = w & 1;      // S: 4x2 warp grid, tile 32x64
    const int wmO = w >> 2, wnO = w & 3;      // O: 2x4 warp grid, tile 64x64

    const float* Qg = g_Q + ((long)b * NTOK + q0) * CDIM;
    const float* Kg = g_K + (long)b * NTOK * CDIM;
    const float* Vg = g_V + (long)b * NTOK * CDIM;

    if (tid < 128) runl[tid] = 0.0f;

    float oacc[4][8][4];
#pragma unroll
    for (int i = 0; i < 4; i++)
#pragma unroll
        for (int j = 0; j < 8; j++)
#pragma unroll
            for (int k = 0; k < 4; k++) oacc[i][j][k] = 0.0f;

    const float SC = 0.0625f * 1.4426950408889634f;   // (1/sqrt(C)) * log2(e)

    for (int m0 = 0; m0 < NTOK; m0 += 128) {
        if (tid < 128) fgf[tid] = fg_mask[b * NTOK + m0 + tid] ? 1.0f : 0.0f;

        float sacc[2][8][4] = {};

        // ---- S = Q K^T over 4 c-chunks of 64 ----
        for (int cc = 0; cc < 4; cc++) {
            const int c0 = cc * 64;
#pragma unroll
            for (int tl = 0; tl < 8; tl++) {
                const int f4 = tid + tl * 256;
                const int row = f4 >> 4, cq = f4 & 15;
                *(float4*)&Qs[row * QS_STRIDE + cq * 4] =
                    *(const float4*)&Qg[(long)row * CDIM + c0 + cq * 4];
                *(float4*)&Ks[row * QS_STRIDE + cq * 4] =
                    *(const float4*)&Kg[(long)(m0 + row) * CDIM + c0 + cq * 4];
            }
            __syncthreads();
#pragma unroll
            for (int ks = 0; ks < 8; ks++) {
                const int k = ks * 8;
                unsigned a[2][4], bb[8][2];
#pragma unroll
                for (int mt = 0; mt < 2; mt++) {
                    const float* qr = &Qs[(wmS * 32 + mt * 16 + g) * QS_STRIDE + k + t];
                    a[mt][0] = __float_as_uint(qr[0]);
                    a[mt][1] = __float_as_uint(qr[8 * QS_STRIDE]);
                    a[mt][2] = __float_as_uint(qr[4]);
                    a[mt][3] = __float_as_uint(qr[8 * QS_STRIDE + 4]);
                }
#pragma unroll
                for (int nt = 0; nt < 8; nt++) {
                    const float* kr = &Ks[(wnS * 64 + nt * 8 + g) * QS_STRIDE + k + t];
                    bb[nt][0] = __float_as_uint(kr[0]);
                    bb[nt][1] = __float_as_uint(kr[4]);
                }
#pragma unroll
                for (int mt = 0; mt < 2; mt++)
#pragma unroll
                    for (int nt = 0; nt < 8; nt++)
                        mma_tf32(sacc[mt][nt], a[mt], bb[nt]);
            }
            __syncthreads();
        }

        // ---- mask + exp (no max needed: |logit| <~ 2) + write P + row sums ----
        float rsum[4] = {0.0f, 0.0f, 0.0f, 0.0f};
#pragma unroll
        for (int mt = 0; mt < 2; mt++) {
            const int r0 = wmS * 32 + mt * 16 + g;
#pragma unroll
            for (int nt = 0; nt < 8; nt++) {
                const int col = wnS * 64 + nt * 8 + 2 * t;
                const float f0 = fgf[col], f1 = fgf[col + 1];
                float p0 = exp2f(sacc[mt][nt][0] * SC) * f0;
                float p1 = exp2f(sacc[mt][nt][1] * SC) * f1;
                float p2 = exp2f(sacc[mt][nt][2] * SC) * f0;
                float p3 = exp2f(sacc[mt][nt][3] * SC) * f1;
                rsum[mt * 2 + 0] += p0 + p1;
                rsum[mt * 2 + 1] += p2 + p3;
                *(float2*)&Ps[r0 * PS_STRIDE + col] =
                    make_float2(to_tf32(p0), to_tf32(p1));
                *(float2*)&Ps[(r0 + 8) * PS_STRIDE + col] =
                    make_float2(to_tf32(p2), to_tf32(p3));
            }
        }
#pragma unroll
        for (int si = 0; si < 4; si++) {
            rsum[si] += __shfl_xor_sync(0xffffffffu, rsum[si], 1);
            rsum[si] += __shfl_xor_sync(0xffffffffu, rsum[si], 2);
        }
        if (t == 0) {
            const int rb = wmS * 32 + g;
            lsumP[wnS * 128 + rb]          = rsum[0];
            lsumP[wnS * 128 + rb + 8]      = rsum[1];
            lsumP[wnS * 128 + rb + 16]     = rsum[2];
            lsumP[wnS * 128 + rb + 24]     = rsum[3];
        }
        __syncthreads();
        if (tid < 128) runl[tid] += lsumP[tid] + lsumP[128 + tid];

        // ---- O += P V over 4 key-chunks of 32 ----
        for (int kc = 0; kc < 4; kc++) {
#pragma unroll
            for (int tl = 0; tl < 8; tl++) {
                const int f4 = tid + tl * 256;
                const int row = f4 >> 6, cq = f4 & 63;
                *(float4*)&Vs[row * VS_STRIDE + cq * 4] =
                    *(const float4*)&Vg[(long)(m0 + kc * 32 + row) * CDIM + cq * 4];
            }
            __syncthreads();
#pragma unroll
            for (int ks = 0; ks < 4; ks++) {
                unsigned a[4][4], bb[8][2];
#pragma unroll
                for (int mt = 0; mt < 4; mt++) {
                    const float* pr =
                        &Ps[(wmO * 64 + mt * 16 + g) * PS_STRIDE + kc * 32 + ks * 8 + t];
                    a[mt][0] = __float_as_uint(pr[0]);
                    a[mt][1] = __float_as_uint(pr[8 * PS_STRIDE]);
                    a[mt][2] = __float_as_uint(pr[4]);
                    a[mt][3] = __float_as_uint(pr[8 * PS_STRIDE + 4]);
                }
#pragma unroll
                for (int nt = 0; nt < 8; nt++) {
                    const float* vr = &Vs[(ks * 8 + t) * VS_STRIDE + wnO * 64 + nt * 8 + g];
                    bb[nt][0] = __float_as_uint(vr[0]);
                    bb[nt][1] = __float_as_uint(vr[4 * VS_STRIDE]);
                }
#pragma unroll
                for (int mt = 0; mt < 4; mt++)
#pragma unroll
                    for (int nt = 0; nt < 8; nt++)
                        mma_tf32(oacc[mt][nt], a[mt], bb[nt]);
            }
            __syncthreads();
        }
    }

    // ---- epilogue: normalize by running l and store ----
    float* AOg = g_AO + ((long)b * NTOK + q0) * CDIM;
#pragma unroll
    for (int mt = 0; mt < 4; mt++) {
        const int r0 = wmO * 64 + mt * 16 + g;
        const float inv0 = 1.0f / runl[r0];
        const float inv1 = 1.0f / runl[r0 + 8];
#pragma unroll
        for (int nt = 0; nt < 8; nt++) {
            const int col = wnO * 64 + nt * 8 + 2 * t;
            *(float2*)&AOg[(long)r0 * CDIM + col] =
                make_float2(oacc[mt][nt][0] * inv0, oacc[mt][nt][1] * inv0);
            *(float2*)&AOg[(long)(r0 + 8) * CDIM + col] =
                make_float2(oacc[mt][nt][2] * inv1, oacc[mt][nt][3] * inv1);
        }
    }
}

// ---------------------------------------------------------------------------
// Kernel 3: projection via tf32 mma + bias + smem transpose store (R5 version).
// ---------------------------------------------------------------------------
#define AS 36
#define CS 132
#define PROJ_SMEM ((2 * (128 * AS + 64 * AS)) * 4)

__global__ __launch_bounds__(256) void proj_kernel(const float* __restrict__ Wp,
                                                   const float* __restrict__ bp,
                                                   float* __restrict__ out) {
    extern __shared__ float sp[];
    float* As[2] = {sp, sp + 128 * AS + 64 * AS};
    float* Wsm[2] = {sp + 128 * AS, sp + 2 * 128 * AS + 64 * AS};
    float* Cs = sp;

    const int b   = blockIdx.z;
    const int n0  = blockIdx.x * 128;
    const int co0 = blockIdx.y * 64;
    const int tid = threadIdx.x;
    const int lane = tid & 31, w = tid >> 5;
    const int g = lane >> 2, t = lane & 3;
    const int wm = w >> 2, wn = w & 3;

    const float* A = g_AO + ((long)b * NTOK + n0) * CDIM;

    float acc[4][2][4] = {};

    {
#pragma unroll
        for (int tl = 0; tl < 4; tl++) {
            const int f4 = tid + tl * 256;
            const int row = f4 >> 3, cq = f4 & 7;
            *(float4*)&As[0][row * AS + cq * 4] =
                to_tf32_4(*(const float4*)&A[(long)row * CDIM + cq * 4]);
        }
#pragma unroll
        for (int tl = 0; tl < 2; tl++) {
            const int f4 = tid + tl * 256;
            const int row = f4 >> 3, cq = f4 & 7;
            *(float4*)&Wsm[0][row * AS + cq * 4] =
                to_tf32_4(*(const float4*)&Wp[(long)(co0 + row) * CDIM + cq * 4]);
        }
    }
    __syncthreads();

    for (int ck = 0; ck < 8; ck++) {
        const int cur = ck & 1;
        if (ck < 7) {
            const int c0 = (ck + 1) * 32;
            const int nxt = cur ^ 1;
#pragma unroll
            for (int tl = 0; tl < 4; tl++) {
                const int f4 = tid + tl * 256;
                const int row = f4 >> 3, cq = f4 & 7;
                *(float4*)&As[nxt][row * AS + cq * 4] =
                    to_tf32_4(*(const float4*)&A[(long)row * CDIM + c0 + cq * 4]);
            }
#pragma unroll
            for (int tl = 0; tl < 2; tl++) {
                const int f4 = tid + tl * 256;
                const int row = f4 >> 3, cq = f4 & 7;
                *(float4*)&Wsm[nxt][row * AS + cq * 4] =
                    to_tf32_4(*(const float4*)&Wp[(long)(co0 + row) * CDIM + c0 + cq * 4]);
            }
        }
#pragma unroll
        for (int ks = 0; ks < 4; ks++) {
            const int k = ks * 8;
            unsigned a[4][4], bb[2][2];
#pragma unroll
            for (int mt = 0; mt < 4; mt++) {
                const float* ar = &As[cur][(wm * 64 + mt * 16 + g) * AS + k + t];
                a[mt][0] = __float_as_uint(ar[0]);
                a[mt][1] = __float_as_uint(ar[8 * AS]);
                a[mt][2] = __float_as_uint(ar[4]);
                a[mt][3] = __float_as_uint(ar[8 * AS + 4]);
            }
#pragma unroll
            for (int nt = 0; nt < 2; nt++) {
                const float* wr = &Wsm[cur][(wn * 16 + nt * 8 + g) * AS + k + t];
                bb[nt][0] = __float_as_uint(wr[0]);
                bb[nt][1] = __float_as_uint(wr[4]);
            }
#pragma unroll
            for (int mt = 0; mt < 4; mt++)
#pragma unroll
                for (int nt = 0; nt < 2; nt++)
                    mma_tf32(acc[mt][nt], a[mt], bb[nt]);
        }
        __syncthreads();
    }

#pragma unroll
    for (int mt = 0; mt < 4; mt++) {
        const int n = wm * 64 + mt * 16 + g;
#pragma unroll
        for (int nt = 0; nt < 2; nt++) {
            const int col = wn * 16 + nt * 8 + 2 * t;
            Cs[(col) * CS + n]         = acc[mt][nt][0];
            Cs[(col + 1) * CS + n]     = acc[mt][nt][1];
            Cs[(col) * CS + n + 8]     = acc[mt][nt][2];
            Cs[(col + 1) * CS + n + 8] = acc[mt][nt][3];
        }
    }
    __syncthreads();

#pragma unroll
    for (int tl = 0; tl < 8; tl++) {
        const int f4 = tid + tl * 256;
        const int row = f4 >> 5, cq = f4 & 31;
        const float bias = bp[co0 + row];
        float4 v = *(const float4*)&Cs[row * CS + cq * 4];
        v.x += bias; v.y += bias; v.z += bias; v.w += bias;
        *(float4*)&out[((long)b * CDIM + co0 + row) * NTOK + n0 + cq * 4] = v;
    }
}

// ---------------------------------------------------------------------------
extern "C" void kernel_launch(void* const* d_in, const int* in_sizes, int n_in,
                              void* d_out, int out_size) {
    const float* x    = (const float*)d_in[0];
    const int*   fg   = (const int*)d_in[1];
    const float* Wqkv = (const float*)d_in[2];
    const float* Wp   = (const float*)d_in[3];
    const float* bp   = (const float*)d_in[4];
    float* out = (float*)d_out;

    cudaFuncSetAttribute(qkv_kernel, cudaFuncAttributeMaxDynamicSharedMemorySize, QKV_SMEM);
    cudaFuncSetAttribute(attn_kernel, cudaFuncAttributeMaxDynamicSharedMemorySize, ATTN_SMEM);
    cudaFuncSetAttribute(proj_kernel, cudaFuncAttributeMaxDynamicSharedMemorySize, PROJ_SMEM);

    qkv_kernel<<<dim3(NTOK / 128, TCD / 64, BATCH), 256, QKV_SMEM>>>(x, Wqkv);
    attn_kernel<<<dim3(NTOK / 128, BATCH), 256, ATTN_SMEM>>>(fg);
    proj_kernel<<<dim3(NTOK / 128, CDIM / 64, BATCH), 256, PROJ_SMEM>>>(Wp, bp, out);
}

// round 8
// speedup vs baseline: 2.4961x; 1.8776x over previous
#include <cuda_runtime.h>
#include <cuda_fp16.h>

#define BATCH 4
#define CDIM 256
#define NTOK 4096   // 64*64
#define TCD 768     // 3*C
#define FULLMASK 0xffffffffu

// Scratch (allocation-free rule: __device__ globals)
__device__ __half g_Q[BATCH * NTOK * CDIM];
__device__ __half g_K[BATCH * NTOK * CDIM];
__device__ __half g_V[BATCH * NTOK * CDIM];
__device__ float  g_AO[BATCH * NTOK * CDIM];

__device__ __forceinline__ unsigned to_tf32_bits(float x) {
    unsigned r;
    asm("cvt.rna.tf32.f32 %0, %1;" : "=r"(r) : "f"(x));
    return r;
}
__device__ __forceinline__ float to_tf32(float x) {
    return __uint_as_float(to_tf32_bits(x));
}
__device__ __forceinline__ float4 to_tf32_4(float4 v) {
    return make_float4(to_tf32(v.x), to_tf32(v.y), to_tf32(v.z), to_tf32(v.w));
}
__device__ __forceinline__ float ex2(float x) {
    float r;
    asm("ex2.approx.f32 %0, %1;" : "=f"(r) : "f"(x));
    return r;
}
__device__ __forceinline__ void mma_tf32(float d[4], const unsigned a[4], const unsigned b[2]) {
    asm volatile(
        "mma.sync.aligned.m16n8k8.row.col.f32.tf32.tf32.f32 "
        "{%0,%1,%2,%3}, {%4,%5,%6,%7}, {%8,%9}, {%0,%1,%2,%3};\n"
        : "+f"(d[0]), "+f"(d[1]), "+f"(d[2]), "+f"(d[3])
        : "r"(a[0]), "r"(a[1]), "r"(a[2]), "r"(a[3]), "r"(b[0]), "r"(b[1]));
}
// fp16 inputs, fp32 accumulate. a/b regs are packed f16x2.
__device__ __forceinline__ void mma_f16(float d[4], const unsigned a[4],
                                        unsigned b0, unsigned b1) {
    asm volatile(
        "mma.sync.aligned.m16n8k16.row.col.f32.f16.f16.f32 "
        "{%0,%1,%2,%3}, {%4,%5,%6,%7}, {%8,%9}, {%0,%1,%2,%3};\n"
        : "+f"(d[0]), "+f"(d[1]), "+f"(d[2]), "+f"(d[3])
        : "r"(a[0]), "r"(a[1]), "r"(a[2]), "r"(a[3]), "r"(b0), "r"(b1));
}

// ---------------------------------------------------------------------------
// Kernel 1: QKV GEMM via tf32 mma (R5/R7 compute), epilogue emits fp16.
// ---------------------------------------------------------------------------
#define XS 132
#define WS 36
#define QKV_SMEM ((2 * (32 * XS + 64 * WS)) * 4)

__global__ __launch_bounds__(256) void qkv_kernel(const float* __restrict__ x,
                                                  const float* __restrict__ Wqkv) {
    extern __shared__ float sq[];
    float* Xs[2] = {sq, sq + 32 * XS + 64 * WS};
    float* Wsm[2] = {sq + 32 * XS, sq + 2 * 32 * XS + 64 * WS};

    const int b  = blockIdx.z;
    const int n0 = blockIdx.x * 128;
    const int d0 = blockIdx.y * 64;
    const int tid = threadIdx.x;
    const int lane = tid & 31, w = tid >> 5;
    const int g = lane >> 2, t = lane & 3;
    const int wm = w >> 2, wn = w & 3;

    const float* xb = x + (long)b * CDIM * NTOK;

    float acc[4][2][4] = {};

    {
#pragma unroll
        for (int tl = 0; tl < 4; tl++) {
            const int f4 = tid + tl * 256;
            const int row = f4 >> 5, cq = f4 & 31;
            *(float4*)&Xs[0][row * XS + cq * 4] =
                to_tf32_4(*(const float4*)&xb[(long)row * NTOK + n0 + cq * 4]);
        }
#pragma unroll
        for (int tl = 0; tl < 2; tl++) {
            const int f4 = tid + tl * 256;
            const int row = f4 >> 3, cq = f4 & 7;
            *(float4*)&Wsm[0][row * WS + cq * 4] =
                to_tf32_4(*(const float4*)&Wqkv[(long)(d0 + row) * CDIM + cq * 4]);
        }
    }
    __syncthreads();

    for (int ck = 0; ck < 8; ck++) {
        const int cur = ck & 1;
        if (ck < 7) {
            const int c0 = (ck + 1) * 32;
            const int nxt = cur ^ 1;
#pragma unroll
            for (int tl = 0; tl < 4; tl++) {
                const int f4 = tid + tl * 256;
                const int row = f4 >> 5, cq = f4 & 31;
                *(float4*)&Xs[nxt][row * XS + cq * 4] =
                    to_tf32_4(*(const float4*)&xb[(long)(c0 + row) * NTOK + n0 + cq * 4]);
            }
#pragma unroll
            for (int tl = 0; tl < 2; tl++) {
                const int f4 = tid + tl * 256;
                const int row = f4 >> 3, cq = f4 & 7;
                *(float4*)&Wsm[nxt][row * WS + cq * 4] =
                    to_tf32_4(*(const float4*)&Wqkv[(long)(d0 + row) * CDIM + c0 + cq * 4]);
            }
        }
#pragma unroll
        for (int ks = 0; ks < 4; ks++) {
            const int k = ks * 8;
            unsigned a[4][4], bb[2][2];
#pragma unroll
            for (int mt = 0; mt < 4; mt++) {
                const int nb = wm * 64 + mt * 16 + g;
                a[mt][0] = __float_as_uint(Xs[cur][(k + t) * XS + nb]);
                a[mt][1] = __float_as_uint(Xs[cur][(k + t) * XS + nb + 8]);
                a[mt][2] = __float_as_uint(Xs[cur][(k + t + 4) * XS + nb]);
                a[mt][3] = __float_as_uint(Xs[cur][(k + t + 4) * XS + nb + 8]);
            }
#pragma unroll
            for (int nt = 0; nt < 2; nt++) {
                const float* wr = &Wsm[cur][(wn * 16 + nt * 8 + g) * WS + k + t];
                bb[nt][0] = __float_as_uint(wr[0]);
                bb[nt][1] = __float_as_uint(wr[4]);
            }
#pragma unroll
            for (int mt = 0; mt < 4; mt++)
#pragma unroll
                for (int nt = 0; nt < 2; nt++)
                    mma_tf32(acc[mt][nt], a[mt], bb[nt]);
        }
        __syncthreads();
    }

    const int seg = d0 >> 8;
    __half* base = (seg == 0) ? g_Q : (seg == 1) ? g_K : g_V;
    const int dlocal0 = (d0 & 255);
#pragma unroll
    for (int mt = 0; mt < 4; mt++) {
        const int n = n0 + wm * 64 + mt * 16 + g;
#pragma unroll
        for (int nt = 0; nt < 2; nt++) {
            const int col = dlocal0 + wn * 16 + nt * 8 + 2 * t;
            *(__half2*)&base[((long)b * NTOK + n) * CDIM + col] =
                __floats2half2_rn(acc[mt][nt][0], acc[mt][nt][1]);
            *(__half2*)&base[((long)b * NTOK + n + 8) * CDIM + col] =
                __floats2half2_rn(acc[mt][nt][2], acc[mt][nt][3]);
        }
    }
}

// ---------------------------------------------------------------------------
// Kernel 2: fp16 mma flash attention. Q + full K tile resident; V overlays K
// buffer in key-pair-interleaved layout. 128-query CTAs, 8 warps,
// S 4x2 (32x64) / PV 2x4 (64x64) warp grids, P via fp16 smem. 4 syncs/tile.
// Word strides: Q/K 132 (=4 mod 32), P 68 (=4 mod 32), V-pairs 264 (=8 mod 32).
// ---------------------------------------------------------------------------
#define QW 132
#define PW 68
#define VW 264
#define KVW (128 * QW)   // 16896 words; V use: 64 * 264 = 16896 words
#define ATTN_SMEM ((128 * QW + KVW + 128 * PW) * 4 + (128 + 256 + 128) * 4)

__global__ __launch_bounds__(256, 1) void attn_kernel(const int* __restrict__ fg_mask) {
    extern __shared__ unsigned smw[];
    unsigned* Qw = smw;                      // [128][132] words (fp16 pairs)
    unsigned* Kw = Qw + 128 * QW;            // K tile OR V pair tile
    unsigned* Pw = Kw + KVW;                 // [128][68] words (fp16 pairs)
    float* fgf   = (float*)(Pw + 128 * PW);  // [128]
    float* lsumP = fgf + 128;                // [2][128]
    float* runl  = lsumP + 256;              // [128]

    const int b   = blockIdx.y;
    const int q0  = blockIdx.x * 128;
    const int tid = threadIdx.x;
    const int lane = tid & 31, w = tid >> 5;
    const int g = lane >> 2, t = lane & 3;
    const int wmS = w >> 1, wnS = w & 1;     // S: 4x2 grid, warp tile 32x64
    const int wmO = w >> 2, wnO = w & 3;     // O: 2x4 grid, warp tile 64x64

    const __half* Qg = g_Q + ((long)b * NTOK + q0) * CDIM;
    const __half* Kg = g_K + (long)b * NTOK * CDIM;
    const __half* Vg = g_V + (long)b * NTOK * CDIM;

    // stage resident Q tile: 128 rows x 256 halves
#pragma unroll
    for (int tl = 0; tl < 16; tl++) {
        const int u = tid + tl * 256;
        const int row = u >> 5, j = u & 31;
        uint4 v = *(const uint4*)&Qg[(long)row * CDIM + j * 8];
        *(uint4*)&Qw[row * QW + j * 4] = v;
    }
    if (tid < 128) runl[tid] = 0.0f;

    float oacc[4][8][4];
#pragma unroll
    for (int i = 0; i < 4; i++)
#pragma unroll
        for (int j = 0; j < 8; j++)
#pragma unroll
            for (int k = 0; k < 4; k++) oacc[i][j][k] = 0.0f;

    const float SC = 0.0625f * 1.4426950408889634f;   // 1/sqrt(C) * log2(e)

    for (int m0 = 0; m0 < NTOK; m0 += 128) {
        __syncthreads();   // prev PV done (V buffer free); Q visible on tile 0
        if (tid < 128) fgf[tid] = fg_mask[b * NTOK + m0 + tid] ? 1.0f : 0.0f;
        // stage K tile: 128 keys x 256 halves
#pragma unroll
        for (int tl = 0; tl < 16; tl++) {
            const int u = tid + tl * 256;
            const int row = u >> 5, j = u & 31;
            uint4 v = *(const uint4*)&Kg[(long)(m0 + row) * CDIM + j * 8];
            *(uint4*)&Kw[row * QW + j * 4] = v;
        }
        __syncthreads();

        // ---- S = Q K^T, K=256 in 16 steps of 16 ----
        float sacc[2][8][4] = {};
#pragma unroll
        for (int ks = 0; ks < 16; ks++) {
            unsigned a[2][4];
#pragma unroll
            for (int mt = 0; mt < 2; mt++) {
                const int base = (wmS * 32 + mt * 16 + g) * QW + ks * 8 + t;
                a[mt][0] = Qw[base];
                a[mt][1] = Qw[base + 8 * QW];
                a[mt][2] = Qw[base + 4];
                a[mt][3] = Qw[base + 8 * QW + 4];
            }
#pragma unroll
            for (int nt = 0; nt < 8; nt++) {
                const int kb = (wnS * 64 + nt * 8 + g) * QW + ks * 8 + t;
                const unsigned b0 = Kw[kb], b1 = Kw[kb + 4];
                mma_f16(sacc[0][nt], a[0], b0, b1);
                mma_f16(sacc[1][nt], a[1], b0, b1);
            }
        }

        // ---- softmax: mask * exp2(S*SC), write fp16 P, row sums ----
        float rsum[4] = {0.0f, 0.0f, 0.0f, 0.0f};
#pragma unroll
        for (int mt = 0; mt < 2; mt++) {
            const int r0 = wmS * 32 + mt * 16 + g;
#pragma unroll
            for (int nt = 0; nt < 8; nt++) {
                const int col = wnS * 64 + nt * 8 + 2 * t;
                const float f0 = fgf[col], f1 = fgf[col + 1];
                float p0 = ex2(sacc[mt][nt][0] * SC) * f0;
                float p1 = ex2(sacc[mt][nt][1] * SC) * f1;
                float p2 = ex2(sacc[mt][nt][2] * SC) * f0;
                float p3 = ex2(sacc[mt][nt][3] * SC) * f1;
                rsum[mt * 2 + 0] += p0 + p1;
                rsum[mt * 2 + 1] += p2 + p3;
                __half2 h01 = __floats2half2_rn(p0, p1);
                __half2 h23 = __floats2half2_rn(p2, p3);
                Pw[r0 * PW + (col >> 1)] = *(unsigned*)&h01;
                Pw[(r0 + 8) * PW + (col >> 1)] = *(unsigned*)&h23;
            }
        }
#pragma unroll
        for (int si = 0; si < 4; si++) {
            rsum[si] += __shfl_xor_sync(FULLMASK, rsum[si], 1);
            rsum[si] += __shfl_xor_sync(FULLMASK, rsum[si], 2);
        }
        if (t == 0) {
            const int rb = wmS * 32 + g;
            lsumP[wnS * 128 + rb]      = rsum[0];
            lsumP[wnS * 128 + rb + 8]  = rsum[1];
            lsumP[wnS * 128 + rb + 16] = rsum[2];
            lsumP[wnS * 128 + rb + 24] = rsum[3];
        }
        __syncthreads();   // S-MMA done reading Kw; lsumP visible
        if (tid < 128) runl[tid] += lsumP[tid] + lsumP[128 + tid];

        // ---- stage V into Kw buffer, key-pair interleaved:
        //      word[pr*VW + c] = {V[2pr][c] lo, V[2pr+1][c] hi} ----
#pragma unroll
        for (int s = 0; s < 8; s++) {
            const int u = tid + s * 256;
            const int pr = u >> 5, j = u & 31;
            uint4 va = *(const uint4*)&Vg[(long)(m0 + 2 * pr) * CDIM + j * 8];
            uint4 vb = *(const uint4*)&Vg[(long)(m0 + 2 * pr + 1) * CDIM + j * 8];
            uint4 w0, w1;
            w0.x = (va.x & 0xFFFFu) | (vb.x << 16);
            w0.y = (va.x >> 16) | (vb.x & 0xFFFF0000u);
            w0.z = (va.y & 0xFFFFu) | (vb.y << 16);
            w0.w = (va.y >> 16) | (vb.y & 0xFFFF0000u);
            w1.x = (va.z & 0xFFFFu) | (vb.z << 16);
            w1.y = (va.z >> 16) | (vb.z & 0xFFFF0000u);
            w1.z = (va.w & 0xFFFFu) | (vb.w << 16);
            w1.w = (va.w >> 16) | (vb.w & 0xFFFF0000u);
            *(uint4*)&Kw[pr * VW + j * 8] = w0;
            *(uint4*)&Kw[pr * VW + j * 8 + 4] = w1;
        }
        __syncthreads();

        // ---- O += P V, K=128 keys in 8 steps of 16 ----
#pragma unroll
        for (int ks = 0; ks < 8; ks++) {
            unsigned a[4][4];
#pragma unroll
            for (int mt = 0; mt < 4; mt++) {
                const int base = (wmO * 64 + mt * 16 + g) * PW + ks * 8 + t;
                a[mt][0] = Pw[base];
                a[mt][1] = Pw[base + 8 * PW];
                a[mt][2] = Pw[base + 4];
                a[mt][3] = Pw[base + 8 * PW + 4];
            }
#pragma unroll
            for (int nt = 0; nt < 8; nt++) {
                const int n = wnO * 64 + nt * 8 + g;
                const unsigned b0 = Kw[(ks * 8 + t) * VW + n];
                const unsigned b1 = Kw[(ks * 8 + t + 4) * VW + n];
#pragma unroll
                for (int mt = 0; mt < 4; mt++)
                    mma_f16(oacc[mt][nt], a[mt], b0, b1);
            }
        }
    }

    // ---- epilogue: normalize by running l and store fp32 AO ----
    float* AOg = g_AO + ((long)b * NTOK + q0) * CDIM;
#pragma unroll
    for (int mt = 0; mt < 4; mt++) {
        const int r0 = wmO * 64 + mt * 16 + g;
        const float inv0 = 1.0f / runl[r0];
        const float inv1 = 1.0f / runl[r0 + 8];
#pragma unroll
        for (int nt = 0; nt < 8; nt++) {
            const int col = wnO * 64 + nt * 8 + 2 * t;
            *(float2*)&AOg[(long)r0 * CDIM + col] =
                make_float2(oacc[mt][nt][0] * inv0, oacc[mt][nt][1] * inv0);
            *(float2*)&AOg[(long)(r0 + 8) * CDIM + col] =
                make_float2(oacc[mt][nt][2] * inv1, oacc[mt][nt][3] * inv1);
        }
    }
}

// ---------------------------------------------------------------------------
// Kernel 3: projection via tf32 mma + bias + smem transpose store (R7 version).
// ---------------------------------------------------------------------------
#define AS 36
#define CS 132
#define PROJ_SMEM ((2 * (128 * AS + 64 * AS)) * 4)

__global__ __launch_bounds__(256) void proj_kernel(const float* __restrict__ Wp,
                                                   const float* __restrict__ bp,
                                                   float* __restrict__ out) {
    extern __shared__ float sp[];
    float* As[2] = {sp, sp + 128 * AS + 64 * AS};
    float* Wsm[2] = {sp + 128 * AS, sp + 2 * 128 * AS + 64 * AS};
    float* Cs = sp;

    const int b   = blockIdx.z;
    const int n0  = blockIdx.x * 128;
    const int co0 = blockIdx.y * 64;
    const int tid = threadIdx.x;
    const int lane = tid & 31, w = tid >> 5;
    const int g = lane >> 2, t = lane & 3;
    const int wm = w >> 2, wn = w & 3;

    const float* A = g_AO + ((long)b * NTOK + n0) * CDIM;

    float acc[4][2][4] = {};

    {
#pragma unroll
        for (int tl = 0; tl < 4; tl++) {
            const int f4 = tid + tl * 256;
            const int row = f4 >> 3, cq = f4 & 7;
            *(float4*)&As[0][row * AS + cq * 4] =
                to_tf32_4(*(const float4*)&A[(long)row * CDIM + cq * 4]);
        }
#pragma unroll
        for (int tl = 0; tl < 2; tl++) {
            const int f4 = tid + tl * 256;
            const int row = f4 >> 3, cq = f4 & 7;
            *(float4*)&Wsm[0][row * AS + cq * 4] =
                to_tf32_4(*(const float4*)&Wp[(long)(co0 + row) * CDIM + cq * 4]);
        }
    }
    __syncthreads();

    for (int ck = 0; ck < 8; ck++) {
        const int cur = ck & 1;
        if (ck < 7) {
            const int c0 = (ck + 1) * 32;
            const int nxt = cur ^ 1;
#pragma unroll
            for (int tl = 0; tl < 4; tl++) {
                const int f4 = tid + tl * 256;
                const int row = f4 >> 3, cq = f4 & 7;
                *(float4*)&As[nxt][row * AS + cq * 4] =
                    to_tf32_4(*(const float4*)&A[(long)row * CDIM + c0 + cq * 4]);
            }
#pragma unroll
            for (int tl = 0; tl < 2; tl++) {
                const int f4 = tid + tl * 256;
                const int row = f4 >> 3, cq = f4 & 7;
                *(float4*)&Wsm[nxt][row * AS + cq * 4] =
                    to_tf32_4(*(const float4*)&Wp[(long)(co0 + row) * CDIM + c0 + cq * 4]);
            }
        }
#pragma unroll
        for (int ks = 0; ks < 4; ks++) {
            const int k = ks * 8;
            unsigned a[4][4], bb[2][2];
#pragma unroll
            for (int mt = 0; mt < 4; mt++) {
                const float* ar = &As[cur][(wm * 64 + mt * 16 + g) * AS + k + t];
                a[mt][0] = __float_as_uint(ar[0]);
                a[mt][1] = __float_as_uint(ar[8 * AS]);
                a[mt][2] = __float_as_uint(ar[4]);
                a[mt][3] = __float_as_uint(ar[8 * AS + 4]);
            }
#pragma unroll
            for (int nt = 0; nt < 2; nt++) {
                const float* wr = &Wsm[cur][(wn * 16 + nt * 8 + g) * AS + k + t];
                bb[nt][0] = __float_as_uint(wr[0]);
                bb[nt][1] = __float_as_uint(wr[4]);
            }
#pragma unroll
            for (int mt = 0; mt < 4; mt++)
#pragma unroll
                for (int nt = 0; nt < 2; nt++)
                    mma_tf32(acc[mt][nt], a[mt], bb[nt]);
        }
        __syncthreads();
    }

#pragma unroll
    for (int mt = 0; mt < 4; mt++) {
        const int n = wm * 64 + mt * 16 + g;
#pragma unroll
        for (int nt = 0; nt < 2; nt++) {
            const int col = wn * 16 + nt * 8 + 2 * t;
            Cs[(col) * CS + n]         = acc[mt][nt][0];
            Cs[(col + 1) * CS + n]     = acc[mt][nt][1];
            Cs[(col) * CS + n + 8]     = acc[mt][nt][2];
            Cs[(col + 1) * CS + n + 8] = acc[mt][nt][3];
        }
    }
    __syncthreads();

#pragma unroll
    for (int tl = 0; tl < 8; tl++) {
        const int f4 = tid + tl * 256;
        const int row = f4 >> 5, cq = f4 & 31;
        const float bias = bp[co0 + row];
        float4 v = *(const float4*)&Cs[row * CS + cq * 4];
        v.x += bias; v.y += bias; v.z += bias; v.w += bias;
        *(float4*)&out[((long)b * CDIM + co0 + row) * NTOK + n0 + cq * 4] = v;
    }
}

// ---------------------------------------------------------------------------
extern "C" void kernel_launch(void* const* d_in, const int* in_sizes, int n_in,
                              void* d_out, int out_size) {
    const float* x    = (const float*)d_in[0];
    const int*   fg   = (const int*)d_in[1];
    const float* Wqkv = (const float*)d_in[2];
    const float* Wp   = (const float*)d_in[3];
    const float* bp   = (const float*)d_in[4];
    float* out = (float*)d_out;

    cudaFuncSetAttribute(qkv_kernel, cudaFuncAttributeMaxDynamicSharedMemorySize, QKV_SMEM);
    cudaFuncSetAttribute(attn_kernel, cudaFuncAttributeMaxDynamicSharedMemorySize, ATTN_SMEM);
    cudaFuncSetAttribute(proj_kernel, cudaFuncAttributeMaxDynamicSharedMemorySize, PROJ_SMEM);

    qkv_kernel<<<dim3(NTOK / 128, TCD / 64, BATCH), 256, QKV_SMEM>>>(x, Wqkv);
    attn_kernel<<<dim3(NTOK / 128, BATCH), 256, ATTN_SMEM>>>(fg);
    proj_kernel<<<dim3(NTOK / 128, CDIM / 64, BATCH), 256, PROJ_SMEM>>>(Wp, bp, out);
}

// round 9
// speedup vs baseline: 2.8386x; 1.1372x over previous
#include <cuda_runtime.h>
#include <cuda_fp16.h>

#define BATCH 4
#define CDIM 256
#define NTOK 4096   // 64*64
#define TCD 768     // 3*C
#define FULLMASK 0xffffffffu

// Scratch (allocation-free rule: __device__ globals)
__device__ __half g_Q[BATCH * NTOK * CDIM];
__device__ __half g_K[BATCH * NTOK * CDIM];
__device__ __half g_V[BATCH * NTOK * CDIM];
__device__ float  g_AO[BATCH * NTOK * CDIM];

__device__ __forceinline__ float ex2(float x) {
    float r;
    asm("ex2.approx.f32 %0, %1;" : "=f"(r) : "f"(x));
    return r;
}
// fp16 inputs, fp32 accumulate. a/b regs are packed f16x2.
__device__ __forceinline__ void mma_f16(float d[4], const unsigned a[4],
                                        unsigned b0, unsigned b1) {
    asm volatile(
        "mma.sync.aligned.m16n8k16.row.col.f32.f16.f16.f32 "
        "{%0,%1,%2,%3}, {%4,%5,%6,%7}, {%8,%9}, {%0,%1,%2,%3};\n"
        : "+f"(d[0]), "+f"(d[1]), "+f"(d[2]), "+f"(d[3])
        : "r"(a[0]), "r"(a[1]), "r"(a[2]), "r"(a[3]), "r"(b0), "r"(b1));
}
__device__ __forceinline__ unsigned h2u(__half2 h) { return *(unsigned*)&h; }

// ---------------------------------------------------------------------------
// Kernel 1: QKV GEMM via fp16 mma.  C[n][d] = sum_c x[b,c,n] * Wqkv[d,c].
// X staged as c-pair words [cp][n] (stride 132: a-frag banks 4g+t distinct);
// W staged as natural c-pair words [d][cp]. Full K=256 resident, 0-sync loop.
// grid (32, 12, 4), 256 threads, warp tile 64n x 16d.
// ---------------------------------------------------------------------------
#define XSW 132
#define WSW 132
#define QKV_SMEM ((128 * XSW + 64 * WSW) * 4)

__global__ __launch_bounds__(256) void qkv_kernel(const float* __restrict__ x,
                                                  const float* __restrict__ Wqkv) {
    extern __shared__ unsigned sqw[];
    unsigned* Xw = sqw;              // [128 cp][132]; n = 0..127
    unsigned* Wh = sqw + 128 * XSW;  // [64 d][132];  cp = 0..127

    const int b  = blockIdx.z;
    const int n0 = blockIdx.x * 128;
    const int d0 = blockIdx.y * 64;
    const int tid = threadIdx.x;
    const int lane = tid & 31, w = tid >> 5;
    const int g = lane >> 2, t = lane & 3;
    const int wm = w >> 2, wn = w & 3;   // 2 x 4 warp grid

    const float* xb = x + (long)b * CDIM * NTOK;

    // stage X: word [cp][n] = {x[2cp][n], x[2cp+1][n]}
#pragma unroll
    for (int tl = 0; tl < 16; tl++) {
        const int u = tid + tl * 256;
        const int cp = u >> 5, j = u & 31;
        const float* rp = &xb[(long)(2 * cp) * NTOK + n0 + 4 * j];
        float4 va = *(const float4*)rp;
        float4 vb = *(const float4*)(rp + NTOK);
        uint4 wv;
        wv.x = h2u(__floats2half2_rn(va.x, vb.x));
        wv.y = h2u(__floats2half2_rn(va.y, vb.y));
        wv.z = h2u(__floats2half2_rn(va.z, vb.z));
        wv.w = h2u(__floats2half2_rn(va.w, vb.w));
        *(uint4*)&Xw[cp * XSW + 4 * j] = wv;
    }
    // stage W: word [d][cp] = {W[d][2cp], W[d][2cp+1]}
#pragma unroll
    for (int tl = 0; tl < 16; tl++) {
        const int u = tid + tl * 256;
        const int d = u >> 6, f = u & 63;
        float4 v = *(const float4*)&Wqkv[(long)(d0 + d) * CDIM + 4 * f];
        uint2 wv;
        wv.x = h2u(__floats2half2_rn(v.x, v.y));
        wv.y = h2u(__floats2half2_rn(v.z, v.w));
        *(uint2*)&Wh[d * WSW + 2 * f] = wv;
    }
    __syncthreads();

    float acc[4][2][4] = {};
#pragma unroll
    for (int ks = 0; ks < 16; ks++) {
        unsigned a[4][4];
#pragma unroll
        for (int mt = 0; mt < 4; mt++) {
            const int nb = wm * 64 + mt * 16 + g;
            a[mt][0] = Xw[(ks * 8 + t) * XSW + nb];
            a[mt][1] = Xw[(ks * 8 + t) * XSW + nb + 8];
            a[mt][2] = Xw[(ks * 8 + t + 4) * XSW + nb];
            a[mt][3] = Xw[(ks * 8 + t + 4) * XSW + nb + 8];
        }
#pragma unroll
        for (int nt = 0; nt < 2; nt++) {
            const int dn = wn * 16 + nt * 8 + g;
            const unsigned b0 = Wh[dn * WSW + ks * 8 + t];
            const unsigned b1 = Wh[dn * WSW + ks * 8 + t + 4];
#pragma unroll
            for (int mt = 0; mt < 4; mt++)
                mma_f16(acc[mt][nt], a[mt], b0, b1);
        }
    }

    const int seg = d0 >> 8;
    __half* base = (seg == 0) ? g_Q : (seg == 1) ? g_K : g_V;
    const int dlocal0 = (d0 & 255);
#pragma unroll
    for (int mt = 0; mt < 4; mt++) {
        const int n = n0 + wm * 64 + mt * 16 + g;
#pragma unroll
        for (int nt = 0; nt < 2; nt++) {
            const int col = dlocal0 + wn * 16 + nt * 8 + 2 * t;
            *(__half2*)&base[((long)b * NTOK + n) * CDIM + col] =
                __floats2half2_rn(acc[mt][nt][0], acc[mt][nt][1]);
            *(__half2*)&base[((long)b * NTOK + n + 8) * CDIM + col] =
                __floats2half2_rn(acc[mt][nt][2], acc[mt][nt][3]);
        }
    }
}

// ---------------------------------------------------------------------------
// Kernel 2: fp16 mma flash attention — Round 8 version VERBATIM (~265us).
// ---------------------------------------------------------------------------
#define QW 132
#define PW 68
#define VW 264
#define KVW (128 * QW)
#define ATTN_SMEM ((128 * QW + KVW + 128 * PW) * 4 + (128 + 256 + 128) * 4)

__global__ __launch_bounds__(256, 1) void attn_kernel(const int* __restrict__ fg_mask) {
    extern __shared__ unsigned smw[];
    unsigned* Qw = smw;                      // [128][132] words (fp16 pairs)
    unsigned* Kw = Qw + 128 * QW;            // K tile OR V pair tile
    unsigned* Pw = Kw + KVW;                 // [128][68] words (fp16 pairs)
    float* fgf   = (float*)(Pw + 128 * PW);  // [128]
    float* lsumP = fgf + 128;                // [2][128]
    float* runl  = lsumP + 256;              // [128]

    const int b   = blockIdx.y;
    const int q0  = blockIdx.x * 128;
    const int tid = threadIdx.x;
    const int lane = tid & 31, w = tid >> 5;
    const int g = lane >> 2, t = lane & 3;
    const int wmS = w >> 1, wnS = w & 1;     // S: 4x2 grid, warp tile 32x64
    const int wmO = w >> 2, wnO = w & 3;     // O: 2x4 grid, warp tile 64x64

    const __half* Qg = g_Q + ((long)b * NTOK + q0) * CDIM;
    const __half* Kg = g_K + (long)b * NTOK * CDIM;
    const __half* Vg = g_V + (long)b * NTOK * CDIM;

#pragma unroll
    for (int tl = 0; tl < 16; tl++) {
        const int u = tid + tl * 256;
        const int row = u >> 5, j = u & 31;
        uint4 v = *(const uint4*)&Qg[(long)row * CDIM + j * 8];
        *(uint4*)&Qw[row * QW + j * 4] = v;
    }
    if (tid < 128) runl[tid] = 0.0f;

    float oacc[4][8][4];
#pragma unroll
    for (int i = 0; i < 4; i++)
#pragma unroll
        for (int j = 0; j < 8; j++)
#pragma unroll
            for (int k = 0; k < 4; k++) oacc[i][j][k] = 0.0f;

    const float SC = 0.0625f * 1.4426950408889634f;

    for (int m0 = 0; m0 < NTOK; m0 += 128) {
        __syncthreads();
        if (tid < 128) fgf[tid] = fg_mask[b * NTOK + m0 + tid] ? 1.0f : 0.0f;
#pragma unroll
        for (int tl = 0; tl < 16; tl++) {
            const int u = tid + tl * 256;
            const int row = u >> 5, j = u & 31;
            uint4 v = *(const uint4*)&Kg[(long)(m0 + row) * CDIM + j * 8];
            *(uint4*)&Kw[row * QW + j * 4] = v;
        }
        __syncthreads();

        float sacc[2][8][4] = {};
#pragma unroll
        for (int ks = 0; ks < 16; ks++) {
            unsigned a[2][4];
#pragma unroll
            for (int mt = 0; mt < 2; mt++) {
                const int base = (wmS * 32 + mt * 16 + g) * QW + ks * 8 + t;
                a[mt][0] = Qw[base];
                a[mt][1] = Qw[base + 8 * QW];
                a[mt][2] = Qw[base + 4];
                a[mt][3] = Qw[base + 8 * QW + 4];
            }
#pragma unroll
            for (int nt = 0; nt < 8; nt++) {
                const int kb = (wnS * 64 + nt * 8 + g) * QW + ks * 8 + t;
                const unsigned b0 = Kw[kb], b1 = Kw[kb + 4];
                mma_f16(sacc[0][nt], a[0], b0, b1);
                mma_f16(sacc[1][nt], a[1], b0, b1);
            }
        }

        float rsum[4] = {0.0f, 0.0f, 0.0f, 0.0f};
#pragma unroll
        for (int mt = 0; mt < 2; mt++) {
            const int r0 = wmS * 32 + mt * 16 + g;
#pragma unroll
            for (int nt = 0; nt < 8; nt++) {
                const int col = wnS * 64 + nt * 8 + 2 * t;
                const float f0 = fgf[col], f1 = fgf[col + 1];
                float p0 = ex2(sacc[mt][nt][0] * SC) * f0;
                float p1 = ex2(sacc[mt][nt][1] * SC) * f1;
                float p2 = ex2(sacc[mt][nt][2] * SC) * f0;
                float p3 = ex2(sacc[mt][nt][3] * SC) * f1;
                rsum[mt * 2 + 0] += p0 + p1;
                rsum[mt * 2 + 1] += p2 + p3;
                __half2 h01 = __floats2half2_rn(p0, p1);
                __half2 h23 = __floats2half2_rn(p2, p3);
                Pw[r0 * PW + (col >> 1)] = *(unsigned*)&h01;
                Pw[(r0 + 8) * PW + (col >> 1)] = *(unsigned*)&h23;
            }
        }
#pragma unroll
        for (int si = 0; si < 4; si++) {
            rsum[si] += __shfl_xor_sync(FULLMASK, rsum[si], 1);
            rsum[si] += __shfl_xor_sync(FULLMASK, rsum[si], 2);
        }
        if (t == 0) {
            const int rb = wmS * 32 + g;
            lsumP[wnS * 128 + rb]      = rsum[0];
            lsumP[wnS * 128 + rb + 8]  = rsum[1];
            lsumP[wnS * 128 + rb + 16] = rsum[2];
            lsumP[wnS * 128 + rb + 24] = rsum[3];
        }
        __syncthreads();
        if (tid < 128) runl[tid] += lsumP[tid] + lsumP[128 + tid];

#pragma unroll
        for (int s = 0; s < 8; s++) {
            const int u = tid + s * 256;
            const int pr = u >> 5, j = u & 31;
            uint4 va = *(const uint4*)&Vg[(long)(m0 + 2 * pr) * CDIM + j * 8];
            uint4 vb = *(const uint4*)&Vg[(long)(m0 + 2 * pr + 1) * CDIM + j * 8];
            uint4 w0, w1;
            w0.x = (va.x & 0xFFFFu) | (vb.x << 16);
            w0.y = (va.x >> 16) | (vb.x & 0xFFFF0000u);
            w0.z = (va.y & 0xFFFFu) | (vb.y << 16);
            w0.w = (va.y >> 16) | (vb.y & 0xFFFF0000u);
            w1.x = (va.z & 0xFFFFu) | (vb.z << 16);
            w1.y = (va.z >> 16) | (vb.z & 0xFFFF0000u);
            w1.z = (va.w & 0xFFFFu) | (vb.w << 16);
            w1.w = (va.w >> 16) | (vb.w & 0xFFFF0000u);
            *(uint4*)&Kw[pr * VW + j * 8] = w0;
            *(uint4*)&Kw[pr * VW + j * 8 + 4] = w1;
        }
        __syncthreads();

#pragma unroll
        for (int ks = 0; ks < 8; ks++) {
            unsigned a[4][4];
#pragma unroll
            for (int mt = 0; mt < 4; mt++) {
                const int base = (wmO * 64 + mt * 16 + g) * PW + ks * 8 + t;
                a[mt][0] = Pw[base];
                a[mt][1] = Pw[base + 8 * PW];
                a[mt][2] = Pw[base + 4];
                a[mt][3] = Pw[base + 8 * PW + 4];
            }
#pragma unroll
            for (int nt = 0; nt < 8; nt++) {
                const int n = wnO * 64 + nt * 8 + g;
                const unsigned b0 = Kw[(ks * 8 + t) * VW + n];
                const unsigned b1 = Kw[(ks * 8 + t + 4) * VW + n];
#pragma unroll
                for (int mt = 0; mt < 4; mt++)
                    mma_f16(oacc[mt][nt], a[mt], b0, b1);
            }
        }
    }

    float* AOg = g_AO + ((long)b * NTOK + q0) * CDIM;
#pragma unroll
    for (int mt = 0; mt < 4; mt++) {
        const int r0 = wmO * 64 + mt * 16 + g;
        const float inv0 = 1.0f / runl[r0];
        const float inv1 = 1.0f / runl[r0 + 8];
#pragma unroll
        for (int nt = 0; nt < 8; nt++) {
            const int col = wnO * 64 + nt * 8 + 2 * t;
            *(float2*)&AOg[(long)r0 * CDIM + col] =
                make_float2(oacc[mt][nt][0] * inv0, oacc[mt][nt][1] * inv0);
            *(float2*)&AOg[(long)(r0 + 8) * CDIM + col] =
                make_float2(oacc[mt][nt][2] * inv1, oacc[mt][nt][3] * inv1);
        }
    }
}

// ---------------------------------------------------------------------------
// Kernel 3: projection via fp16 mma + bias + smem transpose store.
// AO [n][c] row-major: c-pairs naturally adjacent -> direct half2 packing.
// grid (32, 4, 4), 256 threads, warp tile 64n x 16d. 0-sync mainloop.
// ---------------------------------------------------------------------------
#define ASW 132
#define PWS 132
#define CS 132
#define PROJ_SMEM ((128 * ASW + 64 * PWS) * 4)

__global__ __launch_bounds__(256) void proj_kernel(const float* __restrict__ Wp,
                                                   const float* __restrict__ bp,
                                                   float* __restrict__ out) {
    extern __shared__ unsigned spw[];
    unsigned* Ah = spw;              // [128 n][132]
    unsigned* Wh = spw + 128 * ASW;  // [64 d][132]
    float* Cs = (float*)spw;         // overlay after GEMM

    const int b   = blockIdx.z;
    const int n0  = blockIdx.x * 128;
    const int co0 = blockIdx.y * 64;
    const int tid = threadIdx.x;
    const int lane = tid & 31, w = tid >> 5;
    const int g = lane >> 2, t = lane & 3;
    const int wm = w >> 2, wn = w & 3;

    const float* A = g_AO + ((long)b * NTOK + n0) * CDIM;

    // stage AO as half2 words [n][cp]
#pragma unroll
    for (int tl = 0; tl < 32; tl++) {
        const int u = tid + tl * 256;
        const int n = u >> 6, f = u & 63;
        float4 v = *(const float4*)&A[(long)n * CDIM + 4 * f];
        uint2 wv;
        wv.x = h2u(__floats2half2_rn(v.x, v.y));
        wv.y = h2u(__floats2half2_rn(v.z, v.w));
        *(uint2*)&Ah[n * ASW + 2 * f] = wv;
    }
#pragma unroll
    for (int tl = 0; tl < 16; tl++) {
        const int u = tid + tl * 256;
        const int d = u >> 6, f = u & 63;
        float4 v = *(const float4*)&Wp[(long)(co0 + d) * CDIM + 4 * f];
        uint2 wv;
        wv.x = h2u(__floats2half2_rn(v.x, v.y));
        wv.y = h2u(__floats2half2_rn(v.z, v.w));
        *(uint2*)&Wh[d * PWS + 2 * f] = wv;
    }
    __syncthreads();

    float acc[4][2][4] = {};
#pragma unroll
    for (int ks = 0; ks < 16; ks++) {
        unsigned a[4][4];
#pragma unroll
        for (int mt = 0; mt < 4; mt++) {
            const int row = wm * 64 + mt * 16 + g;
            a[mt][0] = Ah[row * ASW + ks * 8 + t];
            a[mt][1] = Ah[(row + 8) * ASW + ks * 8 + t];
            a[mt][2] = Ah[row * ASW + ks * 8 + t + 4];
            a[mt][3] = Ah[(row + 8) * ASW + ks * 8 + t + 4];
        }
#pragma unroll
        for (int nt = 0; nt < 2; nt++) {
            const int dn = wn * 16 + nt * 8 + g;
            const unsigned b0 = Wh[dn * PWS + ks * 8 + t];
            const unsigned b1 = Wh[dn * PWS + ks * 8 + t + 4];
#pragma unroll
            for (int mt = 0; mt < 4; mt++)
                mma_f16(acc[mt][nt], a[mt], b0, b1);
        }
    }
    __syncthreads();   // smem free; overlay Cs

    // stage transposed into Cs[d][n]
#pragma unroll
    for (int mt = 0; mt < 4; mt++) {
        const int n = wm * 64 + mt * 16 + g;
#pragma unroll
        for (int nt = 0; nt < 2; nt++) {
            const int col = wn * 16 + nt * 8 + 2 * t;
            Cs[(col) * CS + n]         = acc[mt][nt][0];
            Cs[(col + 1) * CS + n]     = acc[mt][nt][1];
            Cs[(col) * CS + n + 8]     = acc[mt][nt][2];
            Cs[(col + 1) * CS + n + 8] = acc[mt][nt][3];
        }
    }
    __syncthreads();

    // coalesced store out[b][co0+d][n0..n0+128) with bias
#pragma unroll
    for (int tl = 0; tl < 8; tl++) {
        const int f4 = tid + tl * 256;
        const int row = f4 >> 5, cq = f4 & 31;
        const float bias = bp[co0 + row];
        float4 v = *(const float4*)&Cs[row * CS + cq * 4];
        v.x += bias; v.y += bias; v.z += bias; v.w += bias;
        *(float4*)&out[((long)b * CDIM + co0 + row) * NTOK + n0 + cq * 4] = v;
    }
}

// ---------------------------------------------------------------------------
extern "C" void kernel_launch(void* const* d_in, const int* in_sizes, int n_in,
                              void* d_out, int out_size) {
    const float* x    = (const float*)d_in[0];
    const int*   fg   = (const int*)d_in[1];
    const float* Wqkv = (const float*)d_in[2];
    const float* Wp   = (const float*)d_in[3];
    const float* bp   = (const float*)d_in[4];
    float* out = (float*)d_out;

    cudaFuncSetAttribute(qkv_kernel, cudaFuncAttributeMaxDynamicSharedMemorySize, QKV_SMEM);
    cudaFuncSetAttribute(attn_kernel, cudaFuncAttributeMaxDynamicSharedMemorySize, ATTN_SMEM);
    cudaFuncSetAttribute(proj_kernel, cudaFuncAttributeMaxDynamicSharedMemorySize, PROJ_SMEM);

    qkv_kernel<<<dim3(NTOK / 128, TCD / 64, BATCH), 256, QKV_SMEM>>>(x, Wqkv);
    attn_kernel<<<dim3(NTOK / 128, BATCH), 256, ATTN_SMEM>>>(fg);
    proj_kernel<<<dim3(NTOK / 128, CDIM / 64, BATCH), 256, PROJ_SMEM>>>(Wp, bp, out);
}

// round 10
// speedup vs baseline: 3.0852x; 1.0869x over previous
#include <cuda_runtime.h>
#include <cuda_fp16.h>

#define BATCH 4
#define CDIM 256
#define NTOK 4096   // 64*64
#define TCD 768     // 3*C
#define FULLMASK 0xffffffffu

// Scratch (allocation-free rule: __device__ globals)
__device__ __half g_Q[BATCH * NTOK * CDIM];
__device__ __half g_K[BATCH * NTOK * CDIM];
__device__ __half g_V[BATCH * NTOK * CDIM];
__device__ float  g_AO[BATCH * NTOK * CDIM];

__device__ __forceinline__ float ex2(float x) {
    float r;
    asm("ex2.approx.f32 %0, %1;" : "=f"(r) : "f"(x));
    return r;
}
__device__ __forceinline__ void mma_f16(float d[4], const unsigned a[4],
                                        unsigned b0, unsigned b1) {
    asm volatile(
        "mma.sync.aligned.m16n8k16.row.col.f32.f16.f16.f32 "
        "{%0,%1,%2,%3}, {%4,%5,%6,%7}, {%8,%9}, {%0,%1,%2,%3};\n"
        : "+f"(d[0]), "+f"(d[1]), "+f"(d[2]), "+f"(d[3])
        : "r"(a[0]), "r"(a[1]), "r"(a[2]), "r"(a[3]), "r"(b0), "r"(b1));
}
__device__ __forceinline__ unsigned h2u(__half2 h) { return *(unsigned*)&h; }
__device__ __forceinline__ unsigned s2u(const void* p) {
    unsigned u;
    asm("{ .reg .u64 t; cvta.to.shared.u64 t, %1; cvt.u32.u64 %0, t; }"
        : "=r"(u) : "l"(p));
    return u;
}
__device__ __forceinline__ void ldsm_x4(unsigned r[4], unsigned addr) {
    asm volatile("ldmatrix.sync.aligned.m8n8.x4.shared.b16 {%0,%1,%2,%3}, [%4];"
        : "=r"(r[0]), "=r"(r[1]), "=r"(r[2]), "=r"(r[3]) : "r"(addr));
}
__device__ __forceinline__ void ldsm_x4_t(unsigned r[4], unsigned addr) {
    asm volatile("ldmatrix.sync.aligned.m8n8.x4.trans.shared.b16 {%0,%1,%2,%3}, [%4];"
        : "=r"(r[0]), "=r"(r[1]), "=r"(r[2]), "=r"(r[3]) : "r"(addr));
}

// ---------------------------------------------------------------------------
// Kernel 1: QKV GEMM via fp16 mma (R9 version verbatim — 62.6us).
// ---------------------------------------------------------------------------
#define XSW 132
#define WSW 132
#define QKV_SMEM ((128 * XSW + 64 * WSW) * 4)

__global__ __launch_bounds__(256) void qkv_kernel(const float* __restrict__ x,
                                                  const float* __restrict__ Wqkv) {
    extern __shared__ unsigned sqw[];
    unsigned* Xw = sqw;              // [128 cp][132]; n = 0..127
    unsigned* Wh = sqw + 128 * XSW;  // [64 d][132];  cp = 0..127

    const int b  = blockIdx.z;
    const int n0 = blockIdx.x * 128;
    const int d0 = blockIdx.y * 64;
    const int tid = threadIdx.x;
    const int lane = tid & 31, w = tid >> 5;
    const int g = lane >> 2, t = lane & 3;
    const int wm = w >> 2, wn = w & 3;

    const float* xb = x + (long)b * CDIM * NTOK;

#pragma unroll
    for (int tl = 0; tl < 16; tl++) {
        const int u = tid + tl * 256;
        const int cp = u >> 5, j = u & 31;
        const float* rp = &xb[(long)(2 * cp) * NTOK + n0 + 4 * j];
        float4 va = *(const float4*)rp;
        float4 vb = *(const float4*)(rp + NTOK);
        uint4 wv;
        wv.x = h2u(__floats2half2_rn(va.x, vb.x));
        wv.y = h2u(__floats2half2_rn(va.y, vb.y));
        wv.z = h2u(__floats2half2_rn(va.z, vb.z));
        wv.w = h2u(__floats2half2_rn(va.w, vb.w));
        *(uint4*)&Xw[cp * XSW + 4 * j] = wv;
    }
#pragma unroll
    for (int tl = 0; tl < 16; tl++) {
        const int u = tid + tl * 256;
        const int d = u >> 6, f = u & 63;
        float4 v = *(const float4*)&Wqkv[(long)(d0 + d) * CDIM + 4 * f];
        uint2 wv;
        wv.x = h2u(__floats2half2_rn(v.x, v.y));
        wv.y = h2u(__floats2half2_rn(v.z, v.w));
        *(uint2*)&Wh[d * WSW + 2 * f] = wv;
    }
    __syncthreads();

    float acc[4][2][4] = {};
#pragma unroll
    for (int ks = 0; ks < 16; ks++) {
        unsigned a[4][4];
#pragma unroll
        for (int mt = 0; mt < 4; mt++) {
            const int nb = wm * 64 + mt * 16 + g;
            a[mt][0] = Xw[(ks * 8 + t) * XSW + nb];
            a[mt][1] = Xw[(ks * 8 + t) * XSW + nb + 8];
            a[mt][2] = Xw[(ks * 8 + t + 4) * XSW + nb];
            a[mt][3] = Xw[(ks * 8 + t + 4) * XSW + nb + 8];
        }
#pragma unroll
        for (int nt = 0; nt < 2; nt++) {
            const int dn = wn * 16 + nt * 8 + g;
            const unsigned b0 = Wh[dn * WSW + ks * 8 + t];
            const unsigned b1 = Wh[dn * WSW + ks * 8 + t + 4];
#pragma unroll
            for (int mt = 0; mt < 4; mt++)
                mma_f16(acc[mt][nt], a[mt], b0, b1);
        }
    }

    const int seg = d0 >> 8;
    __half* base = (seg == 0) ? g_Q : (seg == 1) ? g_K : g_V;
    const int dlocal0 = (d0 & 255);
#pragma unroll
    for (int mt = 0; mt < 4; mt++) {
        const int n = n0 + wm * 64 + mt * 16 + g;
#pragma unroll
        for (int nt = 0; nt < 2; nt++) {
            const int col = dlocal0 + wn * 16 + nt * 8 + 2 * t;
            *(__half2*)&base[((long)b * NTOK + n) * CDIM + col] =
                __floats2half2_rn(acc[mt][nt][0], acc[mt][nt][1]);
            *(__half2*)&base[((long)b * NTOK + n + 8) * CDIM + col] =
                __floats2half2_rn(acc[mt][nt][2], acc[mt][nt][3]);
        }
    }
}

// ---------------------------------------------------------------------------
// Kernel 2: fp16 mma flash attention with LDSM fragment loads.
// Q resident; K and V staged as plain [row][c] tiles (stride QW, shared
// buffer); V B-frags via ldmatrix.trans (no repack). 128-query CTAs, 8 warps.
// ---------------------------------------------------------------------------
#define QW 132
#define PW 68
#define KVW (128 * QW)
#define ATTN_SMEM ((128 * QW + KVW + 128 * PW) * 4 + (128 + 256 + 128) * 4)

__global__ __launch_bounds__(256, 1) void attn_kernel(const int* __restrict__ fg_mask) {
    extern __shared__ unsigned smw[];
    unsigned* Qw = smw;                      // [128][132] words (fp16 pairs)
    unsigned* Kw = Qw + 128 * QW;            // K tile, then V tile (plain)
    unsigned* Pw = Kw + KVW;                 // [128][68] words (fp16 pairs)
    float* fgf   = (float*)(Pw + 128 * PW);  // [128]
    float* lsumP = fgf + 128;                // [2][128]
    float* runl  = lsumP + 256;              // [128]

    const int b   = blockIdx.y;
    const int q0  = blockIdx.x * 128;
    const int tid = threadIdx.x;
    const int lane = tid & 31, w = tid >> 5;
    const int g = lane >> 2, t = lane & 3;
    const int wmS = w >> 1, wnS = w & 1;     // S: 4x2 grid, warp tile 32x64
    const int wmO = w >> 2, wnO = w & 3;     // O: 2x4 grid, warp tile 64x64

    const __half* Qg = g_Q + ((long)b * NTOK + q0) * CDIM;
    const __half* Kg = g_K + (long)b * NTOK * CDIM;
    const __half* Vg = g_V + (long)b * NTOK * CDIM;

    // stage resident Q tile: 128 rows x 256 halves
#pragma unroll
    for (int tl = 0; tl < 16; tl++) {
        const int u = tid + tl * 256;
        const int row = u >> 5, j = u & 31;
        uint4 v = *(const uint4*)&Qg[(long)row * CDIM + j * 8];
        *(uint4*)&Qw[row * QW + j * 4] = v;
    }
    if (tid < 128) runl[tid] = 0.0f;

    // ldmatrix base addresses (per-lane, loop-invariant)
    // A-frags (Q): m0 rows 0-7 k0-7 | m1 rows 8-15 k0-7 | m2 rows 0-7 k8-15 | m3 rows 8-15 k8-15
    const unsigned qaB = s2u(Qw) +
        (((wmS * 32 + (lane & 15)) * QW + 4 * (lane >> 4)) << 2);
    // B-frags (K), 2 n-tiles per x4: m0 rows nt*8+0-7 k0-7 | m1 same rows k8-15
    //                                 m2 rows +8 k0-7      | m3 rows +8 k8-15
    const unsigned kbB = s2u(Kw) +
        (((wnS * 64 + ((lane >> 4) << 3) + (lane & 7)) * QW + ((lane >> 3) & 1) * 4) << 2);
    // A-frags (P): same pattern as Q with stride PW
    const unsigned paB = s2u(Pw) +
        (((wmO * 64 + (lane & 15)) * PW + 4 * (lane >> 4)) << 2);
    // B-frags (V) via trans, 2 n-tiles per x4: rows = keys, cols = c
    const unsigned vbB = s2u(Kw) + (((lane & 15) * QW) << 2) +
        ((wnO * 64 + (lane >> 4) * 8) << 1);

    float oacc[4][8][4];
#pragma unroll
    for (int i = 0; i < 4; i++)
#pragma unroll
        for (int j = 0; j < 8; j++)
#pragma unroll
            for (int k = 0; k < 4; k++) oacc[i][j][k] = 0.0f;

    const float SC = 0.0625f * 1.4426950408889634f;

    for (int m0 = 0; m0 < NTOK; m0 += 128) {
        __syncthreads();   // prev PV done reading V buffer; Q visible on tile 0
        if (tid < 128) fgf[tid] = fg_mask[b * NTOK + m0 + tid] ? 1.0f : 0.0f;
        // stage K tile
#pragma unroll
        for (int tl = 0; tl < 16; tl++) {
            const int u = tid + tl * 256;
            const int row = u >> 5, j = u & 31;
            uint4 v = *(const uint4*)&Kg[(long)(m0 + row) * CDIM + j * 8];
            *(uint4*)&Kw[row * QW + j * 4] = v;
        }
        __syncthreads();

        // ---- S = Q K^T, K=256 in 16 steps of 16 ----
        float sacc[2][8][4] = {};
#pragma unroll
        for (int ks = 0; ks < 16; ks++) {
            unsigned a[2][4];
            ldsm_x4(a[0], qaB + ((ks * 8) << 2));
            ldsm_x4(a[1], qaB + ((16 * QW + ks * 8) << 2));
#pragma unroll
            for (int ntp = 0; ntp < 4; ntp++) {
                unsigned bb[4];
                ldsm_x4(bb, kbB + ((ntp * 16 * QW + ks * 8) << 2));
                mma_f16(sacc[0][2 * ntp], a[0], bb[0], bb[1]);
                mma_f16(sacc[1][2 * ntp], a[1], bb[0], bb[1]);
                mma_f16(sacc[0][2 * ntp + 1], a[0], bb[2], bb[3]);
                mma_f16(sacc[1][2 * ntp + 1], a[1], bb[2], bb[3]);
            }
        }

        // ---- softmax: mask * exp2(S*SC), write fp16 P, row sums ----
        float rsum[4] = {0.0f, 0.0f, 0.0f, 0.0f};
#pragma unroll
        for (int mt = 0; mt < 2; mt++) {
            const int r0 = wmS * 32 + mt * 16 + g;
#pragma unroll
            for (int nt = 0; nt < 8; nt++) {
                const int col = wnS * 64 + nt * 8 + 2 * t;
                const float f0 = fgf[col], f1 = fgf[col + 1];
                float p0 = ex2(sacc[mt][nt][0] * SC) * f0;
                float p1 = ex2(sacc[mt][nt][1] * SC) * f1;
                float p2 = ex2(sacc[mt][nt][2] * SC) * f0;
                float p3 = ex2(sacc[mt][nt][3] * SC) * f1;
                rsum[mt * 2 + 0] += p0 + p1;
                rsum[mt * 2 + 1] += p2 + p3;
                __half2 h01 = __floats2half2_rn(p0, p1);
                __half2 h23 = __floats2half2_rn(p2, p3);
                Pw[r0 * PW + (col >> 1)] = *(unsigned*)&h01;
                Pw[(r0 + 8) * PW + (col >> 1)] = *(unsigned*)&h23;
            }
        }
#pragma unroll
        for (int si = 0; si < 4; si++) {
            rsum[si] += __shfl_xor_sync(FULLMASK, rsum[si], 1);
            rsum[si] += __shfl_xor_sync(FULLMASK, rsum[si], 2);
        }
        if (t == 0) {
            const int rb = wmS * 32 + g;
            lsumP[wnS * 128 + rb]      = rsum[0];
            lsumP[wnS * 128 + rb + 8]  = rsum[1];
            lsumP[wnS * 128 + rb + 16] = rsum[2];
            lsumP[wnS * 128 + rb + 24] = rsum[3];
        }
        __syncthreads();   // S-MMA done reading Kw; lsumP visible
        if (tid < 128) runl[tid] += lsumP[tid] + lsumP[128 + tid];

        // ---- stage V tile (plain copy, same layout as K) ----
#pragma unroll
        for (int tl = 0; tl < 16; tl++) {
            const int u = tid + tl * 256;
            const int row = u >> 5, j = u & 31;
            uint4 v = *(const uint4*)&Vg[(long)(m0 + row) * CDIM + j * 8];
            *(uint4*)&Kw[row * QW + j * 4] = v;
        }
        __syncthreads();

        // ---- O += P V, K=128 keys in 8 steps of 16; V frags via trans ----
#pragma unroll
        for (int ks = 0; ks < 8; ks++) {
            unsigned a[4][4];
#pragma unroll
            for (int mt = 0; mt < 4; mt++)
                ldsm_x4(a[mt], paB + ((mt * 16 * PW + ks * 8) << 2));
#pragma unroll
            for (int ntp = 0; ntp < 4; ntp++) {
                unsigned vv[4];
                ldsm_x4_t(vv, vbB + ((ks * 16 * QW) << 2) + (ntp << 5));
#pragma unroll
                for (int mt = 0; mt < 4; mt++) {
                    mma_f16(oacc[mt][2 * ntp], a[mt], vv[0], vv[1]);
                    mma_f16(oacc[mt][2 * ntp + 1], a[mt], vv[2], vv[3]);
                }
            }
        }
    }

    // ---- epilogue: normalize by running l and store fp32 AO ----
    float* AOg = g_AO + ((long)b * NTOK + q0) * CDIM;
#pragma unroll
    for (int mt = 0; mt < 4; mt++) {
        const int r0 = wmO * 64 + mt * 16 + g;
        const float inv0 = 1.0f / runl[r0];
        const float inv1 = 1.0f / runl[r0 + 8];
#pragma unroll
        for (int nt = 0; nt < 8; nt++) {
            const int col = wnO * 64 + nt * 8 + 2 * t;
            *(float2*)&AOg[(long)r0 * CDIM + col] =
                make_float2(oacc[mt][nt][0] * inv0, oacc[mt][nt][1] * inv0);
            *(float2*)&AOg[(long)(r0 + 8) * CDIM + col] =
                make_float2(oacc[mt][nt][2] * inv1, oacc[mt][nt][3] * inv1);
        }
    }
}

// ---------------------------------------------------------------------------
// Kernel 3: projection via fp16 mma (R9 version verbatim).
// ---------------------------------------------------------------------------
#define ASW 132
#define PWS 132
#define CS 132
#define PROJ_SMEM ((128 * ASW + 64 * PWS) * 4)

__global__ __launch_bounds__(256) void proj_kernel(const float* __restrict__ Wp,
                                                   const float* __restrict__ bp,
                                                   float* __restrict__ out) {
    extern __shared__ unsigned spw[];
    unsigned* Ah = spw;              // [128 n][132]
    unsigned* Wh = spw + 128 * ASW;  // [64 d][132]
    float* Cs = (float*)spw;         // overlay after GEMM

    const int b   = blockIdx.z;
    const int n0  = blockIdx.x * 128;
    const int co0 = blockIdx.y * 64;
    const int tid = threadIdx.x;
    const int lane = tid & 31, w = tid >> 5;
    const int g = lane >> 2, t = lane & 3;
    const int wm = w >> 2, wn = w & 3;

    const float* A = g_AO + ((long)b * NTOK + n0) * CDIM;

#pragma unroll
    for (int tl = 0; tl < 32; tl++) {
        const int u = tid + tl * 256;
        const int n = u >> 6, f = u & 63;
        float4 v = *(const float4*)&A[(long)n * CDIM + 4 * f];
        uint2 wv;
        wv.x = h2u(__floats2half2_rn(v.x, v.y));
        wv.y = h2u(__floats2half2_rn(v.z, v.w));
        *(uint2*)&Ah[n * ASW + 2 * f] = wv;
    }
#pragma unroll
    for (int tl = 0; tl < 16; tl++) {
        const int u = tid + tl * 256;
        const int d = u >> 6, f = u & 63;
        float4 v = *(const float4*)&Wp[(long)(co0 + d) * CDIM + 4 * f];
        uint2 wv;
        wv.x = h2u(__floats2half2_rn(v.x, v.y));
        wv.y = h2u(__floats2half2_rn(v.z, v.w));
        *(uint2*)&Wh[d * PWS + 2 * f] = wv;
    }
    __syncthreads();

    float acc[4][2][4] = {};
#pragma unroll
    for (int ks = 0; ks < 16; ks++) {
        unsigned a[4][4];
#pragma unroll
        for (int mt = 0; mt < 4; mt++) {
            const int row = wm * 64 + mt * 16 + g;
            a[mt][0] = Ah[row * ASW + ks * 8 + t];
            a[mt][1] = Ah[(row + 8) * ASW + ks * 8 + t];
            a[mt][2] = Ah[row * ASW + ks * 8 + t + 4];
            a[mt][3] = Ah[(row + 8) * ASW + ks * 8 + t + 4];
        }
#pragma unroll
        for (int nt = 0; nt < 2; nt++) {
            const int dn = wn * 16 + nt * 8 + g;
            const unsigned b0 = Wh[dn * PWS + ks * 8 + t];
            const unsigned b1 = Wh[dn * PWS + ks * 8 + t + 4];
#pragma unroll
            for (int mt = 0; mt < 4; mt++)
                mma_f16(acc[mt][nt], a[mt], b0, b1);
        }
    }
    __syncthreads();   // smem free; overlay Cs

#pragma unroll
    for (int mt = 0; mt < 4; mt++) {
        const int n = wm * 64 + mt * 16 + g;
#pragma unroll
        for (int nt = 0; nt < 2; nt++) {
            const int col = wn * 16 + nt * 8 + 2 * t;
            Cs[(col) * CS + n]         = acc[mt][nt][0];
            Cs[(col + 1) * CS + n]     = acc[mt][nt][1];
            Cs[(col) * CS + n + 8]     = acc[mt][nt][2];
            Cs[(col + 1) * CS + n + 8] = acc[mt][nt][3];
        }
    }
    __syncthreads();

#pragma unroll
    for (int tl = 0; tl < 8; tl++) {
        const int f4 = tid + tl * 256;
        const int row = f4 >> 5, cq = f4 & 31;
        const float bias = bp[co0 + row];
        float4 v = *(const float4*)&Cs[row * CS + cq * 4];
        v.x += bias; v.y += bias; v.z += bias; v.w += bias;
        *(float4*)&out[((long)b * CDIM + co0 + row) * NTOK + n0 + cq * 4] = v;
    }
}

// ---------------------------------------------------------------------------
extern "C" void kernel_launch(void* const* d_in, const int* in_sizes, int n_in,
                              void* d_out, int out_size) {
    const float* x    = (const float*)d_in[0];
    const int*   fg   = (const int*)d_in[1];
    const float* Wqkv = (const float*)d_in[2];
    const float* Wp   = (const float*)d_in[3];
    const float* bp   = (const float*)d_in[4];
    float* out = (float*)d_out;

    cudaFuncSetAttribute(qkv_kernel, cudaFuncAttributeMaxDynamicSharedMemorySize, QKV_SMEM);
    cudaFuncSetAttribute(attn_kernel, cudaFuncAttributeMaxDynamicSharedMemorySize, ATTN_SMEM);
    cudaFuncSetAttribute(proj_kernel, cudaFuncAttributeMaxDynamicSharedMemorySize, PROJ_SMEM);

    qkv_kernel<<<dim3(NTOK / 128, TCD / 64, BATCH), 256, QKV_SMEM>>>(x, Wqkv);
    attn_kernel<<<dim3(NTOK / 128, BATCH), 256, ATTN_SMEM>>>(fg);
    proj_kernel<<<dim3(NTOK / 128, CDIM / 64, BATCH), 256, PROJ_SMEM>>>(Wp, bp, out);
}

// round 11
// speedup vs baseline: 3.1099x; 1.0080x over previous
#include <cuda_runtime.h>
#include <cuda_fp16.h>

#define BATCH 4
#define CDIM 256
#define NTOK 4096   // 64*64
#define TCD 768     // 3*C
#define FULLMASK 0xffffffffu

// Scratch (allocation-free rule: __device__ globals)
__device__ __half g_Q[BATCH * NTOK * CDIM];
__device__ __half g_K[BATCH * NTOK * CDIM];
__device__ __half g_V[BATCH * NTOK * CDIM];
__device__ float  g_AO[BATCH * NTOK * CDIM];

__device__ __forceinline__ float ex2(float x) {
    float r;
    asm("ex2.approx.f32 %0, %1;" : "=f"(r) : "f"(x));
    return r;
}
__device__ __forceinline__ void mma_f16(float d[4], const unsigned a[4],
                                        unsigned b0, unsigned b1) {
    asm volatile(
        "mma.sync.aligned.m16n8k16.row.col.f32.f16.f16.f32 "
        "{%0,%1,%2,%3}, {%4,%5,%6,%7}, {%8,%9}, {%0,%1,%2,%3};\n"
        : "+f"(d[0]), "+f"(d[1]), "+f"(d[2]), "+f"(d[3])
        : "r"(a[0]), "r"(a[1]), "r"(a[2]), "r"(a[3]), "r"(b0), "r"(b1));
}
__device__ __forceinline__ unsigned h2u(__half2 h) { return *(unsigned*)&h; }
__device__ __forceinline__ unsigned s2u(const void* p) {
    unsigned u;
    asm("{ .reg .u64 t; cvta.to.shared.u64 t, %1; cvt.u32.u64 %0, t; }"
        : "=r"(u) : "l"(p));
    return u;
}
__device__ __forceinline__ void ldsm_x4(unsigned r[4], unsigned addr) {
    asm volatile("ldmatrix.sync.aligned.m8n8.x4.shared.b16 {%0,%1,%2,%3}, [%4];"
        : "=r"(r[0]), "=r"(r[1]), "=r"(r[2]), "=r"(r[3]) : "r"(addr));
}
__device__ __forceinline__ void ldsm_x4_t(unsigned r[4], unsigned addr) {
    asm volatile("ldmatrix.sync.aligned.m8n8.x4.trans.shared.b16 {%0,%1,%2,%3}, [%4];"
        : "=r"(r[0]), "=r"(r[1]), "=r"(r[2]), "=r"(r[3]) : "r"(addr));
}
__device__ __forceinline__ void cp16(unsigned dst, const void* src) {
    asm volatile("cp.async.cg.shared.global [%0], [%1], 16;" :: "r"(dst), "l"(src));
}
#define CP_COMMIT() asm volatile("cp.async.commit_group;" ::: "memory")
#define CP_WAIT(n)  asm volatile("cp.async.wait_group %0;" :: "n"(n) : "memory")

// ---------------------------------------------------------------------------
// Kernel 1: QKV GEMM via fp16 mma, 64-n tiles for 3 CTAs/SM occupancy.
// grid (64, 12, 4), 256 threads, warp tile 32n x 16d (2m x 4n warp grid).
// ---------------------------------------------------------------------------
#define XSW 68
#define WSW 132
#define QKV_SMEM ((128 * XSW + 64 * WSW) * 4)

__global__ __launch_bounds__(256) void qkv_kernel(const float* __restrict__ x,
                                                  const float* __restrict__ Wqkv) {
    extern __shared__ unsigned sqw[];
    unsigned* Xw = sqw;              // [128 cp][68]; n = 0..63
    unsigned* Wh = sqw + 128 * XSW;  // [64 d][132];  cp = 0..127

    const int b  = blockIdx.z;
    const int n0 = blockIdx.x * 64;
    const int d0 = blockIdx.y * 64;
    const int tid = threadIdx.x;
    const int lane = tid & 31, w = tid >> 5;
    const int g = lane >> 2, t = lane & 3;
    const int wm = w >> 2, wn = w & 3;

    const float* xb = x + (long)b * CDIM * NTOK;

    // stage X: word [cp][n] = {x[2cp][n0+n], x[2cp+1][n0+n]}
#pragma unroll
    for (int tl = 0; tl < 8; tl++) {
        const int u = tid + tl * 256;
        const int cp = u >> 4, j = u & 15;
        const float* rp = &xb[(long)(2 * cp) * NTOK + n0 + 4 * j];
        float4 va = *(const float4*)rp;
        float4 vb = *(const float4*)(rp + NTOK);
        uint4 wv;
        wv.x = h2u(__floats2half2_rn(va.x, vb.x));
        wv.y = h2u(__floats2half2_rn(va.y, vb.y));
        wv.z = h2u(__floats2half2_rn(va.z, vb.z));
        wv.w = h2u(__floats2half2_rn(va.w, vb.w));
        *(uint4*)&Xw[cp * XSW + 4 * j] = wv;
    }
    // stage W: word [d][cp] = {W[d][2cp], W[d][2cp+1]}
#pragma unroll
    for (int tl = 0; tl < 16; tl++) {
        const int u = tid + tl * 256;
        const int d = u >> 6, f = u & 63;
        float4 v = *(const float4*)&Wqkv[(long)(d0 + d) * CDIM + 4 * f];
        uint2 wv;
        wv.x = h2u(__floats2half2_rn(v.x, v.y));
        wv.y = h2u(__floats2half2_rn(v.z, v.w));
        *(uint2*)&Wh[d * WSW + 2 * f] = wv;
    }
    __syncthreads();

    float acc[2][2][4] = {};
#pragma unroll
    for (int ks = 0; ks < 16; ks++) {
        unsigned a[2][4];
#pragma unroll
        for (int mt = 0; mt < 2; mt++) {
            const int nb = wm * 32 + mt * 16 + g;
            a[mt][0] = Xw[(ks * 8 + t) * XSW + nb];
            a[mt][1] = Xw[(ks * 8 + t) * XSW + nb + 8];
            a[mt][2] = Xw[(ks * 8 + t + 4) * XSW + nb];
            a[mt][3] = Xw[(ks * 8 + t + 4) * XSW + nb + 8];
        }
#pragma unroll
        for (int nt = 0; nt < 2; nt++) {
            const int dn = wn * 16 + nt * 8 + g;
            const unsigned b0 = Wh[dn * WSW + ks * 8 + t];
            const unsigned b1 = Wh[dn * WSW + ks * 8 + t + 4];
#pragma unroll
            for (int mt = 0; mt < 2; mt++)
                mma_f16(acc[mt][nt], a[mt], b0, b1);
        }
    }

    const int seg = d0 >> 8;
    __half* base = (seg == 0) ? g_Q : (seg == 1) ? g_K : g_V;
    const int dlocal0 = (d0 & 255);
#pragma unroll
    for (int mt = 0; mt < 2; mt++) {
        const int n = n0 + wm * 32 + mt * 16 + g;
#pragma unroll
        for (int nt = 0; nt < 2; nt++) {
            const int col = dlocal0 + wn * 16 + nt * 8 + 2 * t;
            *(__half2*)&base[((long)b * NTOK + n) * CDIM + col] =
                __floats2half2_rn(acc[mt][nt][0], acc[mt][nt][1]);
            *(__half2*)&base[((long)b * NTOK + n + 8) * CDIM + col] =
                __floats2half2_rn(acc[mt][nt][2], acc[mt][nt][3]);
        }
    }
}

// ---------------------------------------------------------------------------
// Kernel 2: fp16 mma flash attention, LDSM frags + cp.async staged K/V.
// K loaded in two c-halves (half1 overlaps half0's S-MMA); V's cp.async is
// issued before softmax so softmax covers its latency. 128-query CTAs.
// ---------------------------------------------------------------------------
#define QW 132
#define PW 68
#define KVW (128 * QW)
#define ATTN_SMEM ((128 * QW + KVW + 128 * PW) * 4 + (128 + 256 + 128) * 4)

__global__ __launch_bounds__(256, 1) void attn_kernel(const int* __restrict__ fg_mask) {
    extern __shared__ unsigned smw[];
    unsigned* Qw = smw;                      // [128][132] words (fp16 pairs)
    unsigned* Kw = Qw + 128 * QW;            // K tile, then V tile (plain)
    unsigned* Pw = Kw + KVW;                 // [128][68] words (fp16 pairs)
    float* fgf   = (float*)(Pw + 128 * PW);  // [128]
    float* lsumP = fgf + 128;                // [2][128]
    float* runl  = lsumP + 256;              // [128]

    const int b   = blockIdx.y;
    const int q0  = blockIdx.x * 128;
    const int tid = threadIdx.x;
    const int lane = tid & 31, w = tid >> 5;
    const int g = lane >> 2, t = lane & 3;
    const int wmS = w >> 1, wnS = w & 1;     // S: 4x2 grid, warp tile 32x64
    const int wmO = w >> 2, wnO = w & 3;     // O: 2x4 grid, warp tile 64x64

    const __half* Qg = g_Q + ((long)b * NTOK + q0) * CDIM;
    const __half* Kg = g_K + (long)b * NTOK * CDIM;
    const __half* Vg = g_V + (long)b * NTOK * CDIM;

    // stage resident Q tile: 128 rows x 256 halves
#pragma unroll
    for (int tl = 0; tl < 16; tl++) {
        const int u = tid + tl * 256;
        const int row = u >> 5, j = u & 31;
        uint4 v = *(const uint4*)&Qg[(long)row * CDIM + j * 8];
        *(uint4*)&Qw[row * QW + j * 4] = v;
    }
    if (tid < 128) runl[tid] = 0.0f;

    const unsigned kwB = s2u(Kw);
    // ldmatrix base addresses (per-lane, loop-invariant)
    const unsigned qaB = s2u(Qw) +
        (((wmS * 32 + (lane & 15)) * QW + 4 * (lane >> 4)) << 2);
    const unsigned kbB = kwB +
        (((wnS * 64 + ((lane >> 4) << 3) + (lane & 7)) * QW + ((lane >> 3) & 1) * 4) << 2);
    const unsigned paB = s2u(Pw) +
        (((wmO * 64 + (lane & 15)) * PW + 4 * (lane >> 4)) << 2);
    const unsigned vbB = kwB + (((lane & 15) * QW) << 2) +
        ((wnO * 64 + (lane >> 4) * 8) << 1);

    float oacc[4][8][4];
#pragma unroll
    for (int i = 0; i < 4; i++)
#pragma unroll
        for (int j = 0; j < 8; j++)
#pragma unroll
            for (int k = 0; k < 4; k++) oacc[i][j][k] = 0.0f;

    const float SC = 0.0625f * 1.4426950408889634f;

    for (int m0 = 0; m0 < NTOK; m0 += 128) {
        __syncthreads();   // prev PV done reading V buffer; Q visible on tile 0

        // K half 0 (c 0..127): 128 rows x 16 chunks of 16B
#pragma unroll
        for (int tl = 0; tl < 8; tl++) {
            const int u = tid + tl * 256;
            const int row = u >> 4, j = u & 15;
            cp16(kwB + ((row * QW + j * 4) << 2),
                 &Kg[(long)(m0 + row) * CDIM + j * 8]);
        }
        CP_COMMIT();
        // K half 1 (c 128..255)
#pragma unroll
        for (int tl = 0; tl < 8; tl++) {
            const int u = tid + tl * 256;
            const int row = u >> 4, j = u & 15;
            cp16(kwB + ((row * QW + 64 + j * 4) << 2),
                 &Kg[(long)(m0 + row) * CDIM + 128 + j * 8]);
        }
        CP_COMMIT();

        if (tid < 128) fgf[tid] = fg_mask[b * NTOK + m0 + tid] ? 1.0f : 0.0f;

        float sacc[2][8][4] = {};

        CP_WAIT(1);        // K half 0 landed
        __syncthreads();
        // ---- S (c 0..127): ks 0..7 ----
#pragma unroll
        for (int ks = 0; ks < 8; ks++) {
            unsigned a[2][4];
            ldsm_x4(a[0], qaB + ((ks * 8) << 2));
            ldsm_x4(a[1], qaB + ((16 * QW + ks * 8) << 2));
#pragma unroll
            for (int ntp = 0; ntp < 4; ntp++) {
                unsigned bb[4];
                ldsm_x4(bb, kbB + ((ntp * 16 * QW + ks * 8) << 2));
                mma_f16(sacc[0][2 * ntp], a[0], bb[0], bb[1]);
                mma_f16(sacc[1][2 * ntp], a[1], bb[0], bb[1]);
                mma_f16(sacc[0][2 * ntp + 1], a[0], bb[2], bb[3]);
                mma_f16(sacc[1][2 * ntp + 1], a[1], bb[2], bb[3]);
            }
        }
        CP_WAIT(0);        // K half 1 landed
        __syncthreads();
        // ---- S (c 128..255): ks 8..15 ----
#pragma unroll
        for (int ks = 8; ks < 16; ks++) {
            unsigned a[2][4];
            ldsm_x4(a[0], qaB + ((ks * 8) << 2));
            ldsm_x4(a[1], qaB + ((16 * QW + ks * 8) << 2));
#pragma unroll
            for (int ntp = 0; ntp < 4; ntp++) {
                unsigned bb[4];
                ldsm_x4(bb, kbB + ((ntp * 16 * QW + ks * 8) << 2));
                mma_f16(sacc[0][2 * ntp], a[0], bb[0], bb[1]);
                mma_f16(sacc[1][2 * ntp], a[1], bb[0], bb[1]);
                mma_f16(sacc[0][2 * ntp + 1], a[0], bb[2], bb[3]);
                mma_f16(sacc[1][2 * ntp + 1], a[1], bb[2], bb[3]);
            }
        }
        __syncthreads();   // all warps done reading K from Kw

        // issue V staging NOW; softmax below hides its latency
#pragma unroll
        for (int tl = 0; tl < 16; tl++) {
            const int u = tid + tl * 256;
            const int row = u >> 5, j = u & 31;
            cp16(kwB + ((row * QW + j * 4) << 2),
                 &Vg[(long)(m0 + row) * CDIM + j * 8]);
        }
        CP_COMMIT();

        // ---- softmax: mask * exp2(S*SC), write fp16 P, row sums ----
        float rsum[4] = {0.0f, 0.0f, 0.0f, 0.0f};
#pragma unroll
        for (int mt = 0; mt < 2; mt++) {
            const int r0 = wmS * 32 + mt * 16 + g;
#pragma unroll
            for (int nt = 0; nt < 8; nt++) {
                const int col = wnS * 64 + nt * 8 + 2 * t;
                const float f0 = fgf[col], f1 = fgf[col + 1];
                float p0 = ex2(sacc[mt][nt][0] * SC) * f0;
                float p1 = ex2(sacc[mt][nt][1] * SC) * f1;
                float p2 = ex2(sacc[mt][nt][2] * SC) * f0;
                float p3 = ex2(sacc[mt][nt][3] * SC) * f1;
                rsum[mt * 2 + 0] += p0 + p1;
                rsum[mt * 2 + 1] += p2 + p3;
                __half2 h01 = __floats2half2_rn(p0, p1);
                __half2 h23 = __floats2half2_rn(p2, p3);
                Pw[r0 * PW + (col >> 1)] = *(unsigned*)&h01;
                Pw[(r0 + 8) * PW + (col >> 1)] = *(unsigned*)&h23;
            }
        }
#pragma unroll
        for (int si = 0; si < 4; si++) {
            rsum[si] += __shfl_xor_sync(FULLMASK, rsum[si], 1);
            rsum[si] += __shfl_xor_sync(FULLMASK, rsum[si], 2);
        }
        if (t == 0) {
            const int rb = wmS * 32 + g;
            lsumP[wnS * 128 + rb]      = rsum[0];
            lsumP[wnS * 128 + rb + 8]  = rsum[1];
            lsumP[wnS * 128 + rb + 16] = rsum[2];
            lsumP[wnS * 128 + rb + 24] = rsum[3];
        }
        CP_WAIT(0);        // V landed
        __syncthreads();   // V + Pw + lsumP visible
        if (tid < 128) runl[tid] += lsumP[tid] + lsumP[128 + tid];

        // ---- O += P V, K=128 keys in 8 steps of 16; V frags via trans ----
#pragma unroll
        for (int ks = 0; ks < 8; ks++) {
            unsigned a[4][4];
#pragma unroll
            for (int mt = 0; mt < 4; mt++)
                ldsm_x4(a[mt], paB + ((mt * 16 * PW + ks * 8) << 2));
#pragma unroll
            for (int ntp = 0; ntp < 4; ntp++) {
                unsigned vv[4];
                ldsm_x4_t(vv, vbB + ((ks * 16 * QW) << 2) + (ntp << 5));
#pragma unroll
                for (int mt = 0; mt < 4; mt++) {
                    mma_f16(oacc[mt][2 * ntp], a[mt], vv[0], vv[1]);
                    mma_f16(oacc[mt][2 * ntp + 1], a[mt], vv[2], vv[3]);
                }
            }
        }
    }

    // ---- epilogue: normalize by running l and store fp32 AO ----
    float* AOg = g_AO + ((long)b * NTOK + q0) * CDIM;
#pragma unroll
    for (int mt = 0; mt < 4; mt++) {
        const int r0 = wmO * 64 + mt * 16 + g;
        const float inv0 = 1.0f / runl[r0];
        const float inv1 = 1.0f / runl[r0 + 8];
#pragma unroll
        for (int nt = 0; nt < 8; nt++) {
            const int col = wnO * 64 + nt * 8 + 2 * t;
            *(float2*)&AOg[(long)r0 * CDIM + col] =
                make_float2(oacc[mt][nt][0] * inv0, oacc[mt][nt][1] * inv0);
            *(float2*)&AOg[(long)(r0 + 8) * CDIM + col] =
                make_float2(oacc[mt][nt][2] * inv1, oacc[mt][nt][3] * inv1);
        }
    }
}

// ---------------------------------------------------------------------------
// Kernel 3: projection via fp16 mma, 64-n tiles for 3 CTAs/SM occupancy.
// grid (64, 4, 4), 256 threads, warp tile 32n x 16d.
// ---------------------------------------------------------------------------
#define ASW 132
#define PWS 132
#define CS 68
#define PROJ_SMEM ((64 * ASW + 64 * PWS) * 4)

__global__ __launch_bounds__(256) void proj_kernel(const float* __restrict__ Wp,
                                                   const float* __restrict__ bp,
                                                   float* __restrict__ out) {
    extern __shared__ unsigned spw[];
    unsigned* Ah = spw;             // [64 n][132]
    unsigned* Wh = spw + 64 * ASW;  // [64 d][132]
    float* Cs = (float*)spw;        // overlay after GEMM: [64 d][68]

    const int b   = blockIdx.z;
    const int n0  = blockIdx.x * 64;
    const int co0 = blockIdx.y * 64;
    const int tid = threadIdx.x;
    const int lane = tid & 31, w = tid >> 5;
    const int g = lane >> 2, t = lane & 3;
    const int wm = w >> 2, wn = w & 3;

    const float* A = g_AO + ((long)b * NTOK + n0) * CDIM;

#pragma unroll
    for (int tl = 0; tl < 16; tl++) {
        const int u = tid + tl * 256;
        const int n = u >> 6, f = u & 63;
        float4 v = *(const float4*)&A[(long)n * CDIM + 4 * f];
        uint2 wv;
        wv.x = h2u(__floats2half2_rn(v.x, v.y));
        wv.y = h2u(__floats2half2_rn(v.z, v.w));
        *(uint2*)&Ah[n * ASW + 2 * f] = wv;
    }
#pragma unroll
    for (int tl = 0; tl < 16; tl++) {
        const int u = tid + tl * 256;
        const int d = u >> 6, f = u & 63;
        float4 v = *(const float4*)&Wp[(long)(co0 + d) * CDIM + 4 * f];
        uint2 wv;
        wv.x = h2u(__floats2half2_rn(v.x, v.y));
        wv.y = h2u(__floats2half2_rn(v.z, v.w));
        *(uint2*)&Wh[d * PWS + 2 * f] = wv;
    }
    __syncthreads();

    float acc[2][2][4] = {};
#pragma unroll
    for (int ks = 0; ks < 16; ks++) {
        unsigned a[2][4];
#pragma unroll
        for (int mt = 0; mt < 2; mt++) {
            const int row = wm * 32 + mt * 16 + g;
            a[mt][0] = Ah[row * ASW + ks * 8 + t];
            a[mt][1] = Ah[(row + 8) * ASW + ks * 8 + t];
            a[mt][2] = Ah[row * ASW + ks * 8 + t + 4];
            a[mt][3] = Ah[(row + 8) * ASW + ks * 8 + t + 4];
        }
#pragma unroll
        for (int nt = 0; nt < 2; nt++) {
            const int dn = wn * 16 + nt * 8 + g;
            const unsigned b0 = Wh[dn * PWS + ks * 8 + t];
            const unsigned b1 = Wh[dn * PWS + ks * 8 + t + 4];
#pragma unroll
            for (int mt = 0; mt < 2; mt++)
                mma_f16(acc[mt][nt], a[mt], b0, b1);
        }
    }
    __syncthreads();   // smem free; overlay Cs

    // stage transposed into Cs[d][n]
#pragma unroll
    for (int mt = 0; mt < 2; mt++) {
        const int n = wm * 32 + mt * 16 + g;
#pragma unroll
        for (int nt = 0; nt < 2; nt++) {
            const int col = wn * 16 + nt * 8 + 2 * t;
            Cs[(col) * CS + n]         = acc[mt][nt][0];
            Cs[(col + 1) * CS + n]     = acc[mt][nt][1];
            Cs[(col) * CS + n + 8]     = acc[mt][nt][2];
            Cs[(col + 1) * CS + n + 8] = acc[mt][nt][3];
        }
    }
    __syncthreads();

    // coalesced store out[b][co0+d][n0..n0+64) with bias
#pragma unroll
    for (int tl = 0; tl < 4; tl++) {
        const int f4 = tid + tl * 256;
        const int row = f4 >> 4, cq = f4 & 15;
        const float bias = bp[co0 + row];
        float4 v = *(const float4*)&Cs[row * CS + cq * 4];
        v.x += bias; v.y += bias; v.z += bias; v.w += bias;
        *(float4*)&out[((long)b * CDIM + co0 + row) * NTOK + n0 + cq * 4] = v;
    }
}

// ---------------------------------------------------------------------------
extern "C" void kernel_launch(void* const* d_in, const int* in_sizes, int n_in,
                              void* d_out, int out_size) {
    const float* x    = (const float*)d_in[0];
    const int*   fg   = (const int*)d_in[1];
    const float* Wqkv = (const float*)d_in[2];
    const float* Wp   = (const float*)d_in[3];
    const float* bp   = (const float*)d_in[4];
    float* out = (float*)d_out;

    cudaFuncSetAttribute(qkv_kernel, cudaFuncAttributeMaxDynamicSharedMemorySize, QKV_SMEM);
    cudaFuncSetAttribute(attn_kernel, cudaFuncAttributeMaxDynamicSharedMemorySize, ATTN_SMEM);
    cudaFuncSetAttribute(proj_kernel, cudaFuncAttributeMaxDynamicSharedMemorySize, PROJ_SMEM);

    qkv_kernel<<<dim3(NTOK / 64, TCD / 64, BATCH), 256, QKV_SMEM>>>(x, Wqkv);
    attn_kernel<<<dim3(NTOK / 128, BATCH), 256, ATTN_SMEM>>>(fg);
    proj_kernel<<<dim3(NTOK / 64, CDIM / 64, BATCH), 256, PROJ_SMEM>>>(Wp, bp, out);
}

// round 12
// speedup vs baseline: 3.3727x; 1.0845x over previous
#include <cuda_runtime.h>
#include <cuda_fp16.h>

#define BATCH 4
#define CDIM 256
#define NTOK 4096   // 64*64
#define TCD 768     // 3*C
#define FULLMASK 0xffffffffu

// Scratch (allocation-free rule: __device__ globals)
__device__ __half g_Q[BATCH * NTOK * CDIM];
__device__ __half g_K[BATCH * NTOK * CDIM];
__device__ __half g_V[BATCH * NTOK * CDIM];
__device__ __half g_AOh[BATCH * NTOK * CDIM];
__device__ __half g_Wh[TCD * CDIM];
__device__ __half g_Wph[CDIM * CDIM];

__device__ __forceinline__ float ex2(float x) {
    float r;
    asm("ex2.approx.f32 %0, %1;" : "=f"(r) : "f"(x));
    return r;
}
__device__ __forceinline__ void mma_f16(float d[4], const unsigned a[4],
                                        unsigned b0, unsigned b1) {
    asm volatile(
        "mma.sync.aligned.m16n8k16.row.col.f32.f16.f16.f32 "
        "{%0,%1,%2,%3}, {%4,%5,%6,%7}, {%8,%9}, {%0,%1,%2,%3};\n"
        : "+f"(d[0]), "+f"(d[1]), "+f"(d[2]), "+f"(d[3])
        : "r"(a[0]), "r"(a[1]), "r"(a[2]), "r"(a[3]), "r"(b0), "r"(b1));
}
__device__ __forceinline__ unsigned h2u(__half2 h) { return *(unsigned*)&h; }
__device__ __forceinline__ unsigned s2u(const void* p) {
    unsigned u;
    asm("{ .reg .u64 t; cvta.to.shared.u64 t, %1; cvt.u32.u64 %0, t; }"
        : "=r"(u) : "l"(p));
    return u;
}
__device__ __forceinline__ void ldsm_x4(unsigned r[4], unsigned addr) {
    asm volatile("ldmatrix.sync.aligned.m8n8.x4.shared.b16 {%0,%1,%2,%3}, [%4];"
        : "=r"(r[0]), "=r"(r[1]), "=r"(r[2]), "=r"(r[3]) : "r"(addr));
}
__device__ __forceinline__ void ldsm_x4_t(unsigned r[4], unsigned addr) {
    asm volatile("ldmatrix.sync.aligned.m8n8.x4.trans.shared.b16 {%0,%1,%2,%3}, [%4];"
        : "=r"(r[0]), "=r"(r[1]), "=r"(r[2]), "=r"(r[3]) : "r"(addr));
}
__device__ __forceinline__ void cp16(unsigned dst, const void* src) {
    asm volatile("cp.async.cg.shared.global [%0], [%1], 16;" :: "r"(dst), "l"(src));
}
#define CP_COMMIT() asm volatile("cp.async.commit_group;" ::: "memory")
#define CP_WAIT(n)  asm volatile("cp.async.wait_group %0;" :: "n"(n) : "memory")

// ---------------------------------------------------------------------------
// Kernel 0: one-time fp32 -> fp16 conversion of both weight matrices.
// 65536 float4 over grid 256 x 256.
// ---------------------------------------------------------------------------
__global__ __launch_bounds__(256) void wconv_kernel(const float* __restrict__ Wqkv,
                                                    const float* __restrict__ Wp) {
    const int idx = blockIdx.x * 256 + threadIdx.x;   // 0..65535
    const float4* src;
    uint2* dst;
    int off;
    if (idx < (TCD * CDIM / 4)) { src = (const float4*)Wqkv; dst = (uint2*)g_Wh;  off = idx; }
    else                        { src = (const float4*)Wp;   dst = (uint2*)g_Wph; off = idx - TCD * CDIM / 4; }
    float4 v = src[off];
    uint2 wv;
    wv.x = h2u(__floats2half2_rn(v.x, v.y));
    wv.y = h2u(__floats2half2_rn(v.z, v.w));
    dst[off] = wv;
}

// ---------------------------------------------------------------------------
// Kernel 1: QKV GEMM, fp16 mma. C[d][n] = sum_c W[d][c] * x[c][n].
// A = W (ldsm on [d][c]); B = x staged untransposed [c][n] fp16, frags via
// ldmatrix.trans (PV/V pattern). Epilogue transposes to [n][d] via smem.
// grid (64 n-tiles, 6 d-tiles(128), 4 b), 256 thr, warp tile 64d x 16n.
// ---------------------------------------------------------------------------
#define XQS 36    // x tile row stride, words ([256 c][64 n] halves)
#define WQS 132   // W tile row stride, words
#define QKV_SMEM ((256 * XQS + 128 * WQS) * 4)

__global__ __launch_bounds__(256) void qkv_kernel(const float* __restrict__ x) {
    extern __shared__ unsigned sqw[];
    unsigned* Xw = sqw;               // [256 c][36]
    unsigned* Wh = sqw + 256 * XQS;   // [128 d][132]

    const int b  = blockIdx.z;
    const int n0 = blockIdx.x * 64;
    const int d0 = blockIdx.y * 128;
    const int tid = threadIdx.x;
    const int lane = tid & 31, w = tid >> 5;
    const int g = lane >> 2, t = lane & 3;
    const int wmd = w >> 2, wnn = w & 3;   // 2d x 4n warp grid

    const float* xb = x + (long)b * CDIM * NTOK;
    const unsigned whB = s2u(Wh);

    // W tile via cp.async (fp16 source)
#pragma unroll
    for (int tl = 0; tl < 16; tl++) {
        const int u = tid + tl * 256;
        const int d = u >> 5, ch = u & 31;
        cp16(whB + ((d * WQS + ch * 4) << 2), &g_Wh[(long)(d0 + d) * CDIM + ch * 8]);
    }
    CP_COMMIT();
    // x tile: convert fp32 -> fp16, keep [c][n] layout (coalesced reads)
#pragma unroll
    for (int tl = 0; tl < 16; tl++) {
        const int u = tid + tl * 256;
        const int c = u >> 4, j = u & 15;
        float4 v = *(const float4*)&xb[(long)c * NTOK + n0 + 4 * j];
        uint2 wv;
        wv.x = h2u(__floats2half2_rn(v.x, v.y));
        wv.y = h2u(__floats2half2_rn(v.z, v.w));
        *(uint2*)&Xw[c * XQS + 2 * j] = wv;
    }
    CP_WAIT(0);
    __syncthreads();

    const unsigned aB = whB + (((wmd * 64 + (lane & 15)) * WQS + 4 * (lane >> 4)) << 2);
    const unsigned xB = s2u(Xw) + (((lane & 15) * XQS) << 2) +
                        ((wnn * 16 + (lane >> 4) * 8) << 1);

    float acc[4][2][4] = {};
#pragma unroll
    for (int ks = 0; ks < 16; ks++) {
        unsigned a[4][4];
#pragma unroll
        for (int mt = 0; mt < 4; mt++)
            ldsm_x4(a[mt], aB + ((mt * 16 * WQS + ks * 8) << 2));
        unsigned bb[4];
        ldsm_x4_t(bb, xB + ((ks * 16 * XQS) << 2));
#pragma unroll
        for (int mt = 0; mt < 4; mt++) {
            mma_f16(acc[mt][0], a[mt], bb[0], bb[1]);
            mma_f16(acc[mt][1], a[mt], bb[2], bb[3]);
        }
    }
    __syncthreads();   // done reading Xw/Wh

    // transpose C[d][n] -> Csh[n][d] (halves), then coalesced fp16 store
    __half* Csh = (__half*)sqw;   // [64 n][136 halves]
#pragma unroll
    for (int mt = 0; mt < 4; mt++) {
        const int r0 = wmd * 64 + mt * 16 + g;   // d
#pragma unroll
        for (int nt = 0; nt < 2; nt++) {
            const int col = wnn * 16 + nt * 8 + 2 * t;   // n
            Csh[col * 136 + r0]           = __float2half(acc[mt][nt][0]);
            Csh[(col + 1) * 136 + r0]     = __float2half(acc[mt][nt][1]);
            Csh[col * 136 + r0 + 8]       = __float2half(acc[mt][nt][2]);
            Csh[(col + 1) * 136 + r0 + 8] = __float2half(acc[mt][nt][3]);
        }
    }
    __syncthreads();

    const int seg = d0 >> 8;                 // 128-tiles never straddle q/k/v
    __half* base = (seg == 0) ? g_Q : (seg == 1) ? g_K : g_V;
    const int dl0 = d0 & 255;
#pragma unroll
    for (int tl = 0; tl < 4; tl++) {
        const int u = tid + tl * 256;
        const int n = u >> 4, d8 = u & 15;
        uint4 v = *(const uint4*)&Csh[n * 136 + d8 * 8];
        *(uint4*)&base[((long)b * NTOK + n0 + n) * CDIM + dl0 + d8 * 8] = v;
    }
}

// ---------------------------------------------------------------------------
// Kernel 2: fp16 mma flash attention (R11 verbatim; epilogue now emits fp16).
// ---------------------------------------------------------------------------
#define QW 132
#define PW 68
#define KVW (128 * QW)
#define ATTN_SMEM ((128 * QW + KVW + 128 * PW) * 4 + (128 + 256 + 128) * 4)

__global__ __launch_bounds__(256, 1) void attn_kernel(const int* __restrict__ fg_mask) {
    extern __shared__ unsigned smw[];
    unsigned* Qw = smw;                      // [128][132] words (fp16 pairs)
    unsigned* Kw = Qw + 128 * QW;            // K tile, then V tile (plain)
    unsigned* Pw = Kw + KVW;                 // [128][68] words (fp16 pairs)
    float* fgf   = (float*)(Pw + 128 * PW);  // [128]
    float* lsumP = fgf + 128;                // [2][128]
    float* runl  = lsumP + 256;              // [128]

    const int b   = blockIdx.y;
    const int q0  = blockIdx.x * 128;
    const int tid = threadIdx.x;
    const int lane = tid & 31, w = tid >> 5;
    const int g = lane >> 2, t = lane & 3;
    const int wmS = w >> 1, wnS = w & 1;     // S: 4x2 grid, warp tile 32x64
    const int wmO = w >> 2, wnO = w & 3;     // O: 2x4 grid, warp tile 64x64

    const __half* Qg = g_Q + ((long)b * NTOK + q0) * CDIM;
    const __half* Kg = g_K + (long)b * NTOK * CDIM;
    const __half* Vg = g_V + (long)b * NTOK * CDIM;

#pragma unroll
    for (int tl = 0; tl < 16; tl++) {
        const int u = tid + tl * 256;
        const int row = u >> 5, j = u & 31;
        uint4 v = *(const uint4*)&Qg[(long)row * CDIM + j * 8];
        *(uint4*)&Qw[row * QW + j * 4] = v;
    }
    if (tid < 128) runl[tid] = 0.0f;

    const unsigned kwB = s2u(Kw);
    const unsigned qaB = s2u(Qw) +
        (((wmS * 32 + (lane & 15)) * QW + 4 * (lane >> 4)) << 2);
    const unsigned kbB = kwB +
        (((wnS * 64 + ((lane >> 4) << 3) + (lane & 7)) * QW + ((lane >> 3) & 1) * 4) << 2);
    const unsigned paB = s2u(Pw) +
        (((wmO * 64 + (lane & 15)) * PW + 4 * (lane >> 4)) << 2);
    const unsigned vbB = kwB + (((lane & 15) * QW) << 2) +
        ((wnO * 64 + (lane >> 4) * 8) << 1);

    float oacc[4][8][4];
#pragma unroll
    for (int i = 0; i < 4; i++)
#pragma unroll
        for (int j = 0; j < 8; j++)
#pragma unroll
            for (int k = 0; k < 4; k++) oacc[i][j][k] = 0.0f;

    const float SC = 0.0625f * 1.4426950408889634f;

    for (int m0 = 0; m0 < NTOK; m0 += 128) {
        __syncthreads();

        // K half 0 (c 0..127)
#pragma unroll
        for (int tl = 0; tl < 8; tl++) {
            const int u = tid + tl * 256;
            const int row = u >> 4, j = u & 15;
            cp16(kwB + ((row * QW + j * 4) << 2),
                 &Kg[(long)(m0 + row) * CDIM + j * 8]);
        }
        CP_COMMIT();
        // K half 1 (c 128..255)
#pragma unroll
        for (int tl = 0; tl < 8; tl++) {
            const int u = tid + tl * 256;
            const int row = u >> 4, j = u & 15;
            cp16(kwB + ((row * QW + 64 + j * 4) << 2),
                 &Kg[(long)(m0 + row) * CDIM + 128 + j * 8]);
        }
        CP_COMMIT();

        if (tid < 128) fgf[tid] = fg_mask[b * NTOK + m0 + tid] ? 1.0f : 0.0f;

        float sacc[2][8][4] = {};

        CP_WAIT(1);
        __syncthreads();
#pragma unroll
        for (int ks = 0; ks < 8; ks++) {
            unsigned a[2][4];
            ldsm_x4(a[0], qaB + ((ks * 8) << 2));
            ldsm_x4(a[1], qaB + ((16 * QW + ks * 8) << 2));
#pragma unroll
            for (int ntp = 0; ntp < 4; ntp++) {
                unsigned bb[4];
                ldsm_x4(bb, kbB + ((ntp * 16 * QW + ks * 8) << 2));
                mma_f16(sacc[0][2 * ntp], a[0], bb[0], bb[1]);
                mma_f16(sacc[1][2 * ntp], a[1], bb[0], bb[1]);
                mma_f16(sacc[0][2 * ntp + 1], a[0], bb[2], bb[3]);
                mma_f16(sacc[1][2 * ntp + 1], a[1], bb[2], bb[3]);
            }
        }
        CP_WAIT(0);
        __syncthreads();
#pragma unroll
        for (int ks = 8; ks < 16; ks++) {
            unsigned a[2][4];
            ldsm_x4(a[0], qaB + ((ks * 8) << 2));
            ldsm_x4(a[1], qaB + ((16 * QW + ks * 8) << 2));
#pragma unroll
            for (int ntp = 0; ntp < 4; ntp++) {
                unsigned bb[4];
                ldsm_x4(bb, kbB + ((ntp * 16 * QW + ks * 8) << 2));
                mma_f16(sacc[0][2 * ntp], a[0], bb[0], bb[1]);
                mma_f16(sacc[1][2 * ntp], a[1], bb[0], bb[1]);
                mma_f16(sacc[0][2 * ntp + 1], a[0], bb[2], bb[3]);
                mma_f16(sacc[1][2 * ntp + 1], a[1], bb[2], bb[3]);
            }
        }
        __syncthreads();

        // V staging issued now; softmax hides its latency
#pragma unroll
        for (int tl = 0; tl < 16; tl++) {
            const int u = tid + tl * 256;
            const int row = u >> 5, j = u & 31;
            cp16(kwB + ((row * QW + j * 4) << 2),
                 &Vg[(long)(m0 + row) * CDIM + j * 8]);
        }
        CP_COMMIT();

        float rsum[4] = {0.0f, 0.0f, 0.0f, 0.0f};
#pragma unroll
        for (int mt = 0; mt < 2; mt++) {
            const int r0 = wmS * 32 + mt * 16 + g;
#pragma unroll
            for (int nt = 0; nt < 8; nt++) {
                const int col = wnS * 64 + nt * 8 + 2 * t;
                const float f0 = fgf[col], f1 = fgf[col + 1];
                float p0 = ex2(sacc[mt][nt][0] * SC) * f0;
                float p1 = ex2(sacc[mt][nt][1] * SC) * f1;
                float p2 = ex2(sacc[mt][nt][2] * SC) * f0;
                float p3 = ex2(sacc[mt][nt][3] * SC) * f1;
                rsum[mt * 2 + 0] += p0 + p1;
                rsum[mt * 2 + 1] += p2 + p3;
                __half2 h01 = __floats2half2_rn(p0, p1);
                __half2 h23 = __floats2half2_rn(p2, p3);
                Pw[r0 * PW + (col >> 1)] = *(unsigned*)&h01;
                Pw[(r0 + 8) * PW + (col >> 1)] = *(unsigned*)&h23;
            }
        }
#pragma unroll
        for (int si = 0; si < 4; si++) {
            rsum[si] += __shfl_xor_sync(FULLMASK, rsum[si], 1);
            rsum[si] += __shfl_xor_sync(FULLMASK, rsum[si], 2);
        }
        if (t == 0) {
            const int rb = wmS * 32 + g;
            lsumP[wnS * 128 + rb]      = rsum[0];
            lsumP[wnS * 128 + rb + 8]  = rsum[1];
            lsumP[wnS * 128 + rb + 16] = rsum[2];
            lsumP[wnS * 128 + rb + 24] = rsum[3];
        }
        CP_WAIT(0);
        __syncthreads();
        if (tid < 128) runl[tid] += lsumP[tid] + lsumP[128 + tid];

#pragma unroll
        for (int ks = 0; ks < 8; ks++) {
            unsigned a[4][4];
#pragma unroll
            for (int mt = 0; mt < 4; mt++)
                ldsm_x4(a[mt], paB + ((mt * 16 * PW + ks * 8) << 2));
#pragma unroll
            for (int ntp = 0; ntp < 4; ntp++) {
                unsigned vv[4];
                ldsm_x4_t(vv, vbB + ((ks * 16 * QW) << 2) + (ntp << 5));
#pragma unroll
                for (int mt = 0; mt < 4; mt++) {
                    mma_f16(oacc[mt][2 * ntp], a[mt], vv[0], vv[1]);
                    mma_f16(oacc[mt][2 * ntp + 1], a[mt], vv[2], vv[3]);
                }
            }
        }
    }

    // ---- epilogue: normalize and store fp16 AO ----
    __half* AOg = g_AOh + ((long)b * NTOK + q0) * CDIM;
#pragma unroll
    for (int mt = 0; mt < 4; mt++) {
        const int r0 = wmO * 64 + mt * 16 + g;
        const float inv0 = 1.0f / runl[r0];
        const float inv1 = 1.0f / runl[r0 + 8];
#pragma unroll
        for (int nt = 0; nt < 8; nt++) {
            const int col = wnO * 64 + nt * 8 + 2 * t;
            *(__half2*)&AOg[(long)r0 * CDIM + col] =
                __floats2half2_rn(oacc[mt][nt][0] * inv0, oacc[mt][nt][1] * inv0);
            *(__half2*)&AOg[(long)(r0 + 8) * CDIM + col] =
                __floats2half2_rn(oacc[mt][nt][2] * inv1, oacc[mt][nt][3] * inv1);
        }
    }
}

// ---------------------------------------------------------------------------
// Kernel 3: projection, fp16 mma, all-native-fp16 inputs via cp.async.
// C[n][d] = AOh[n][:]·Wp[d][:]; attention-S-phase clone (128x128 tile).
// Epilogue: bias + transpose to out[b][d][n] via fp32 smem overlay.
// grid (32 n-tiles, 2 d-tiles(128), 4 b).
// ---------------------------------------------------------------------------
#define PJS 132
#define PROJ_SMEM ((128 * PJS + 128 * PJS) * 4)

__global__ __launch_bounds__(256) void proj_kernel(const float* __restrict__ bp,
                                                   float* __restrict__ out) {
    extern __shared__ unsigned spw[];
    unsigned* Ah = spw;               // [128 n][132]
    unsigned* Wh = spw + 128 * PJS;   // [128 d][132]
    float* Cs = (float*)spw;          // overlay after GEMM: [128 d][132] fp32

    const int b   = blockIdx.z;
    const int n0  = blockIdx.x * 128;
    const int co0 = blockIdx.y * 128;
    const int tid = threadIdx.x;
    const int lane = tid & 31, w = tid >> 5;
    const int g = lane >> 2, t = lane & 3;
    const int wm = w >> 1, wn = w & 1;   // 4n x 2d grid, warp tile 32n x 64d

    const unsigned ahB = s2u(Ah), whB = s2u(Wh);
#pragma unroll
    for (int tl = 0; tl < 16; tl++) {
        const int u = tid + tl * 256;
        const int n = u >> 5, ch = u & 31;
        cp16(ahB + ((n * PJS + ch * 4) << 2),
             &g_AOh[((long)b * NTOK + n0 + n) * CDIM + ch * 8]);
    }
#pragma unroll
    for (int tl = 0; tl < 16; tl++) {
        const int u = tid + tl * 256;
        const int d = u >> 5, ch = u & 31;
        cp16(whB + ((d * PJS + ch * 4) << 2),
             &g_Wph[(long)(co0 + d) * CDIM + ch * 8]);
    }
    CP_COMMIT();
    CP_WAIT(0);
    __syncthreads();

    const unsigned aB = ahB + (((wm * 32 + (lane & 15)) * PJS + 4 * (lane >> 4)) << 2);
    const unsigned bB = whB +
        (((wn * 64 + ((lane >> 4) << 3) + (lane & 7)) * PJS + ((lane >> 3) & 1) * 4) << 2);

    float sacc[2][8][4] = {};
#pragma unroll
    for (int ks = 0; ks < 16; ks++) {
        unsigned a[2][4];
        ldsm_x4(a[0], aB + ((ks * 8) << 2));
        ldsm_x4(a[1], aB + ((16 * PJS + ks * 8) << 2));
#pragma unroll
        for (int ntp = 0; ntp < 4; ntp++) {
            unsigned bb[4];
            ldsm_x4(bb, bB + ((ntp * 16 * PJS + ks * 8) << 2));
            mma_f16(sacc[0][2 * ntp], a[0], bb[0], bb[1]);
            mma_f16(sacc[1][2 * ntp], a[1], bb[0], bb[1]);
            mma_f16(sacc[0][2 * ntp + 1], a[0], bb[2], bb[3]);
            mma_f16(sacc[1][2 * ntp + 1], a[1], bb[2], bb[3]);
        }
    }
    __syncthreads();   // done reading Ah/Wh; overlay Cs

    // stage transposed into Cs[d][n]
#pragma unroll
    for (int mt = 0; mt < 2; mt++) {
        const int r0 = wm * 32 + mt * 16 + g;   // n
#pragma unroll
        for (int nt = 0; nt < 8; nt++) {
            const int col = wn * 64 + nt * 8 + 2 * t;   // d
            Cs[col * PJS + r0]           = sacc[mt][nt][0];
            Cs[(col + 1) * PJS + r0]     = sacc[mt][nt][1];
            Cs[col * PJS + r0 + 8]       = sacc[mt][nt][2];
            Cs[(col + 1) * PJS + r0 + 8] = sacc[mt][nt][3];
        }
    }
    __syncthreads();

    // coalesced store out[b][co0+d][n0..n0+128) with bias
#pragma unroll
    for (int tl = 0; tl < 16; tl++) {
        const int u = tid + tl * 256;
        const int d = u >> 5, q = u & 31;
        const float bias = bp[co0 + d];
        float4 v = *(const float4*)&Cs[d * PJS + 4 * q];
        v.x += bias; v.y += bias; v.z += bias; v.w += bias;
        *(float4*)&out[((long)b * CDIM + co0 + d) * NTOK + n0 + 4 * q] = v;
    }
}

// ---------------------------------------------------------------------------
extern "C" void kernel_launch(void* const* d_in, const int* in_sizes, int n_in,
                              void* d_out, int out_size) {
    const float* x    = (const float*)d_in[0];
    const int*   fg   = (const int*)d_in[1];
    const float* Wqkv = (const float*)d_in[2];
    const float* Wp   = (const float*)d_in[3];
    const float* bp   = (const float*)d_in[4];
    float* out = (float*)d_out;

    cudaFuncSetAttribute(qkv_kernel, cudaFuncAttributeMaxDynamicSharedMemorySize, QKV_SMEM);
    cudaFuncSetAttribute(attn_kernel, cudaFuncAttributeMaxDynamicSharedMemorySize, ATTN_SMEM);
    cudaFuncSetAttribute(proj_kernel, cudaFuncAttributeMaxDynamicSharedMemorySize, PROJ_SMEM);

    wconv_kernel<<<256, 256>>>(Wqkv, Wp);
    qkv_kernel<<<dim3(NTOK / 64, TCD / 128, BATCH), 256, QKV_SMEM>>>(x);
    attn_kernel<<<dim3(NTOK / 128, BATCH), 256, ATTN_SMEM>>>(fg);
    proj_kernel<<<dim3(NTOK / 128, CDIM / 128, BATCH), 256, PROJ_SMEM>>>(bp, out);
}

// round 14
// speedup vs baseline: 5.0497x; 1.4972x over previous
#include <cuda_runtime.h>
#include <cuda_fp16.h>

#define BATCH 4
#define CDIM 256
#define NTOK 4096   // 64*64
#define TCD 768     // 3*C
#define FULLMASK 0xffffffffu

// Scratch (allocation-free rule: __device__ globals)
__device__ __half g_Q[BATCH * NTOK * CDIM];
__device__ __half g_K[BATCH * NTOK * CDIM];
__device__ __half g_V[BATCH * NTOK * CDIM];
__device__ __half g_Kc[BATCH * NTOK * CDIM];   // compacted keys
__device__ __half g_Vc[BATCH * NTOK * CDIM];   // compacted values
__device__ __half g_AOh[BATCH * NTOK * CDIM];
__device__ __half g_Wh[TCD * CDIM];
__device__ __half g_Wph[CDIM * CDIM];
__device__ int    g_idx[BATCH * NTOK];
__device__ int    g_cnt[BATCH];

__device__ __forceinline__ float ex2(float x) {
    float r;
    asm("ex2.approx.f32 %0, %1;" : "=f"(r) : "f"(x));
    return r;
}
__device__ __forceinline__ void mma_f16(float d[4], const unsigned a[4],
                                        unsigned b0, unsigned b1) {
    asm volatile(
        "mma.sync.aligned.m16n8k16.row.col.f32.f16.f16.f32 "
        "{%0,%1,%2,%3}, {%4,%5,%6,%7}, {%8,%9}, {%0,%1,%2,%3};\n"
        : "+f"(d[0]), "+f"(d[1]), "+f"(d[2]), "+f"(d[3])
        : "r"(a[0]), "r"(a[1]), "r"(a[2]), "r"(a[3]), "r"(b0), "r"(b1));
}
__device__ __forceinline__ unsigned h2u(__half2 h) { return *(unsigned*)&h; }
__device__ __forceinline__ unsigned s2u(const void* p) {
    unsigned u;
    asm("{ .reg .u64 t; cvta.to.shared.u64 t, %1; cvt.u32.u64 %0, t; }"
        : "=r"(u) : "l"(p));
    return u;
}
__device__ __forceinline__ void ldsm_x4(unsigned r[4], unsigned addr) {
    asm volatile("ldmatrix.sync.aligned.m8n8.x4.shared.b16 {%0,%1,%2,%3}, [%4];"
        : "=r"(r[0]), "=r"(r[1]), "=r"(r[2]), "=r"(r[3]) : "r"(addr));
}
__device__ __forceinline__ void ldsm_x4_t(unsigned r[4], unsigned addr) {
    asm volatile("ldmatrix.sync.aligned.m8n8.x4.trans.shared.b16 {%0,%1,%2,%3}, [%4];"
        : "=r"(r[0]), "=r"(r[1]), "=r"(r[2]), "=r"(r[3]) : "r"(addr));
}
__device__ __forceinline__ void cp16(unsigned dst, const void* src) {
    asm volatile("cp.async.cg.shared.global [%0], [%1], 16;" :: "r"(dst), "l"(src));
}
#define CP_COMMIT() asm volatile("cp.async.commit_group;" ::: "memory")
#define CP_WAIT(n)  asm volatile("cp.async.wait_group %0;" :: "n"(n) : "memory")

// ---------------------------------------------------------------------------
// Kernel 0: one-time fp32 -> fp16 conversion of both weight matrices.
// ---------------------------------------------------------------------------
__global__ __launch_bounds__(256) void wconv_kernel(const float* __restrict__ Wqkv,
                                                    const float* __restrict__ Wp) {
    const int idx = blockIdx.x * 256 + threadIdx.x;
    const float4* src;
    uint2* dst;
    int off;
    if (idx < (TCD * CDIM / 4)) { src = (const float4*)Wqkv; dst = (uint2*)g_Wh;  off = idx; }
    else                        { src = (const float4*)Wp;   dst = (uint2*)g_Wph; off = idx - TCD * CDIM / 4; }
    float4 v = src[off];
    uint2 wv;
    wv.x = h2u(__floats2half2_rn(v.x, v.y));
    wv.y = h2u(__floats2half2_rn(v.z, v.w));
    dst[off] = wv;
}

// ---------------------------------------------------------------------------
// Kernel 0b: deterministic mask compaction (order-preserving block scan).
// grid (4), 256 threads; thread handles 16 consecutive mask entries.
// ---------------------------------------------------------------------------
__global__ __launch_bounds__(256) void compact_kernel(const int* __restrict__ fg) {
    __shared__ int ps[256];
    const int b = blockIdx.x, tid = threadIdx.x;
    const int* f = fg + b * NTOK + tid * 16;
    int loc[16], c = 0;
#pragma unroll
    for (int i = 0; i < 16; i++) { loc[i] = (f[i] != 0); c += loc[i]; }
    ps[tid] = c;
    __syncthreads();
    for (int s = 1; s < 256; s <<= 1) {
        int v = (tid >= s) ? ps[tid - s] : 0;
        __syncthreads();
        ps[tid] += v;
        __syncthreads();
    }
    int off = ps[tid] - c;   // exclusive prefix
#pragma unroll
    for (int i = 0; i < 16; i++)
        if (loc[i]) g_idx[b * NTOK + off++] = tid * 16 + i;
    if (tid == 255) g_cnt[b] = ps[255];
}

// ---------------------------------------------------------------------------
// Kernel 0c: gather compacted K/V rows (512B coalesced rows); zero-pad tail
// up to the next multiple of 128.
// grid (32, 4), 256 threads; CTA handles 128 rows.
// ---------------------------------------------------------------------------
__global__ __launch_bounds__(256) void gather_kernel() {
    const int b = blockIdx.y;
    const int cnt = g_cnt[b];
    const int padded = (cnt + 127) & ~127;
    const int r0 = blockIdx.x * 128;
    if (r0 >= padded) return;
    const int tid = threadIdx.x;
    const long bofs = (long)b * NTOK * CDIM;
#pragma unroll
    for (int tl = 0; tl < 16; tl++) {
        const int u = tid + tl * 256;
        const int row = u >> 5, j = u & 31;
        const int i = r0 + row;
        uint4 kv = make_uint4(0, 0, 0, 0), vv = make_uint4(0, 0, 0, 0);
        if (i < cnt) {
            const long src = bofs + (long)g_idx[b * NTOK + i] * CDIM + j * 8;
            kv = *(const uint4*)&g_K[src];
            vv = *(const uint4*)&g_V[src];
        }
        *(uint4*)&g_Kc[bofs + (long)i * CDIM + j * 8] = kv;
        *(uint4*)&g_Vc[bofs + (long)i * CDIM + j * 8] = vv;
    }
}

// ---------------------------------------------------------------------------
// Kernel 1: QKV GEMM (R12 version verbatim).
// ---------------------------------------------------------------------------
#define XQS 36
#define WQS 132
#define QKV_SMEM ((256 * XQS + 128 * WQS) * 4)

__global__ __launch_bounds__(256) void qkv_kernel(const float* __restrict__ x) {
    extern __shared__ unsigned sqw[];
    unsigned* Xw = sqw;
    unsigned* Wh = sqw + 256 * XQS;

    const int b  = blockIdx.z;
    const int n0 = blockIdx.x * 64;
    const int d0 = blockIdx.y * 128;
    const int tid = threadIdx.x;
    const int lane = tid & 31, w = tid >> 5;
    const int g = lane >> 2, t = lane & 3;
    const int wmd = w >> 2, wnn = w & 3;

    const float* xb = x + (long)b * CDIM * NTOK;
    const unsigned whB = s2u(Wh);

#pragma unroll
    for (int tl = 0; tl < 16; tl++) {
        const int u = tid + tl * 256;
        const int d = u >> 5, ch = u & 31;
        cp16(whB + ((d * WQS + ch * 4) << 2), &g_Wh[(long)(d0 + d) * CDIM + ch * 8]);
    }
    CP_COMMIT();
#pragma unroll
    for (int tl = 0; tl < 16; tl++) {
        const int u = tid + tl * 256;
        const int c = u >> 4, j = u & 15;
        float4 v = *(const float4*)&xb[(long)c * NTOK + n0 + 4 * j];
        uint2 wv;
        wv.x = h2u(__floats2half2_rn(v.x, v.y));
        wv.y = h2u(__floats2half2_rn(v.z, v.w));
        *(uint2*)&Xw[c * XQS + 2 * j] = wv;
    }
    CP_WAIT(0);
    __syncthreads();

    const unsigned aB = whB + (((wmd * 64 + (lane & 15)) * WQS + 4 * (lane >> 4)) << 2);
    const unsigned xB = s2u(Xw) + (((lane & 15) * XQS) << 2) +
                        ((wnn * 16 + (lane >> 4) * 8) << 1);

    float acc[4][2][4] = {};
#pragma unroll
    for (int ks = 0; ks < 16; ks++) {
        unsigned a[4][4];
#pragma unroll
        for (int mt = 0; mt < 4; mt++)
            ldsm_x4(a[mt], aB + ((mt * 16 * WQS + ks * 8) << 2));
        unsigned bb[4];
        ldsm_x4_t(bb, xB + ((ks * 16 * XQS) << 2));
#pragma unroll
        for (int mt = 0; mt < 4; mt++) {
            mma_f16(acc[mt][0], a[mt], bb[0], bb[1]);
            mma_f16(acc[mt][1], a[mt], bb[2], bb[3]);
        }
    }
    __syncthreads();

    __half* Csh = (__half*)sqw;   // [64 n][136 halves]
#pragma unroll
    for (int mt = 0; mt < 4; mt++) {
        const int r0 = wmd * 64 + mt * 16 + g;
#pragma unroll
        for (int nt = 0; nt < 2; nt++) {
            const int col = wnn * 16 + nt * 8 + 2 * t;
            Csh[col * 136 + r0]           = __float2half(acc[mt][nt][0]);
            Csh[(col + 1) * 136 + r0]     = __float2half(acc[mt][nt][1]);
            Csh[col * 136 + r0 + 8]       = __float2half(acc[mt][nt][2]);
            Csh[(col + 1) * 136 + r0 + 8] = __float2half(acc[mt][nt][3]);
        }
    }
    __syncthreads();

    const int seg = d0 >> 8;
    __half* base = (seg == 0) ? g_Q : (seg == 1) ? g_K : g_V;
    const int dl0 = d0 & 255;
#pragma unroll
    for (int tl = 0; tl < 4; tl++) {
        const int u = tid + tl * 256;
        const int n = u >> 4, d8 = u & 15;
        uint4 v = *(const uint4*)&Csh[n * 136 + d8 * 8];
        *(uint4*)&base[((long)b * NTOK + n0 + n) * CDIM + dl0 + d8 * 8] = v;
    }
}

// ---------------------------------------------------------------------------
// Kernel 2: fp16 mma flash attention over COMPACTED keys (R12 body verbatim;
// dynamic tile count from g_cnt, mask replaced by padding predicate).
// ---------------------------------------------------------------------------
#define QW 132
#define PW 68
#define KVW (128 * QW)
#define ATTN_SMEM ((128 * QW + KVW + 128 * PW) * 4 + (128 + 256 + 128) * 4)

__global__ __launch_bounds__(256, 1) void attn_kernel() {
    extern __shared__ unsigned smw[];
    unsigned* Qw = smw;                      // [128][132] words (fp16 pairs)
    unsigned* Kw = Qw + 128 * QW;            // K tile, then V tile (plain)
    unsigned* Pw = Kw + KVW;                 // [128][68] words (fp16 pairs)
    float* fgf   = (float*)(Pw + 128 * PW);  // [128]
    float* lsumP = fgf + 128;                // [2][128]
    float* runl  = lsumP + 256;              // [128]

    const int b   = blockIdx.y;
    const int q0  = blockIdx.x * 128;
    const int tid = threadIdx.x;
    const int lane = tid & 31, w = tid >> 5;
    const int g = lane >> 2, t = lane & 3;
    const int wmS = w >> 1, wnS = w & 1;     // S: 4x2 grid, warp tile 32x64
    const int wmO = w >> 2, wnO = w & 3;     // O: 2x4 grid, warp tile 64x64

    const int cnt = g_cnt[b];
    const int padded = (cnt + 127) & ~127;

    const __half* Qg = g_Q + ((long)b * NTOK + q0) * CDIM;
    const __half* Kg = g_Kc + (long)b * NTOK * CDIM;
    const __half* Vg = g_Vc + (long)b * NTOK * CDIM;

#pragma unroll
    for (int tl = 0; tl < 16; tl++) {
        const int u = tid + tl * 256;
        const int row = u >> 5, j = u & 31;
        uint4 v = *(const uint4*)&Qg[(long)row * CDIM + j * 8];
        *(uint4*)&Qw[row * QW + j * 4] = v;
    }
    if (tid < 128) runl[tid] = 0.0f;

    const unsigned kwB = s2u(Kw);
    const unsigned qaB = s2u(Qw) +
        (((wmS * 32 + (lane & 15)) * QW + 4 * (lane >> 4)) << 2);
    const unsigned kbB = kwB +
        (((wnS * 64 + ((lane >> 4) << 3) + (lane & 7)) * QW + ((lane >> 3) & 1) * 4) << 2);
    const unsigned paB = s2u(Pw) +
        (((wmO * 64 + (lane & 15)) * PW + 4 * (lane >> 4)) << 2);
    const unsigned vbB = kwB + (((lane & 15) * QW) << 2) +
        ((wnO * 64 + (lane >> 4) * 8) << 1);

    float oacc[4][8][4];
#pragma unroll
    for (int i = 0; i < 4; i++)
#pragma unroll
        for (int j = 0; j < 8; j++)
#pragma unroll
            for (int k = 0; k < 4; k++) oacc[i][j][k] = 0.0f;

    const float SC = 0.0625f * 1.4426950408889634f;

    for (int m0 = 0; m0 < padded; m0 += 128) {
        __syncthreads();

        // K half 0 (c 0..127)
#pragma unroll
        for (int tl = 0; tl < 8; tl++) {
            const int u = tid + tl * 256;
            const int row = u >> 4, j = u & 15;
            cp16(kwB + ((row * QW + j * 4) << 2),
                 &Kg[(long)(m0 + row) * CDIM + j * 8]);
        }
        CP_COMMIT();
        // K half 1 (c 128..255)
#pragma unroll
        for (int tl = 0; tl < 8; tl++) {
            const int u = tid + tl * 256;
            const int row = u >> 4, j = u & 15;
            cp16(kwB + ((row * QW + 64 + j * 4) << 2),
                 &Kg[(long)(m0 + row) * CDIM + 128 + j * 8]);
        }
        CP_COMMIT();

        if (tid < 128) fgf[tid] = (m0 + tid < cnt) ? 1.0f : 0.0f;

        float sacc[2][8][4] = {};

        CP_WAIT(1);
        __syncthreads();
#pragma unroll
        for (int ks = 0; ks < 8; ks++) {
            unsigned a[2][4];
            ldsm_x4(a[0], qaB + ((ks * 8) << 2));
            ldsm_x4(a[1], qaB + ((16 * QW + ks * 8) << 2));
#pragma unroll
            for (int ntp = 0; ntp < 4; ntp++) {
                unsigned bb[4];
                ldsm_x4(bb, kbB + ((ntp * 16 * QW + ks * 8) << 2));
                mma_f16(sacc[0][2 * ntp], a[0], bb[0], bb[1]);
                mma_f16(sacc[1][2 * ntp], a[1], bb[0], bb[1]);
                mma_f16(sacc[0][2 * ntp + 1], a[0], bb[2], bb[3]);
                mma_f16(sacc[1][2 * ntp + 1], a[1], bb[2], bb[3]);
            }
        }
        CP_WAIT(0);
        __syncthreads();
#pragma unroll
        for (int ks = 8; ks < 16; ks++) {
            unsigned a[2][4];
            ldsm_x4(a[0], qaB + ((ks * 8) << 2));
            ldsm_x4(a[1], qaB + ((16 * QW + ks * 8) << 2));
#pragma unroll
            for (int ntp = 0; ntp < 4; ntp++) {
                unsigned bb[4];
                ldsm_x4(bb, kbB + ((ntp * 16 * QW + ks * 8) << 2));
                mma_f16(sacc[0][2 * ntp], a[0], bb[0], bb[1]);
                mma_f16(sacc[1][2 * ntp], a[1], bb[0], bb[1]);
                mma_f16(sacc[0][2 * ntp + 1], a[0], bb[2], bb[3]);
                mma_f16(sacc[1][2 * ntp + 1], a[1], bb[2], bb[3]);
            }
        }
        __syncthreads();

        // V staging issued now; softmax hides its latency
#pragma unroll
        for (int tl = 0; tl < 16; tl++) {
            const int u = tid + tl * 256;
            const int row = u >> 5, j = u & 31;
            cp16(kwB + ((row * QW + j * 4) << 2),
                 &Vg[(long)(m0 + row) * CDIM + j * 8]);
        }
        CP_COMMIT();

        float rsum[4] = {0.0f, 0.0f, 0.0f, 0.0f};
#pragma unroll
        for (int mt = 0; mt < 2; mt++) {
            const int r0 = wmS * 32 + mt * 16 + g;
#pragma unroll
            for (int nt = 0; nt < 8; nt++) {
                const int col = wnS * 64 + nt * 8 + 2 * t;
                const float f0 = fgf[col], f1 = fgf[col + 1];
                float p0 = ex2(sacc[mt][nt][0] * SC) * f0;
                float p1 = ex2(sacc[mt][nt][1] * SC) * f1;
                float p2 = ex2(sacc[mt][nt][2] * SC) * f0;
                float p3 = ex2(sacc[mt][nt][3] * SC) * f1;
                rsum[mt * 2 + 0] += p0 + p1;
                rsum[mt * 2 + 1] += p2 + p3;
                __half2 h01 = __floats2half2_rn(p0, p1);
                __half2 h23 = __floats2half2_rn(p2, p3);
                Pw[r0 * PW + (col >> 1)] = *(unsigned*)&h01;
                Pw[(r0 + 8) * PW + (col >> 1)] = *(unsigned*)&h23;
            }
        }
#pragma unroll
        for (int si = 0; si < 4; si++) {
            rsum[si] += __shfl_xor_sync(FULLMASK, rsum[si], 1);
            rsum[si] += __shfl_xor_sync(FULLMASK, rsum[si], 2);
        }
        if (t == 0) {
            const int rb = wmS * 32 + g;
            lsumP[wnS * 128 + rb]      = rsum[0];
            lsumP[wnS * 128 + rb + 8]  = rsum[1];
            lsumP[wnS * 128 + rb + 16] = rsum[2];
            lsumP[wnS * 128 + rb + 24] = rsum[3];
        }
        CP_WAIT(0);
        __syncthreads();
        if (tid < 128) runl[tid] += lsumP[tid] + lsumP[128 + tid];

#pragma unroll
        for (int ks = 0; ks < 8; ks++) {
            unsigned a[4][4];
#pragma unroll
            for (int mt = 0; mt < 4; mt++)
                ldsm_x4(a[mt], paB + ((mt * 16 * PW + ks * 8) << 2));
#pragma unroll
            for (int ntp = 0; ntp < 4; ntp++) {
                unsigned vv[4];
                ldsm_x4_t(vv, vbB + ((ks * 16 * QW) << 2) + (ntp << 5));
#pragma unroll
                for (int mt = 0; mt < 4; mt++) {
                    mma_f16(oacc[mt][2 * ntp], a[mt], vv[0], vv[1]);
                    mma_f16(oacc[mt][2 * ntp + 1], a[mt], vv[2], vv[3]);
                }
            }
        }
    }

    // ---- epilogue: normalize and store fp16 AO ----
    __half* AOg = g_AOh + ((long)b * NTOK + q0) * CDIM;
#pragma unroll
    for (int mt = 0; mt < 4; mt++) {
        const int r0 = wmO * 64 + mt * 16 + g;
        const float inv0 = 1.0f / runl[r0];
        const float inv1 = 1.0f / runl[r0 + 8];
#pragma unroll
        for (int nt = 0; nt < 8; nt++) {
            const int col = wnO * 64 + nt * 8 + 2 * t;
            *(__half2*)&AOg[(long)r0 * CDIM + col] =
                __floats2half2_rn(oacc[mt][nt][0] * inv0, oacc[mt][nt][1] * inv0);
            *(__half2*)&AOg[(long)(r0 + 8) * CDIM + col] =
                __floats2half2_rn(oacc[mt][nt][2] * inv1, oacc[mt][nt][3] * inv1);
        }
    }
}

// ---------------------------------------------------------------------------
// Kernel 3: projection (R12 version verbatim — 17.5us).
// ---------------------------------------------------------------------------
#define PJS 132
#define PROJ_SMEM ((128 * PJS + 128 * PJS) * 4)

__global__ __launch_bounds__(256) void proj_kernel(const float* __restrict__ bp,
                                                   float* __restrict__ out) {
    extern __shared__ unsigned spw[];
    unsigned* Ah = spw;
    unsigned* Wh = spw + 128 * PJS;
    float* Cs = (float*)spw;

    const int b   = blockIdx.z;
    const int n0  = blockIdx.x * 128;
    const int co0 = blockIdx.y * 128;
    const int tid = threadIdx.x;
    const int lane = tid & 31, w = tid >> 5;
    const int g = lane >> 2, t = lane & 3;
    const int wm = w >> 1, wn = w & 1;

    const unsigned ahB = s2u(Ah), whB = s2u(Wh);
#pragma unroll
    for (int tl = 0; tl < 16; tl++) {
        const int u = tid + tl * 256;
        const int n = u >> 5, ch = u & 31;
        cp16(ahB + ((n * PJS + ch * 4) << 2),
             &g_AOh[((long)b * NTOK + n0 + n) * CDIM + ch * 8]);
    }
#pragma unroll
    for (int tl = 0; tl < 16; tl++) {
        const int u = tid + tl * 256;
        const int d = u >> 5, ch = u & 31;
        cp16(whB + ((d * PJS + ch * 4) << 2),
             &g_Wph[(long)(co0 + d) * CDIM + ch * 8]);
    }
    CP_COMMIT();
    CP_WAIT(0);
    __syncthreads();

    const unsigned aB = ahB + (((wm * 32 + (lane & 15)) * PJS + 4 * (lane >> 4)) << 2);
    const unsigned bB = whB +
        (((wn * 64 + ((lane >> 4) << 3) + (lane & 7)) * PJS + ((lane >> 3) & 1) * 4) << 2);

    float sacc[2][8][4] = {};
#pragma unroll
    for (int ks = 0; ks < 16; ks++) {
        unsigned a[2][4];
        ldsm_x4(a[0], aB + ((ks * 8) << 2));
        ldsm_x4(a[1], aB + ((16 * PJS + ks * 8) << 2));
#pragma unroll
        for (int ntp = 0; ntp < 4; ntp++) {
            unsigned bb[4];
            ldsm_x4(bb, bB + ((ntp * 16 * PJS + ks * 8) << 2));
            mma_f16(sacc[0][2 * ntp], a[0], bb[0], bb[1]);
            mma_f16(sacc[1][2 * ntp], a[1], bb[0], bb[1]);
            mma_f16(sacc[0][2 * ntp + 1], a[0], bb[2], bb[3]);
            mma_f16(sacc[1][2 * ntp + 1], a[1], bb[2], bb[3]);
        }
    }
    __syncthreads();

#pragma unroll
    for (int mt = 0; mt < 2; mt++) {
        const int r0 = wm * 32 + mt * 16 + g;
#pragma unroll
        for (int nt = 0; nt < 8; nt++) {
            const int col = wn * 64 + nt * 8 + 2 * t;
            Cs[col * PJS + r0]           = sacc[mt][nt][0];
            Cs[(col + 1) * PJS + r0]     = sacc[mt][nt][1];
            Cs[col * PJS + r0 + 8]       = sacc[mt][nt][2];
            Cs[(col + 1) * PJS + r0 + 8] = sacc[mt][nt][3];
        }
    }
    __syncthreads();

#pragma unroll
    for (int tl = 0; tl < 16; tl++) {
        const int u = tid + tl * 256;
        const int d = u >> 5, q = u & 31;
        const float bias = bp[co0 + d];
        float4 v = *(const float4*)&Cs[d * PJS + 4 * q];
        v.x += bias; v.y += bias; v.z += bias; v.w += bias;
        *(float4*)&out[((long)b * CDIM + co0 + d) * NTOK + n0 + 4 * q] = v;
    }
}

// ---------------------------------------------------------------------------
extern "C" void kernel_launch(void* const* d_in, const int* in_sizes, int n_in,
                              void* d_out, int out_size) {
    const float* x    = (const float*)d_in[0];
    const int*   fg   = (const int*)d_in[1];
    const float* Wqkv = (const float*)d_in[2];
    const float* Wp   = (const float*)d_in[3];
    const float* bp   = (const float*)d_in[4];
    float* out = (float*)d_out;

    cudaFuncSetAttribute(qkv_kernel, cudaFuncAttributeMaxDynamicSharedMemorySize, QKV_SMEM);
    cudaFuncSetAttribute(attn_kernel, cudaFuncAttributeMaxDynamicSharedMemorySize, ATTN_SMEM);
    cudaFuncSetAttribute(proj_kernel, cudaFuncAttributeMaxDynamicSharedMemorySize, PROJ_SMEM);

    wconv_kernel<<<256, 256>>>(Wqkv, Wp);
    compact_kernel<<<BATCH, 256>>>(fg);
    qkv_kernel<<<dim3(NTOK / 64, TCD / 128, BATCH), 256, QKV_SMEM>>>(x);
    gather_kernel<<<dim3(NTOK / 128, BATCH), 256>>>();
    attn_kernel<<<dim3(NTOK / 128, BATCH), 256, ATTN_SMEM>>>();
    proj_kernel<<<dim3(NTOK / 128, CDIM / 128, BATCH), 256, PROJ_SMEM>>>(bp, out);
}

// round 15
// speedup vs baseline: 5.1517x; 1.0202x over previous
#include <cuda_runtime.h>
#include <cuda_fp16.h>

#define BATCH 4
#define CDIM 256
#define NTOK 4096   // 64*64
#define TCD 768     // 3*C
#define FULLMASK 0xffffffffu

// Scratch (allocation-free rule: __device__ globals)
__device__ __half g_Q[BATCH * NTOK * CDIM];
__device__ __half g_Kc[BATCH * NTOK * CDIM];   // compacted keys
__device__ __half g_Vc[BATCH * NTOK * CDIM];   // compacted values
__device__ __half g_AOh[BATCH * NTOK * CDIM];
__device__ __half g_Wh[TCD * CDIM];
__device__ __half g_Wph[CDIM * CDIM];
__device__ int    g_pos[BATCH * NTOK];         // scatter index or -1
__device__ int    g_cnt[BATCH];

__device__ __forceinline__ float ex2(float x) {
    float r;
    asm("ex2.approx.f32 %0, %1;" : "=f"(r) : "f"(x));
    return r;
}
__device__ __forceinline__ void mma_f16(float d[4], const unsigned a[4],
                                        unsigned b0, unsigned b1) {
    asm volatile(
        "mma.sync.aligned.m16n8k16.row.col.f32.f16.f16.f32 "
        "{%0,%1,%2,%3}, {%4,%5,%6,%7}, {%8,%9}, {%0,%1,%2,%3};\n"
        : "+f"(d[0]), "+f"(d[1]), "+f"(d[2]), "+f"(d[3])
        : "r"(a[0]), "r"(a[1]), "r"(a[2]), "r"(a[3]), "r"(b0), "r"(b1));
}
__device__ __forceinline__ unsigned h2u(__half2 h) { return *(unsigned*)&h; }
__device__ __forceinline__ unsigned s2u(const void* p) {
    unsigned u;
    asm("{ .reg .u64 t; cvta.to.shared.u64 t, %1; cvt.u32.u64 %0, t; }"
        : "=r"(u) : "l"(p));
    return u;
}
__device__ __forceinline__ void ldsm_x4(unsigned r[4], unsigned addr) {
    asm volatile("ldmatrix.sync.aligned.m8n8.x4.shared.b16 {%0,%1,%2,%3}, [%4];"
        : "=r"(r[0]), "=r"(r[1]), "=r"(r[2]), "=r"(r[3]) : "r"(addr));
}
__device__ __forceinline__ void ldsm_x4_t(unsigned r[4], unsigned addr) {
    asm volatile("ldmatrix.sync.aligned.m8n8.x4.trans.shared.b16 {%0,%1,%2,%3}, [%4];"
        : "=r"(r[0]), "=r"(r[1]), "=r"(r[2]), "=r"(r[3]) : "r"(addr));
}
__device__ __forceinline__ void cp16(unsigned dst, const void* src) {
    asm volatile("cp.async.cg.shared.global [%0], [%1], 16;" :: "r"(dst), "l"(src));
}
#define CP_COMMIT() asm volatile("cp.async.commit_group;" ::: "memory")
#define CP_WAIT(n)  asm volatile("cp.async.wait_group %0;" :: "n"(n) : "memory")

// ---------------------------------------------------------------------------
// Kernel 0: one-time fp32 -> fp16 conversion of both weight matrices.
// ---------------------------------------------------------------------------
__global__ __launch_bounds__(256) void wconv_kernel(const float* __restrict__ Wqkv,
                                                    const float* __restrict__ Wp) {
    const int idx = blockIdx.x * 256 + threadIdx.x;
    const float4* src;
    uint2* dst;
    int off;
    if (idx < (TCD * CDIM / 4)) { src = (const float4*)Wqkv; dst = (uint2*)g_Wh;  off = idx; }
    else                        { src = (const float4*)Wp;   dst = (uint2*)g_Wph; off = idx - TCD * CDIM / 4; }
    float4 v = src[off];
    uint2 wv;
    wv.x = h2u(__floats2half2_rn(v.x, v.y));
    wv.y = h2u(__floats2half2_rn(v.z, v.w));
    dst[off] = wv;
}

// ---------------------------------------------------------------------------
// Kernel 0b: deterministic mask compaction -> per-key scatter position.
// grid (4), 256 threads; thread handles 16 consecutive mask entries.
// ---------------------------------------------------------------------------
__global__ __launch_bounds__(256) void compact_kernel(const int* __restrict__ fg) {
    __shared__ int ps[256];
    const int b = blockIdx.x, tid = threadIdx.x;
    const int* f = fg + b * NTOK + tid * 16;
    int loc[16], c = 0;
#pragma unroll
    for (int i = 0; i < 16; i++) { loc[i] = (f[i] != 0); c += loc[i]; }
    ps[tid] = c;
    __syncthreads();
    for (int s = 1; s < 256; s <<= 1) {
        int v = (tid >= s) ? ps[tid - s] : 0;
        __syncthreads();
        ps[tid] += v;
        __syncthreads();
    }
    int off = ps[tid] - c;   // exclusive prefix
#pragma unroll
    for (int i = 0; i < 16; i++) {
        g_pos[b * NTOK + tid * 16 + i] = loc[i] ? off : -1;
        off += loc[i];
    }
    if (tid == 255) g_cnt[b] = ps[255];
}

// ---------------------------------------------------------------------------
// Kernel 0c: zero-pad tail rows [cnt, padded128) of compacted K/V.
// grid (4), 256 threads.
// ---------------------------------------------------------------------------
__global__ __launch_bounds__(256) void pad_kernel() {
    const int b = blockIdx.x;
    const int cnt = g_cnt[b];
    const int padded = (cnt + 127) & ~127;
    const int n4 = (padded - cnt) * 32;   // uint4 per matrix
    for (int i = threadIdx.x; i < n4; i += 256) {
        const int row = cnt + (i >> 5), j = i & 31;
        const long o = ((long)b * NTOK + row) * CDIM + j * 8;
        *(uint4*)&g_Kc[o] = make_uint4(0, 0, 0, 0);
        *(uint4*)&g_Vc[o] = make_uint4(0, 0, 0, 0);
    }
}

// ---------------------------------------------------------------------------
// Kernel 1: QKV GEMM (R12 mainloop verbatim). K/V segments scatter rows
// directly to compacted positions (dead keys skipped).
// ---------------------------------------------------------------------------
#define XQS 36
#define WQS 132
#define QKV_SMEM ((256 * XQS + 128 * WQS) * 4)

__global__ __launch_bounds__(256) void qkv_kernel(const float* __restrict__ x) {
    extern __shared__ unsigned sqw[];
    unsigned* Xw = sqw;
    unsigned* Wh = sqw + 256 * XQS;

    const int b  = blockIdx.z;
    const int n0 = blockIdx.x * 64;
    const int d0 = blockIdx.y * 128;
    const int tid = threadIdx.x;
    const int lane = tid & 31, w = tid >> 5;
    const int g = lane >> 2, t = lane & 3;
    const int wmd = w >> 2, wnn = w & 3;

    const float* xb = x + (long)b * CDIM * NTOK;
    const unsigned whB = s2u(Wh);

#pragma unroll
    for (int tl = 0; tl < 16; tl++) {
        const int u = tid + tl * 256;
        const int d = u >> 5, ch = u & 31;
        cp16(whB + ((d * WQS + ch * 4) << 2), &g_Wh[(long)(d0 + d) * CDIM + ch * 8]);
    }
    CP_COMMIT();
#pragma unroll
    for (int tl = 0; tl < 16; tl++) {
        const int u = tid + tl * 256;
        const int c = u >> 4, j = u & 15;
        float4 v = *(const float4*)&xb[(long)c * NTOK + n0 + 4 * j];
        uint2 wv;
        wv.x = h2u(__floats2half2_rn(v.x, v.y));
        wv.y = h2u(__floats2half2_rn(v.z, v.w));
        *(uint2*)&Xw[c * XQS + 2 * j] = wv;
    }
    CP_WAIT(0);
    __syncthreads();

    const unsigned aB = whB + (((wmd * 64 + (lane & 15)) * WQS + 4 * (lane >> 4)) << 2);
    const unsigned xB = s2u(Xw) + (((lane & 15) * XQS) << 2) +
                        ((wnn * 16 + (lane >> 4) * 8) << 1);

    float acc[4][2][4] = {};
#pragma unroll
    for (int ks = 0; ks < 16; ks++) {
        unsigned a[4][4];
#pragma unroll
        for (int mt = 0; mt < 4; mt++)
            ldsm_x4(a[mt], aB + ((mt * 16 * WQS + ks * 8) << 2));
        unsigned bb[4];
        ldsm_x4_t(bb, xB + ((ks * 16 * XQS) << 2));
#pragma unroll
        for (int mt = 0; mt < 4; mt++) {
            mma_f16(acc[mt][0], a[mt], bb[0], bb[1]);
            mma_f16(acc[mt][1], a[mt], bb[2], bb[3]);
        }
    }
    __syncthreads();

    __half* Csh = (__half*)sqw;   // [64 n][136 halves]
#pragma unroll
    for (int mt = 0; mt < 4; mt++) {
        const int r0 = wmd * 64 + mt * 16 + g;
#pragma unroll
        for (int nt = 0; nt < 2; nt++) {
            const int col = wnn * 16 + nt * 8 + 2 * t;
            Csh[col * 136 + r0]           = __float2half(acc[mt][nt][0]);
            Csh[(col + 1) * 136 + r0]     = __float2half(acc[mt][nt][1]);
            Csh[col * 136 + r0 + 8]       = __float2half(acc[mt][nt][2]);
            Csh[(col + 1) * 136 + r0 + 8] = __float2half(acc[mt][nt][3]);
        }
    }
    __syncthreads();

    const int seg = d0 >> 8;
    const int dl0 = d0 & 255;
    if (seg == 0) {
#pragma unroll
        for (int tl = 0; tl < 4; tl++) {
            const int u = tid + tl * 256;
            const int n = u >> 4, d8 = u & 15;
            uint4 v = *(const uint4*)&Csh[n * 136 + d8 * 8];
            *(uint4*)&g_Q[((long)b * NTOK + n0 + n) * CDIM + dl0 + d8 * 8] = v;
        }
    } else {
        __half* basec = (seg == 1) ? g_Kc : g_Vc;
#pragma unroll
        for (int tl = 0; tl < 4; tl++) {
            const int u = tid + tl * 256;
            const int n = u >> 4, d8 = u & 15;
            const int np = g_pos[b * NTOK + n0 + n];
            if (np >= 0) {
                uint4 v = *(const uint4*)&Csh[n * 136 + d8 * 8];
                *(uint4*)&basec[((long)b * NTOK + np) * CDIM + dl0 + d8 * 8] = v;
            }
        }
    }
}

// ---------------------------------------------------------------------------
// Kernel 2: fp16 mma flash attention over COMPACTED keys (R14 verbatim).
// ---------------------------------------------------------------------------
#define QW 132
#define PW 68
#define KVW (128 * QW)
#define ATTN_SMEM ((128 * QW + KVW + 128 * PW) * 4 + (128 + 256 + 128) * 4)

__global__ __launch_bounds__(256, 1) void attn_kernel() {
    extern __shared__ unsigned smw[];
    unsigned* Qw = smw;                      // [128][132] words (fp16 pairs)
    unsigned* Kw = Qw + 128 * QW;            // K tile, then V tile (plain)
    unsigned* Pw = Kw + KVW;                 // [128][68] words (fp16 pairs)
    float* fgf   = (float*)(Pw + 128 * PW);  // [128]
    float* lsumP = fgf + 128;                // [2][128]
    float* runl  = lsumP + 256;              // [128]

    const int b   = blockIdx.y;
    const int q0  = blockIdx.x * 128;
    const int tid = threadIdx.x;
    const int lane = tid & 31, w = tid >> 5;
    const int g = lane >> 2, t = lane & 3;
    const int wmS = w >> 1, wnS = w & 1;     // S: 4x2 grid, warp tile 32x64
    const int wmO = w >> 2, wnO = w & 3;     // O: 2x4 grid, warp tile 64x64

    const int cnt = g_cnt[b];
    const int padded = (cnt + 127) & ~127;

    const __half* Qg = g_Q + ((long)b * NTOK + q0) * CDIM;
    const __half* Kg = g_Kc + (long)b * NTOK * CDIM;
    const __half* Vg = g_Vc + (long)b * NTOK * CDIM;

#pragma unroll
    for (int tl = 0; tl < 16; tl++) {
        const int u = tid + tl * 256;
        const int row = u >> 5, j = u & 31;
        uint4 v = *(const uint4*)&Qg[(long)row * CDIM + j * 8];
        *(uint4*)&Qw[row * QW + j * 4] = v;
    }
    if (tid < 128) runl[tid] = 0.0f;

    const unsigned kwB = s2u(Kw);
    const unsigned qaB = s2u(Qw) +
        (((wmS * 32 + (lane & 15)) * QW + 4 * (lane >> 4)) << 2);
    const unsigned kbB = kwB +
        (((wnS * 64 + ((lane >> 4) << 3) + (lane & 7)) * QW + ((lane >> 3) & 1) * 4) << 2);
    const unsigned paB = s2u(Pw) +
        (((wmO * 64 + (lane & 15)) * PW + 4 * (lane >> 4)) << 2);
    const unsigned vbB = kwB + (((lane & 15) * QW) << 2) +
        ((wnO * 64 + (lane >> 4) * 8) << 1);

    float oacc[4][8][4];
#pragma unroll
    for (int i = 0; i < 4; i++)
#pragma unroll
        for (int j = 0; j < 8; j++)
#pragma unroll
            for (int k = 0; k < 4; k++) oacc[i][j][k] = 0.0f;

    const float SC = 0.0625f * 1.4426950408889634f;

    for (int m0 = 0; m0 < padded; m0 += 128) {
        __syncthreads();

        // K half 0 (c 0..127)
#pragma unroll
        for (int tl = 0; tl < 8; tl++) {
            const int u = tid + tl * 256;
            const int row = u >> 4, j = u & 15;
            cp16(kwB + ((row * QW + j * 4) << 2),
                 &Kg[(long)(m0 + row) * CDIM + j * 8]);
        }
        CP_COMMIT();
        // K half 1 (c 128..255)
#pragma unroll
        for (int tl = 0; tl < 8; tl++) {
            const int u = tid + tl * 256;
            const int row = u >> 4, j = u & 15;
            cp16(kwB + ((row * QW + 64 + j * 4) << 2),
                 &Kg[(long)(m0 + row) * CDIM + 128 + j * 8]);
        }
        CP_COMMIT();

        if (tid < 128) fgf[tid] = (m0 + tid < cnt) ? 1.0f : 0.0f;

        float sacc[2][8][4] = {};

        CP_WAIT(1);
        __syncthreads();
#pragma unroll
        for (int ks = 0; ks < 8; ks++) {
            unsigned a[2][4];
            ldsm_x4(a[0], qaB + ((ks * 8) << 2));
            ldsm_x4(a[1], qaB + ((16 * QW + ks * 8) << 2));
#pragma unroll
            for (int ntp = 0; ntp < 4; ntp++) {
                unsigned bb[4];
                ldsm_x4(bb, kbB + ((ntp * 16 * QW + ks * 8) << 2));
                mma_f16(sacc[0][2 * ntp], a[0], bb[0], bb[1]);
                mma_f16(sacc[1][2 * ntp], a[1], bb[0], bb[1]);
                mma_f16(sacc[0][2 * ntp + 1], a[0], bb[2], bb[3]);
                mma_f16(sacc[1][2 * ntp + 1], a[1], bb[2], bb[3]);
            }
        }
        CP_WAIT(0);
        __syncthreads();
#pragma unroll
        for (int ks = 8; ks < 16; ks++) {
            unsigned a[2][4];
            ldsm_x4(a[0], qaB + ((ks * 8) << 2));
            ldsm_x4(a[1], qaB + ((16 * QW + ks * 8) << 2));
#pragma unroll
            for (int ntp = 0; ntp < 4; ntp++) {
                unsigned bb[4];
                ldsm_x4(bb, kbB + ((ntp * 16 * QW + ks * 8) << 2));
                mma_f16(sacc[0][2 * ntp], a[0], bb[0], bb[1]);
                mma_f16(sacc[1][2 * ntp], a[1], bb[0], bb[1]);
                mma_f16(sacc[0][2 * ntp + 1], a[0], bb[2], bb[3]);
                mma_f16(sacc[1][2 * ntp + 1], a[1], bb[2], bb[3]);
            }
        }
        __syncthreads();

        // V staging issued now; softmax hides its latency
#pragma unroll
        for (int tl = 0; tl < 16; tl++) {
            const int u = tid + tl * 256;
            const int row = u >> 5, j = u & 31;
            cp16(kwB + ((row * QW + j * 4) << 2),
                 &Vg[(long)(m0 + row) * CDIM + j * 8]);
        }
        CP_COMMIT();

        float rsum[4] = {0.0f, 0.0f, 0.0f, 0.0f};
#pragma unroll
        for (int mt = 0; mt < 2; mt++) {
            const int r0 = wmS * 32 + mt * 16 + g;
#pragma unroll
            for (int nt = 0; nt < 8; nt++) {
                const int col = wnS * 64 + nt * 8 + 2 * t;
                const float f0 = fgf[col], f1 = fgf[col + 1];
                float p0 = ex2(sacc[mt][nt][0] * SC) * f0;
                float p1 = ex2(sacc[mt][nt][1] * SC) * f1;
                float p2 = ex2(sacc[mt][nt][2] * SC) * f0;
                float p3 = ex2(sacc[mt][nt][3] * SC) * f1;
                rsum[mt * 2 + 0] += p0 + p1;
                rsum[mt * 2 + 1] += p2 + p3;
                __half2 h01 = __floats2half2_rn(p0, p1);
                __half2 h23 = __floats2half2_rn(p2, p3);
                Pw[r0 * PW + (col >> 1)] = *(unsigned*)&h01;
                Pw[(r0 + 8) * PW + (col >> 1)] = *(unsigned*)&h23;
            }
        }
#pragma unroll
        for (int si = 0; si < 4; si++) {
            rsum[si] += __shfl_xor_sync(FULLMASK, rsum[si], 1);
            rsum[si] += __shfl_xor_sync(FULLMASK, rsum[si], 2);
        }
        if (t == 0) {
            const int rb = wmS * 32 + g;
            lsumP[wnS * 128 + rb]      = rsum[0];
            lsumP[wnS * 128 + rb + 8]  = rsum[1];
            lsumP[wnS * 128 + rb + 16] = rsum[2];
            lsumP[wnS * 128 + rb + 24] = rsum[3];
        }
        CP_WAIT(0);
        __syncthreads();
        if (tid < 128) runl[tid] += lsumP[tid] + lsumP[128 + tid];

#pragma unroll
        for (int ks = 0; ks < 8; ks++) {
            unsigned a[4][4];
#pragma unroll
            for (int mt = 0; mt < 4; mt++)
                ldsm_x4(a[mt], paB + ((mt * 16 * PW + ks * 8) << 2));
#pragma unroll
            for (int ntp = 0; ntp < 4; ntp++) {
                unsigned vv[4];
                ldsm_x4_t(vv, vbB + ((ks * 16 * QW) << 2) + (ntp << 5));
#pragma unroll
                for (int mt = 0; mt < 4; mt++) {
                    mma_f16(oacc[mt][2 * ntp], a[mt], vv[0], vv[1]);
                    mma_f16(oacc[mt][2 * ntp + 1], a[mt], vv[2], vv[3]);
                }
            }
        }
    }

    // ---- epilogue: normalize and store fp16 AO ----
    __half* AOg = g_AOh + ((long)b * NTOK + q0) * CDIM;
#pragma unroll
    for (int mt = 0; mt < 4; mt++) {
        const int r0 = wmO * 64 + mt * 16 + g;
        const float inv0 = 1.0f / runl[r0];
        const float inv1 = 1.0f / runl[r0 + 8];
#pragma unroll
        for (int nt = 0; nt < 8; nt++) {
            const int col = wnO * 64 + nt * 8 + 2 * t;
            *(__half2*)&AOg[(long)r0 * CDIM + col] =
                __floats2half2_rn(oacc[mt][nt][0] * inv0, oacc[mt][nt][1] * inv0);
            *(__half2*)&AOg[(long)(r0 + 8) * CDIM + col] =
                __floats2half2_rn(oacc[mt][nt][2] * inv1, oacc[mt][nt][3] * inv1);
        }
    }
}

// ---------------------------------------------------------------------------
// Kernel 3: projection (R12 version verbatim — 17.5us).
// ---------------------------------------------------------------------------
#define PJS 132
#define PROJ_SMEM ((128 * PJS + 128 * PJS) * 4)

__global__ __launch_bounds__(256) void proj_kernel(const float* __restrict__ bp,
                                                   float* __restrict__ out) {
    extern __shared__ unsigned spw[];
    unsigned* Ah = spw;
    unsigned* Wh = spw + 128 * PJS;
    float* Cs = (float*)spw;

    const int b   = blockIdx.z;
    const int n0  = blockIdx.x * 128;
    const int co0 = blockIdx.y * 128;
    const int tid = threadIdx.x;
    const int lane = tid & 31, w = tid >> 5;
    const int g = lane >> 2, t = lane & 3;
    const int wm = w >> 1, wn = w & 1;

    const unsigned ahB = s2u(Ah), whB = s2u(Wh);
#pragma unroll
    for (int tl = 0; tl < 16; tl++) {
        const int u = tid + tl * 256;
        const int n = u >> 5, ch = u & 31;
        cp16(ahB + ((n * PJS + ch * 4) << 2),
             &g_AOh[((long)b * NTOK + n0 + n) * CDIM + ch * 8]);
    }
#pragma unroll
    for (int tl = 0; tl < 16; tl++) {
        const int u = tid + tl * 256;
        const int d = u >> 5, ch = u & 31;
        cp16(whB + ((d * PJS + ch * 4) << 2),
             &g_Wph[(long)(co0 + d) * CDIM + ch * 8]);
    }
    CP_COMMIT();
    CP_WAIT(0);
    __syncthreads();

    const unsigned aB = ahB + (((wm * 32 + (lane & 15)) * PJS + 4 * (lane >> 4)) << 2);
    const unsigned bB = whB +
        (((wn * 64 + ((lane >> 4) << 3) + (lane & 7)) * PJS + ((lane >> 3) & 1) * 4) << 2);

    float sacc[2][8][4] = {};
#pragma unroll
    for (int ks = 0; ks < 16; ks++) {
        unsigned a[2][4];
        ldsm_x4(a[0], aB + ((ks * 8) << 2));
        ldsm_x4(a[1], aB + ((16 * PJS + ks * 8) << 2));
#pragma unroll
        for (int ntp = 0; ntp < 4; ntp++) {
            unsigned bb[4];
            ldsm_x4(bb, bB + ((ntp * 16 * PJS + ks * 8) << 2));
            mma_f16(sacc[0][2 * ntp], a[0], bb[0], bb[1]);
            mma_f16(sacc[1][2 * ntp], a[1], bb[0], bb[1]);
            mma_f16(sacc[0][2 * ntp + 1], a[0], bb[2], bb[3]);
            mma_f16(sacc[1][2 * ntp + 1], a[1], bb[2], bb[3]);
        }
    }
    __syncthreads();

#pragma unroll
    for (int mt = 0; mt < 2; mt++) {
        const int r0 = wm * 32 + mt * 16 + g;
#pragma unroll
        for (int nt = 0; nt < 8; nt++) {
            const int col = wn * 64 + nt * 8 + 2 * t;
            Cs[col * PJS + r0]           = sacc[mt][nt][0];
            Cs[(col + 1) * PJS + r0]     = sacc[mt][nt][1];
            Cs[col * PJS + r0 + 8]       = sacc[mt][nt][2];
            Cs[(col + 1) * PJS + r0 + 8] = sacc[mt][nt][3];
        }
    }
    __syncthreads();

#pragma unroll
    for (int tl = 0; tl < 16; tl++) {
        const int u = tid + tl * 256;
        const int d = u >> 5, q = u & 31;
        const float bias = bp[co0 + d];
        float4 v = *(const float4*)&Cs[d * PJS + 4 * q];
        v.x += bias; v.y += bias; v.z += bias; v.w += bias;
        *(float4*)&out[((long)b * CDIM + co0 + d) * NTOK + n0 + 4 * q] = v;
    }
}

// ---------------------------------------------------------------------------
extern "C" void kernel_launch(void* const* d_in, const int* in_sizes, int n_in,
                              void* d_out, int out_size) {
    const float* x    = (const float*)d_in[0];
    const int*   fg   = (const int*)d_in[1];
    const float* Wqkv = (const float*)d_in[2];
    const float* Wp   = (const float*)d_in[3];
    const float* bp   = (const float*)d_in[4];
    float* out = (float*)d_out;

    cudaFuncSetAttribute(qkv_kernel, cudaFuncAttributeMaxDynamicSharedMemorySize, QKV_SMEM);
    cudaFuncSetAttribute(attn_kernel, cudaFuncAttributeMaxDynamicSharedMemorySize, ATTN_SMEM);
    cudaFuncSetAttribute(proj_kernel, cudaFuncAttributeMaxDynamicSharedMemorySize, PROJ_SMEM);

    wconv_kernel<<<256, 256>>>(Wqkv, Wp);
    compact_kernel<<<BATCH, 256>>>(fg);
    pad_kernel<<<BATCH, 256>>>();
    qkv_kernel<<<dim3(NTOK / 64, TCD / 128, BATCH), 256, QKV_SMEM>>>(x);
    attn_kernel<<<dim3(NTOK / 128, BATCH), 256, ATTN_SMEM>>>();
    proj_kernel<<<dim3(NTOK / 128, CDIM / 128, BATCH), 256, PROJ_SMEM>>>(bp, out);
}

// round 16
// speedup vs baseline: 5.2579x; 1.0206x over previous
#include <cuda_runtime.h>
#include <cuda_fp16.h>

#define BATCH 4
#define CDIM 256
#define NTOK 4096   // 64*64
#define TCD 768     // 3*C
#define FULLMASK 0xffffffffu

// Scratch (allocation-free rule: __device__ globals)
__device__ __half g_xh[BATCH * CDIM * NTOK];   // x converted to fp16, [b][c][n]
__device__ __half g_Q[BATCH * NTOK * CDIM];
__device__ __half g_Kc[BATCH * NTOK * CDIM];   // compacted keys
__device__ __half g_Vc[BATCH * NTOK * CDIM];   // compacted values
__device__ __half g_AOh[BATCH * NTOK * CDIM];
__device__ __half g_Wh[TCD * CDIM];
__device__ __half g_Wph[CDIM * CDIM];
__device__ int    g_pos[BATCH * NTOK];         // scatter index or -1
__device__ int    g_cnt[BATCH];

__device__ __forceinline__ float ex2(float x) {
    float r;
    asm("ex2.approx.f32 %0, %1;" : "=f"(r) : "f"(x));
    return r;
}
__device__ __forceinline__ void mma_f16(float d[4], const unsigned a[4],
                                        unsigned b0, unsigned b1) {
    asm volatile(
        "mma.sync.aligned.m16n8k16.row.col.f32.f16.f16.f32 "
        "{%0,%1,%2,%3}, {%4,%5,%6,%7}, {%8,%9}, {%0,%1,%2,%3};\n"
        : "+f"(d[0]), "+f"(d[1]), "+f"(d[2]), "+f"(d[3])
        : "r"(a[0]), "r"(a[1]), "r"(a[2]), "r"(a[3]), "r"(b0), "r"(b1));
}
__device__ __forceinline__ unsigned h2u(__half2 h) { return *(unsigned*)&h; }
__device__ __forceinline__ unsigned s2u(const void* p) {
    unsigned u;
    asm("{ .reg .u64 t; cvta.to.shared.u64 t, %1; cvt.u32.u64 %0, t; }"
        : "=r"(u) : "l"(p));
    return u;
}
__device__ __forceinline__ void ldsm_x4(unsigned r[4], unsigned addr) {
    asm volatile("ldmatrix.sync.aligned.m8n8.x4.shared.b16 {%0,%1,%2,%3}, [%4];"
        : "=r"(r[0]), "=r"(r[1]), "=r"(r[2]), "=r"(r[3]) : "r"(addr));
}
__device__ __forceinline__ void ldsm_x4_t(unsigned r[4], unsigned addr) {
    asm volatile("ldmatrix.sync.aligned.m8n8.x4.trans.shared.b16 {%0,%1,%2,%3}, [%4];"
        : "=r"(r[0]), "=r"(r[1]), "=r"(r[2]), "=r"(r[3]) : "r"(addr));
}
__device__ __forceinline__ void cp16(unsigned dst, const void* src) {
    asm volatile("cp.async.cg.shared.global [%0], [%1], 16;" :: "r"(dst), "l"(src));
}
#define CP_COMMIT() asm volatile("cp.async.commit_group;" ::: "memory")
#define CP_WAIT(n)  asm volatile("cp.async.wait_group %0;" :: "n"(n) : "memory")

// ---------------------------------------------------------------------------
// Kernel 0: one-time fp32 -> fp16 conversion: x, Wqkv, Wp.
// grid (4352, 256): 1 float4 per thread, exact cover.
// ---------------------------------------------------------------------------
#define N_X4_X  (BATCH * CDIM * NTOK / 4)   // 1048576
#define N_X4_W  (TCD * CDIM / 4)            // 49152
#define N_X4_WP (CDIM * CDIM / 4)           // 16384

__global__ __launch_bounds__(256) void conv_kernel(const float* __restrict__ x,
                                                   const float* __restrict__ Wqkv,
                                                   const float* __restrict__ Wp) {
    const int idx = blockIdx.x * 256 + threadIdx.x;
    const float4* src;
    uint2* dst;
    int off;
    if (idx < N_X4_X) { src = (const float4*)x; dst = (uint2*)g_xh; off = idx; }
    else if (idx < N_X4_X + N_X4_W) {
        src = (const float4*)Wqkv; dst = (uint2*)g_Wh; off = idx - N_X4_X;
    } else {
        src = (const float4*)Wp; dst = (uint2*)g_Wph; off = idx - N_X4_X - N_X4_W;
    }
    float4 v = src[off];
    uint2 wv;
    wv.x = h2u(__floats2half2_rn(v.x, v.y));
    wv.y = h2u(__floats2half2_rn(v.z, v.w));
    dst[off] = wv;
}

// ---------------------------------------------------------------------------
// Kernel 0b: mask compaction (order-preserving scan) + zero-pad tail of Kc/Vc.
// grid (4), 256 threads.
// ---------------------------------------------------------------------------
__global__ __launch_bounds__(256) void compact_kernel(const int* __restrict__ fg) {
    __shared__ int ps[256];
    const int b = blockIdx.x, tid = threadIdx.x;
    const int* f = fg + b * NTOK + tid * 16;
    int loc[16], c = 0;
#pragma unroll
    for (int i = 0; i < 16; i++) { loc[i] = (f[i] != 0); c += loc[i]; }
    ps[tid] = c;
    __syncthreads();
    for (int s = 1; s < 256; s <<= 1) {
        int v = (tid >= s) ? ps[tid - s] : 0;
        __syncthreads();
        ps[tid] += v;
        __syncthreads();
    }
    int off = ps[tid] - c;   // exclusive prefix
#pragma unroll
    for (int i = 0; i < 16; i++) {
        g_pos[b * NTOK + tid * 16 + i] = loc[i] ? off : -1;
        off += loc[i];
    }
    if (tid == 255) g_cnt[b] = ps[255];
    __syncthreads();
    // zero-pad tail rows [cnt, padded128)
    const int cnt = ps[255];
    const int padded = (cnt + 127) & ~127;
    const int n4 = (padded - cnt) * 32;
    for (int i = tid; i < n4; i += 256) {
        const int row = cnt + (i >> 5), j = i & 31;
        const long o = ((long)b * NTOK + row) * CDIM + j * 8;
        *(uint4*)&g_Kc[o] = make_uint4(0, 0, 0, 0);
        *(uint4*)&g_Vc[o] = make_uint4(0, 0, 0, 0);
    }
}

// ---------------------------------------------------------------------------
// Kernel 1: QKV GEMM; all-fp16 inputs via cp.async (x pre-converted).
// K/V rows scatter directly to compacted positions.
// ---------------------------------------------------------------------------
#define XQS 36
#define WQS 132
#define QKV_SMEM ((256 * XQS + 128 * WQS) * 4)

__global__ __launch_bounds__(256) void qkv_kernel() {
    extern __shared__ unsigned sqw[];
    unsigned* Xw = sqw;
    unsigned* Wh = sqw + 256 * XQS;

    const int b  = blockIdx.z;
    const int n0 = blockIdx.x * 64;
    const int d0 = blockIdx.y * 128;
    const int tid = threadIdx.x;
    const int lane = tid & 31, w = tid >> 5;
    const int g = lane >> 2, t = lane & 3;
    const int wmd = w >> 2, wnn = w & 3;

    const unsigned whB = s2u(Wh), xwB = s2u(Xw);

#pragma unroll
    for (int tl = 0; tl < 16; tl++) {
        const int u = tid + tl * 256;
        const int d = u >> 5, ch = u & 31;
        cp16(whB + ((d * WQS + ch * 4) << 2), &g_Wh[(long)(d0 + d) * CDIM + ch * 8]);
    }
#pragma unroll
    for (int tl = 0; tl < 8; tl++) {
        const int u = tid + tl * 256;
        const int c = u >> 3, j = u & 7;
        cp16(xwB + ((c * XQS + j * 4) << 2),
             &g_xh[((long)b * CDIM + c) * NTOK + n0 + j * 8]);
    }
    CP_COMMIT();
    CP_WAIT(0);
    __syncthreads();

    const unsigned aB = whB + (((wmd * 64 + (lane & 15)) * WQS + 4 * (lane >> 4)) << 2);
    const unsigned xB = xwB + (((lane & 15) * XQS) << 2) +
                        ((wnn * 16 + (lane >> 4) * 8) << 1);

    float acc[4][2][4] = {};
#pragma unroll
    for (int ks = 0; ks < 16; ks++) {
        unsigned a[4][4];
#pragma unroll
        for (int mt = 0; mt < 4; mt++)
            ldsm_x4(a[mt], aB + ((mt * 16 * WQS + ks * 8) << 2));
        unsigned bb[4];
        ldsm_x4_t(bb, xB + ((ks * 16 * XQS) << 2));
#pragma unroll
        for (int mt = 0; mt < 4; mt++) {
            mma_f16(acc[mt][0], a[mt], bb[0], bb[1]);
            mma_f16(acc[mt][1], a[mt], bb[2], bb[3]);
        }
    }
    __syncthreads();

    __half* Csh = (__half*)sqw;   // [64 n][136 halves]
#pragma unroll
    for (int mt = 0; mt < 4; mt++) {
        const int r0 = wmd * 64 + mt * 16 + g;
#pragma unroll
        for (int nt = 0; nt < 2; nt++) {
            const int col = wnn * 16 + nt * 8 + 2 * t;
            Csh[col * 136 + r0]           = __float2half(acc[mt][nt][0]);
            Csh[(col + 1) * 136 + r0]     = __float2half(acc[mt][nt][1]);
            Csh[col * 136 + r0 + 8]       = __float2half(acc[mt][nt][2]);
            Csh[(col + 1) * 136 + r0 + 8] = __float2half(acc[mt][nt][3]);
        }
    }
    __syncthreads();

    const int seg = d0 >> 8;
    const int dl0 = d0 & 255;
    if (seg == 0) {
#pragma unroll
        for (int tl = 0; tl < 4; tl++) {
            const int u = tid + tl * 256;
            const int n = u >> 4, d8 = u & 15;
            uint4 v = *(const uint4*)&Csh[n * 136 + d8 * 8];
            *(uint4*)&g_Q[((long)b * NTOK + n0 + n) * CDIM + dl0 + d8 * 8] = v;
        }
    } else {
        __half* basec = (seg == 1) ? g_Kc : g_Vc;
#pragma unroll
        for (int tl = 0; tl < 4; tl++) {
            const int u = tid + tl * 256;
            const int n = u >> 4, d8 = u & 15;
            const int np = g_pos[b * NTOK + n0 + n];
            if (np >= 0) {
                uint4 v = *(const uint4*)&Csh[n * 136 + d8 * 8];
                *(uint4*)&basec[((long)b * NTOK + np) * CDIM + dl0 + d8 * 8] = v;
            }
        }
    }
}

// ---------------------------------------------------------------------------
// Kernel 2: fp16 mma flash attention over compacted keys.
// NEW: K-half0 of the NEXT tile is prefetched into a dedicated K0N buffer
// during the current tile's softmax/PV window -> no exposed K latency at
// tile top. Group order: {K0(i)} -> +K1(i) -> wait(1)=K0 done; post-S:
// commit V(i), commit K0(i+1) (clamped); wait(1)=V done.
// ---------------------------------------------------------------------------
#define QW 132
#define PW 68
#define K0S 68
#define KVW (128 * QW)
// words: Q 16896 | Kw 16896 | Pw 8704 | fgf 128 | lsumP 256 | runl 128 | K0N 8704
#define ATTN_SMEM ((16896 * 2 + 8704 * 2 + 512) * 4)

__global__ __launch_bounds__(256, 1) void attn_kernel() {
    extern __shared__ unsigned smw[];
    unsigned* Qw  = smw;
    unsigned* Kw  = Qw + 128 * QW;
    unsigned* Pw  = Kw + KVW;
    float* fgf    = (float*)(Pw + 128 * PW);
    float* lsumP  = fgf + 128;
    float* runl   = lsumP + 256;
    unsigned* K0N = (unsigned*)(runl + 128);

    const int b   = blockIdx.y;
    const int q0  = blockIdx.x * 128;
    const int tid = threadIdx.x;
    const int lane = tid & 31, w = tid >> 5;
    const int g = lane >> 2, t = lane & 3;
    const int wmS = w >> 1, wnS = w & 1;     // S: 4x2 grid, warp tile 32x64
    const int wmO = w >> 2, wnO = w & 3;     // O: 2x4 grid, warp tile 64x64

    const int cnt = g_cnt[b];
    const int padded = (cnt + 127) & ~127;

    const __half* Qg = g_Q + ((long)b * NTOK + q0) * CDIM;
    const __half* Kg = g_Kc + (long)b * NTOK * CDIM;
    const __half* Vg = g_Vc + (long)b * NTOK * CDIM;

    const unsigned kwB = s2u(Kw), k0B = s2u(K0N);

    // prologue: K-half0 of tile 0 into K0N (1 group in flight at loop top)
#pragma unroll
    for (int tl = 0; tl < 8; tl++) {
        const int u = tid + tl * 256;
        const int row = u >> 4, j = u & 15;
        cp16(k0B + ((row * K0S + j * 4) << 2), &Kg[(long)row * CDIM + j * 8]);
    }
    CP_COMMIT();

#pragma unroll
    for (int tl = 0; tl < 16; tl++) {
        const int u = tid + tl * 256;
        const int row = u >> 5, j = u & 31;
        uint4 v = *(const uint4*)&Qg[(long)row * CDIM + j * 8];
        *(uint4*)&Qw[row * QW + j * 4] = v;
    }
    if (tid < 128) runl[tid] = 0.0f;

    const unsigned qaB = s2u(Qw) +
        (((wmS * 32 + (lane & 15)) * QW + 4 * (lane >> 4)) << 2);
    const unsigned kb0B = k0B +
        (((wnS * 64 + ((lane >> 4) << 3) + (lane & 7)) * K0S + ((lane >> 3) & 1) * 4) << 2);
    const unsigned kb1B = kwB +
        (((wnS * 64 + ((lane >> 4) << 3) + (lane & 7)) * QW + ((lane >> 3) & 1) * 4) << 2);
    const unsigned paB = s2u(Pw) +
        (((wmO * 64 + (lane & 15)) * PW + 4 * (lane >> 4)) << 2);
    const unsigned vbB = kwB + (((lane & 15) * QW) << 2) +
        ((wnO * 64 + (lane >> 4) * 8) << 1);

    float oacc[4][8][4];
#pragma unroll
    for (int i = 0; i < 4; i++)
#pragma unroll
        for (int j = 0; j < 8; j++)
#pragma unroll
            for (int k = 0; k < 4; k++) oacc[i][j][k] = 0.0f;

    const float SC = 0.0625f * 1.4426950408889634f;

    for (int m0 = 0; m0 < padded; m0 += 128) {
        __syncthreads();   // prev PV done reading Kw; Q visible on tile 0

        // K half 1 (c 128..255) -> Kw words 0..63
#pragma unroll
        for (int tl = 0; tl < 8; tl++) {
            const int u = tid + tl * 256;
            const int row = u >> 4, j = u & 15;
            cp16(kwB + ((row * QW + j * 4) << 2),
                 &Kg[(long)(m0 + row) * CDIM + 128 + j * 8]);
        }
        CP_COMMIT();

        if (tid < 128) fgf[tid] = (m0 + tid < cnt) ? 1.0f : 0.0f;

        float sacc[2][8][4] = {};

        CP_WAIT(1);        // K half 0 (prefetched) landed
        __syncthreads();
#pragma unroll
        for (int ks = 0; ks < 8; ks++) {
            unsigned a[2][4];
            ldsm_x4(a[0], qaB + ((ks * 8) << 2));
            ldsm_x4(a[1], qaB + ((16 * QW + ks * 8) << 2));
#pragma unroll
            for (int ntp = 0; ntp < 4; ntp++) {
                unsigned bb[4];
                ldsm_x4(bb, kb0B + ((ntp * 16 * K0S + ks * 8) << 2));
                mma_f16(sacc[0][2 * ntp], a[0], bb[0], bb[1]);
                mma_f16(sacc[1][2 * ntp], a[1], bb[0], bb[1]);
                mma_f16(sacc[0][2 * ntp + 1], a[0], bb[2], bb[3]);
                mma_f16(sacc[1][2 * ntp + 1], a[1], bb[2], bb[3]);
            }
        }
        CP_WAIT(0);        // K half 1 landed
        __syncthreads();
#pragma unroll
        for (int ks = 8; ks < 16; ks++) {
            unsigned a[2][4];
            ldsm_x4(a[0], qaB + ((ks * 8) << 2));
            ldsm_x4(a[1], qaB + ((16 * QW + ks * 8) << 2));
#pragma unroll
            for (int ntp = 0; ntp < 4; ntp++) {
                unsigned bb[4];
                ldsm_x4(bb, kb1B + ((ntp * 16 * QW + (ks - 8) * 8) << 2));
                mma_f16(sacc[0][2 * ntp], a[0], bb[0], bb[1]);
                mma_f16(sacc[1][2 * ntp], a[1], bb[0], bb[1]);
                mma_f16(sacc[0][2 * ntp + 1], a[0], bb[2], bb[3]);
                mma_f16(sacc[1][2 * ntp + 1], a[1], bb[2], bb[3]);
            }
        }
        __syncthreads();   // all warps done reading K0N and Kw

        // V into Kw (full rows); then next tile's K half 0 into K0N
#pragma unroll
        for (int tl = 0; tl < 16; tl++) {
            const int u = tid + tl * 256;
            const int row = u >> 5, j = u & 31;
            cp16(kwB + ((row * QW + j * 4) << 2),
                 &Vg[(long)(m0 + row) * CDIM + j * 8]);
        }
        CP_COMMIT();
        {
            const int mn = (m0 + 128 < padded) ? (m0 + 128) : 0;   // clamp: keep group count fixed
#pragma unroll
            for (int tl = 0; tl < 8; tl++) {
                const int u = tid + tl * 256;
                const int row = u >> 4, j = u & 15;
                cp16(k0B + ((row * K0S + j * 4) << 2),
                     &Kg[(long)(mn + row) * CDIM + j * 8]);
            }
            CP_COMMIT();
        }

        float rsum[4] = {0.0f, 0.0f, 0.0f, 0.0f};
#pragma unroll
        for (int mt = 0; mt < 2; mt++) {
            const int r0 = wmS * 32 + mt * 16 + g;
#pragma unroll
            for (int nt = 0; nt < 8; nt++) {
                const int col = wnS * 64 + nt * 8 + 2 * t;
                const float f0 = fgf[col], f1 = fgf[col + 1];
                float p0 = ex2(sacc[mt][nt][0] * SC) * f0;
                float p1 = ex2(sacc[mt][nt][1] * SC) * f1;
                float p2 = ex2(sacc[mt][nt][2] * SC) * f0;
                float p3 = ex2(sacc[mt][nt][3] * SC) * f1;
                rsum[mt * 2 + 0] += p0 + p1;
                rsum[mt * 2 + 1] += p2 + p3;
                __half2 h01 = __floats2half2_rn(p0, p1);
                __half2 h23 = __floats2half2_rn(p2, p3);
                Pw[r0 * PW + (col >> 1)] = *(unsigned*)&h01;
                Pw[(r0 + 8) * PW + (col >> 1)] = *(unsigned*)&h23;
            }
        }
#pragma unroll
        for (int si = 0; si < 4; si++) {
            rsum[si] += __shfl_xor_sync(FULLMASK, rsum[si], 1);
            rsum[si] += __shfl_xor_sync(FULLMASK, rsum[si], 2);
        }
        if (t == 0) {
            const int rb = wmS * 32 + g;
            lsumP[wnS * 128 + rb]      = rsum[0];
            lsumP[wnS * 128 + rb + 8]  = rsum[1];
            lsumP[wnS * 128 + rb + 16] = rsum[2];
            lsumP[wnS * 128 + rb + 24] = rsum[3];
        }
        CP_WAIT(1);        // V landed (K0 prefetch may still fly)
        __syncthreads();
        if (tid < 128) runl[tid] += lsumP[tid] + lsumP[128 + tid];

#pragma unroll
        for (int ks = 0; ks < 8; ks++) {
            unsigned a[4][4];
#pragma unroll
            for (int mt = 0; mt < 4; mt++)
                ldsm_x4(a[mt], paB + ((mt * 16 * PW + ks * 8) << 2));
#pragma unroll
            for (int ntp = 0; ntp < 4; ntp++) {
                unsigned vv[4];
                ldsm_x4_t(vv, vbB + ((ks * 16 * QW) << 2) + (ntp << 5));
#pragma unroll
                for (int mt = 0; mt < 4; mt++) {
                    mma_f16(oacc[mt][2 * ntp], a[mt], vv[0], vv[1]);
                    mma_f16(oacc[mt][2 * ntp + 1], a[mt], vv[2], vv[3]);
                }
            }
        }
    }

    // ---- epilogue: normalize and store fp16 AO ----
    __half* AOg = g_AOh + ((long)b * NTOK + q0) * CDIM;
#pragma unroll
    for (int mt = 0; mt < 4; mt++) {
        const int r0 = wmO * 64 + mt * 16 + g;
        const float inv0 = 1.0f / runl[r0];
        const float inv1 = 1.0f / runl[r0 + 8];
#pragma unroll
        for (int nt = 0; nt < 8; nt++) {
            const int col = wnO * 64 + nt * 8 + 2 * t;
            *(__half2*)&AOg[(long)r0 * CDIM + col] =
                __floats2half2_rn(oacc[mt][nt][0] * inv0, oacc[mt][nt][1] * inv0);
            *(__half2*)&AOg[(long)(r0 + 8) * CDIM + col] =
                __floats2half2_rn(oacc[mt][nt][2] * inv1, oacc[mt][nt][3] * inv1);
        }
    }
}

// ---------------------------------------------------------------------------
// Kernel 3: projection (R12 version verbatim — 17.5us).
// ---------------------------------------------------------------------------
#define PJS 132
#define PROJ_SMEM ((128 * PJS + 128 * PJS) * 4)

__global__ __launch_bounds__(256) void proj_kernel(const float* __restrict__ bp,
                                                   float* __restrict__ out) {
    extern __shared__ unsigned spw[];
    unsigned* Ah = spw;
    unsigned* Wh = spw + 128 * PJS;
    float* Cs = (float*)spw;

    const int b   = blockIdx.z;
    const int n0  = blockIdx.x * 128;
    const int co0 = blockIdx.y * 128;
    const int tid = threadIdx.x;
    const int lane = tid & 31, w = tid >> 5;
    const int g = lane >> 2, t = lane & 3;
    const int wm = w >> 1, wn = w & 1;

    const unsigned ahB = s2u(Ah), whB = s2u(Wh);
#pragma unroll
    for (int tl = 0; tl < 16; tl++) {
        const int u = tid + tl * 256;
        const int n = u >> 5, ch = u & 31;
        cp16(ahB + ((n * PJS + ch * 4) << 2),
             &g_AOh[((long)b * NTOK + n0 + n) * CDIM + ch * 8]);
    }
#pragma unroll
    for (int tl = 0; tl < 16; tl++) {
        const int u = tid + tl * 256;
        const int d = u >> 5, ch = u & 31;
        cp16(whB + ((d * PJS + ch * 4) << 2),
             &g_Wph[(long)(co0 + d) * CDIM + ch * 8]);
    }
    CP_COMMIT();
    CP_WAIT(0);
    __syncthreads();

    const unsigned aB = ahB + (((wm * 32 + (lane & 15)) * PJS + 4 * (lane >> 4)) << 2);
    const unsigned bB = whB +
        (((wn * 64 + ((lane >> 4) << 3) + (lane & 7)) * PJS + ((lane >> 3) & 1) * 4) << 2);

    float sacc[2][8][4] = {};
#pragma unroll
    for (int ks = 0; ks < 16; ks++) {
        unsigned a[2][4];
        ldsm_x4(a[0], aB + ((ks * 8) << 2));
        ldsm_x4(a[1], aB + ((16 * PJS + ks * 8) << 2));
#pragma unroll
        for (int ntp = 0; ntp < 4; ntp++) {
            unsigned bb[4];
            ldsm_x4(bb, bB + ((ntp * 16 * PJS + ks * 8) << 2));
            mma_f16(sacc[0][2 * ntp], a[0], bb[0], bb[1]);
            mma_f16(sacc[1][2 * ntp], a[1], bb[0], bb[1]);
            mma_f16(sacc[0][2 * ntp + 1], a[0], bb[2], bb[3]);
            mma_f16(sacc[1][2 * ntp + 1], a[1], bb[2], bb[3]);
        }
    }
    __syncthreads();

#pragma unroll
    for (int mt = 0; mt < 2; mt++) {
        const int r0 = wm * 32 + mt * 16 + g;
#pragma unroll
        for (int nt = 0; nt < 8; nt++) {
            const int col = wn * 64 + nt * 8 + 2 * t;
            Cs[col * PJS + r0]           = sacc[mt][nt][0];
            Cs[(col + 1) * PJS + r0]     = sacc[mt][nt][1];
            Cs[col * PJS + r0 + 8]       = sacc[mt][nt][2];
            Cs[(col + 1) * PJS + r0 + 8] = sacc[mt][nt][3];
        }
    }
    __syncthreads();

#pragma unroll
    for (int tl = 0; tl < 16; tl++) {
        const int u = tid + tl * 256;
        const int d = u >> 5, q = u & 31;
        const float bias = bp[co0 + d];
        float4 v = *(const float4*)&Cs[d * PJS + 4 * q];
        v.x += bias; v.y += bias; v.z += bias; v.w += bias;
        *(float4*)&out[((long)b * CDIM + co0 + d) * NTOK + n0 + 4 * q] = v;
    }
}

// ---------------------------------------------------------------------------
extern "C" void kernel_launch(void* const* d_in, const int* in_sizes, int n_in,
                              void* d_out, int out_size) {
    const float* x    = (const float*)d_in[0];
    const int*   fg   = (const int*)d_in[1];
    const float* Wqkv = (const float*)d_in[2];
    const float* Wp   = (const float*)d_in[3];
    const float* bp   = (const float*)d_in[4];
    float* out = (float*)d_out;

    cudaFuncSetAttribute(qkv_kernel, cudaFuncAttributeMaxDynamicSharedMemorySize, QKV_SMEM);
    cudaFuncSetAttribute(attn_kernel, cudaFuncAttributeMaxDynamicSharedMemorySize, ATTN_SMEM);
    cudaFuncSetAttribute(proj_kernel, cudaFuncAttributeMaxDynamicSharedMemorySize, PROJ_SMEM);

    conv_kernel<<<(N_X4_X + N_X4_W + N_X4_WP) / 256, 256>>>(x, Wqkv, Wp);
    compact_kernel<<<BATCH, 256>>>(fg);
    qkv_kernel<<<dim3(NTOK / 64, TCD / 128, BATCH), 256, QKV_SMEM>>>();
    attn_kernel<<<dim3(NTOK / 128, BATCH), 256, ATTN_SMEM>>>();
    proj_kernel<<<dim3(NTOK / 128, CDIM / 128, BATCH), 256, PROJ_SMEM>>>(bp, out);
}